// round 4
// baseline (speedup 1.0000x reference)
#include <cuda_runtime.h>
#include <math.h>

#define NPER 20000
#define CH 64
#define NREL 15
#define NEDGE 30000
#define NH 60000

__constant__ int c_tsrc[NREL] = {0,1,2,0,1,2,0,1,2,0,0,1,1,2,2};
__constant__ int c_tdst[NREL] = {0,1,2,0,1,2,0,1,2,1,2,0,2,0,1};
__constant__ int c_off[3] = {0, 2*NPER, NPER};

// ---------------- scratch (device globals; no allocs allowed) ----------------
__device__ float    g_hs[(size_t)NREL*NPER*CH];
__device__ float    g_as[NREL*NPER];
__device__ float    g_ad[NREL*NPER];
__device__ float    g_cnt[NREL*NPER];
__device__ float    g_icnt[NREL*NPER];
__device__ float    g_acc[3*NPER*CH];
__device__ float    g_xd[3*NPER*CH];       // layer-1 output (type-major)
__device__ float    g_hx[3*NPER*CH];       // layer-2 output (attention row order)
__device__ float    g_u0[6*CH];
__device__ float    g_cd[6];
__device__ float    g_q[(size_t)NH*128];
__device__ float    g_k[(size_t)NH*128];
__device__ float    g_v[(size_t)NH*128];
__device__ float    g_outb[(size_t)NH*CH];
__device__ float    g_score[(size_t)NREL*NEDGE*2];
__device__ unsigned g_smax[NH*2];
__device__ float    g_den[NH*2];
__device__ float    g_num[(size_t)NH*128];
__device__ double   g_sum[CH];
__device__ double   g_sumsq[CH];
__device__ float    g_mu[CH];
__device__ float    g_rstd[CH];

__device__ __forceinline__ void red_add_v4(float* p, float4 v) {
    asm volatile("red.global.add.v4.f32 [%0], {%1,%2,%3,%4};"
                 :: "l"(p), "f"(v.x), "f"(v.y), "f"(v.z), "f"(v.w) : "memory");
}
__device__ __forceinline__ unsigned f2tf(float f) {
    unsigned u; asm("cvt.rna.tf32.f32 %0, %1;" : "=r"(u) : "f"(f)); return u;
}
__device__ __forceinline__ void split_tf(float f, unsigned& hi, unsigned& lo) {
    hi = f2tf(f);
    lo = f2tf(f - __uint_as_float(hi));
}
__device__ __forceinline__ void mma_tf32(float c[4], unsigned a0, unsigned a1,
                                         unsigned a2, unsigned a3,
                                         unsigned b0, unsigned b1) {
    asm volatile("mma.sync.aligned.m16n8k8.row.col.f32.tf32.tf32.f32 "
                 "{%0,%1,%2,%3}, {%4,%5,%6,%7}, {%8,%9}, {%0,%1,%2,%3};"
                 : "+f"(c[0]), "+f"(c[1]), "+f"(c[2]), "+f"(c[3])
                 : "r"(a0), "r"(a1), "r"(a2), "r"(a3), "r"(b0), "r"(b1));
}

#define DSMEM_BYTES (4*64*68*4)

// ---------------- edge counts (static across layers) -------------------------
__global__ void cnt_kernel(const int* __restrict__ ei) {
    int e = blockIdx.x*blockDim.x + threadIdx.x;
    if (e >= NREL*NEDGE) return;
    int r = e / NEDGE, w = e - r*NEDGE;
    int dst = ei[(size_t)r*2*NEDGE + NEDGE + w];
    atomicAdd(&g_cnt[r*NPER + dst], 1.0f);
}
__global__ void icnt_kernel() {
    int i = blockIdx.x*blockDim.x + threadIdx.x;
    if (i < NREL*NPER) g_icnt[i] = 0.2f / fmaxf(g_cnt[i], 1.0f);
}

// ---------------- prep: u0 = Wlin @ wa0, cd = blin . wa0 (cross relations) ---
__global__ void prep_u_kernel(const float* __restrict__ Wlin_l,
                              const float* __restrict__ blin_l,
                              const float* __restrict__ Wa_l) {
    int k = threadIdx.x; // 64
    for (int j = 0; j < 6; j++) {
        int r = 9 + j;
        const float* W = Wlin_l + r*4096 + k*64;
        const float* wa0 = Wa_l + r*128;
        float s = 0.f;
        #pragma unroll 8
        for (int c = 0; c < 64; c++) s += W[c] * wa0[c];
        g_u0[j*64 + k] = s;
    }
    if (k < 6) {
        int r = 9 + k;
        float s = 0.f;
        for (int c = 0; c < 64; c++) s += blin_l[r*64 + c] * Wa_l[r*128 + c];
        g_cd[k] = s;
    }
}

// ---------------- hs = x[tsrc] @ Wlin + blin  (3xTF32 MMA) -------------------
// 64-row tile, 8 warps = 4 row-groups x 2 col-halves. Fused a_s/a_d epilogue.
__global__ void lin_mma_kernel(const float* __restrict__ x,
                               const float* __restrict__ Wlin_l,
                               const float* __restrict__ blin_l,
                               const float* __restrict__ Wa_l,
                               const float* __restrict__ ba_l) {
    extern __shared__ unsigned dsm[];
    unsigned (*xh)[68] = (unsigned(*)[68])dsm;
    unsigned (*xl)[68] = xh + 64;
    unsigned (*Wh)[68] = xl + 64;
    unsigned (*Wl)[68] = Wh + 64;
    __shared__ float bsh[64], wa0s[64], wa1s[64];
    __shared__ float red_s[64][2], red_d[64][2];
    int r = blockIdx.y;
    int tid = threadIdx.x;
    const float* W = Wlin_l + r*4096;
    for (int i = tid; i < 1024; i += 256) {
        float4 v = ((const float4*)W)[i];
        int rr = i >> 4, c4 = (i & 15)*4;
        split_tf(v.x, Wh[rr][c4+0], Wl[rr][c4+0]);
        split_tf(v.y, Wh[rr][c4+1], Wl[rr][c4+1]);
        split_tf(v.z, Wh[rr][c4+2], Wl[rr][c4+2]);
        split_tf(v.w, Wh[rr][c4+3], Wl[rr][c4+3]);
    }
    if (tid < 64) {
        bsh[tid]  = blin_l[r*64 + tid];
        wa0s[tid] = Wa_l[r*128 + tid];
        wa1s[tid] = Wa_l[r*128 + 64 + tid];
    }
    int t = c_tsrc[r];
    int row0 = blockIdx.x*64;
    const float* xb = x + ((size_t)t*NPER + row0)*CH;
    for (int i = tid; i < 1024; i += 256) {
        int rr = i >> 4, c4 = (i & 15)*4;
        float4 v = (row0 + rr < NPER) ? ((const float4*)xb)[i]
                                      : make_float4(0.f,0.f,0.f,0.f);
        split_tf(v.x, xh[rr][c4+0], xl[rr][c4+0]);
        split_tf(v.y, xh[rr][c4+1], xl[rr][c4+1]);
        split_tf(v.z, xh[rr][c4+2], xl[rr][c4+2]);
        split_tf(v.w, xh[rr][c4+3], xl[rr][c4+3]);
    }
    __syncthreads();

    int warp = tid >> 5, lane = tid & 31;
    int wr = warp >> 1, wc = warp & 1;
    int gid = lane >> 2, tig = lane & 3;
    int rA = wr*16 + gid;
    float acc[4][4];
    #pragma unroll
    for (int nt = 0; nt < 4; nt++)
        #pragma unroll
        for (int j = 0; j < 4; j++) acc[nt][j] = 0.f;

    #pragma unroll
    for (int kk = 0; kk < 8; kk++) {
        int k0 = kk*8;
        unsigned ah0 = xh[rA][k0+tig],   ah1 = xh[rA+8][k0+tig];
        unsigned ah2 = xh[rA][k0+tig+4], ah3 = xh[rA+8][k0+tig+4];
        unsigned al0 = xl[rA][k0+tig],   al1 = xl[rA+8][k0+tig];
        unsigned al2 = xl[rA][k0+tig+4], al3 = xl[rA+8][k0+tig+4];
        #pragma unroll
        for (int nt = 0; nt < 4; nt++) {
            int n0 = wc*32 + nt*8 + gid;
            unsigned bh0 = Wh[k0+tig][n0], bh1 = Wh[k0+tig+4][n0];
            unsigned bl0 = Wl[k0+tig][n0], bl1 = Wl[k0+tig+4][n0];
            mma_tf32(acc[nt], ah0, ah1, ah2, ah3, bh0, bh1);
            mma_tf32(acc[nt], al0, al1, al2, al3, bh0, bh1);
            mma_tf32(acc[nt], ah0, ah1, ah2, ah3, bl0, bl1);
        }
    }
    // bias + store hs + fused a_s/a_d partial dots
    int n = row0 + rA;
    float* base = g_hs + ((size_t)r*NPER + n)*CH;
    float sA = 0.f, sB = 0.f, dA = 0.f, dB = 0.f;
    #pragma unroll
    for (int nt = 0; nt < 4; nt++) {
        int col = wc*32 + nt*8 + 2*tig;
        float c0 = acc[nt][0] + bsh[col], c1 = acc[nt][1] + bsh[col+1];
        float c2 = acc[nt][2] + bsh[col], c3 = acc[nt][3] + bsh[col+1];
        if (n < NPER)     *(float2*)(base + col)        = make_float2(c0, c1);
        if (n + 8 < NPER) *(float2*)(base + 8*CH + col) = make_float2(c2, c3);
        sA += c0*wa1s[col] + c1*wa1s[col+1];
        sB += c2*wa1s[col] + c3*wa1s[col+1];
        dA += c0*wa0s[col] + c1*wa0s[col+1];
        dB += c2*wa0s[col] + c3*wa0s[col+1];
    }
    sA += __shfl_xor_sync(0xffffffffu, sA, 1); sA += __shfl_xor_sync(0xffffffffu, sA, 2);
    sB += __shfl_xor_sync(0xffffffffu, sB, 1); sB += __shfl_xor_sync(0xffffffffu, sB, 2);
    dA += __shfl_xor_sync(0xffffffffu, dA, 1); dA += __shfl_xor_sync(0xffffffffu, dA, 2);
    dB += __shfl_xor_sync(0xffffffffu, dB, 1); dB += __shfl_xor_sync(0xffffffffu, dB, 2);
    if (tig == 0) {
        red_s[rA][wc] = sA;   red_s[rA+8][wc] = sB;
        red_d[rA][wc] = dA;   red_d[rA+8][wc] = dB;
    }
    __syncthreads();
    if (tid < 64 && row0 + tid < NPER) {
        g_as[r*NPER + row0 + tid] = red_s[tid][0] + red_s[tid][1];
        if (r < 9)
            g_ad[r*NPER + row0 + tid] = red_d[tid][0] + red_d[tid][1] + ba_l[r];
    }
}

// ---------------- a_d for the 6 cross-type relations -------------------------
__global__ void ad_cross_kernel(const float* __restrict__ x,
                                const float* __restrict__ ba_l) {
    int j = blockIdx.y;
    int r = 9 + j;
    int warp = threadIdx.x >> 5, lane = threadIdx.x & 31;
    int n = blockIdx.x*8 + warp;
    int t = c_tdst[r];
    const float* xrow = x + ((size_t)t*NPER + n)*CH;
    float p = xrow[lane]*g_u0[j*64 + lane] + xrow[lane+32]*g_u0[j*64 + lane + 32];
    #pragma unroll
    for (int s = 16; s; s >>= 1) p += __shfl_xor_sync(0xffffffffu, p, s);
    if (lane == 0) g_ad[r*NPER + n] = p + g_cd[j] + ba_l[r];
}

// ---------------- per-edge gated message scatter (direct to type accum) ------
__global__ void edge_scatter_kernel(const int* __restrict__ ei) {
    int idx = blockIdx.x*blockDim.x + threadIdx.x;
    int e = idx >> 4, lane = idx & 15;
    if (e >= NREL*NEDGE) return;
    int r = e / NEDGE, w = e - r*NEDGE;
    const int* base = ei + (size_t)r*2*NEDGE;
    int src = base[w], dst = base[NEDGE + w];
    float g = 0.f;
    if (lane == 0)
        g = tanhf(g_ad[r*NPER + dst] + g_as[r*NPER + src]) * g_icnt[r*NPER + dst];
    g = __shfl_sync(0xffffffffu, g, threadIdx.x & 16);
    float4 h = ((const float4*)(g_hs + ((size_t)r*NPER + src)*CH))[lane];
    int t = c_tdst[r];
    red_add_v4(g_acc + ((size_t)t*NPER + dst)*CH + lane*4,
               make_float4(g*h.x, g*h.y, g*h.z, g*h.w));
}

// ---------------- relu + store layer output ----------------------------------
__global__ void relu_kernel(int mode, float* __restrict__ dst) {
    int idx = blockIdx.x*blockDim.x + threadIdx.x;
    if (idx >= 3*NPER*16) return;
    int lane = idx & 15, tn = idx >> 4;
    int t = tn / NPER, n = tn - t*NPER;
    float4 a = ((const float4*)(g_acc + (size_t)tn*CH))[lane];
    a.x = fmaxf(a.x, 0.f); a.y = fmaxf(a.y, 0.f);
    a.z = fmaxf(a.z, 0.f); a.w = fmaxf(a.w, 0.f);
    int row = mode ? (c_off[t] + n) : tn;
    ((float4*)(dst + (size_t)row*CH))[lane] = a;
}

// ---------------- q/k/v/skip GEMM via 3xTF32 MMA (7 chunks of 64 cols) -------
__global__ void qkv_mma_kernel(const float* __restrict__ Wq, const float* __restrict__ bq,
                               const float* __restrict__ Wk, const float* __restrict__ bk,
                               const float* __restrict__ Wv, const float* __restrict__ bv,
                               const float* __restrict__ Wskip, const float* __restrict__ bskip) {
    extern __shared__ unsigned dsm[];
    unsigned (*xh)[68] = (unsigned(*)[68])dsm;
    unsigned (*xl)[68] = xh + 64;
    unsigned (*Wh)[68] = xl + 64;
    unsigned (*Wl)[68] = Wh + 64;
    __shared__ float bsh[64];
    int chunk = blockIdx.y;
    const float *Wsrc, *bsrc;
    float* dst;
    int ldW, coff, ldD;
    if (chunk < 2)      { Wsrc = Wq;    bsrc = bq;    dst = g_q;    ldW = 128; coff = chunk*64;     ldD = 128; }
    else if (chunk < 4) { Wsrc = Wk;    bsrc = bk;    dst = g_k;    ldW = 128; coff = (chunk-2)*64; ldD = 128; }
    else if (chunk < 6) { Wsrc = Wv;    bsrc = bv;    dst = g_v;    ldW = 128; coff = (chunk-4)*64; ldD = 128; }
    else                { Wsrc = Wskip; bsrc = bskip; dst = g_outb; ldW = 64;  coff = 0;            ldD = 64;  }
    int tid = threadIdx.x;
    for (int i = tid; i < 4096; i += 256) {
        float v = Wsrc[(i>>6)*ldW + coff + (i&63)];
        split_tf(v, Wh[i>>6][i&63], Wl[i>>6][i&63]);
    }
    if (tid < 64) bsh[tid] = bsrc[coff + tid];
    int m0 = blockIdx.x*64;
    const float* xb = g_hx + (size_t)m0*CH;
    for (int i = tid; i < 1024; i += 256) {
        int rr = i >> 4, c4 = (i & 15)*4;
        float4 v = (m0 + rr < NH) ? ((const float4*)xb)[i]
                                  : make_float4(0.f,0.f,0.f,0.f);
        split_tf(v.x, xh[rr][c4+0], xl[rr][c4+0]);
        split_tf(v.y, xh[rr][c4+1], xl[rr][c4+1]);
        split_tf(v.z, xh[rr][c4+2], xl[rr][c4+2]);
        split_tf(v.w, xh[rr][c4+3], xl[rr][c4+3]);
    }
    __syncthreads();

    int warp = tid >> 5, lane = tid & 31;
    int wr = warp >> 1, wc = warp & 1;
    int gid = lane >> 2, tig = lane & 3;
    int rA = wr*16 + gid;
    float acc[4][4];
    #pragma unroll
    for (int nt = 0; nt < 4; nt++)
        #pragma unroll
        for (int j = 0; j < 4; j++) acc[nt][j] = 0.f;

    #pragma unroll
    for (int kk = 0; kk < 8; kk++) {
        int k0 = kk*8;
        unsigned ah0 = xh[rA][k0+tig],   ah1 = xh[rA+8][k0+tig];
        unsigned ah2 = xh[rA][k0+tig+4], ah3 = xh[rA+8][k0+tig+4];
        unsigned al0 = xl[rA][k0+tig],   al1 = xl[rA+8][k0+tig];
        unsigned al2 = xl[rA][k0+tig+4], al3 = xl[rA+8][k0+tig+4];
        #pragma unroll
        for (int nt = 0; nt < 4; nt++) {
            int n0 = wc*32 + nt*8 + gid;
            unsigned bh0 = Wh[k0+tig][n0], bh1 = Wh[k0+tig+4][n0];
            unsigned bl0 = Wl[k0+tig][n0], bl1 = Wl[k0+tig+4][n0];
            mma_tf32(acc[nt], ah0, ah1, ah2, ah3, bh0, bh1);
            mma_tf32(acc[nt], al0, al1, al2, al3, bh0, bh1);
            mma_tf32(acc[nt], ah0, ah1, ah2, ah3, bl0, bl1);
        }
    }
    int m = m0 + rA;
    #pragma unroll
    for (int nt = 0; nt < 4; nt++) {
        int col = wc*32 + nt*8 + 2*tig;
        if (m < NH)
            *(float2*)(dst + (size_t)m*ldD + coff + col)
                = make_float2(acc[nt][0]+bsh[col], acc[nt][1]+bsh[col+1]);
        if (m + 8 < NH)
            *(float2*)(dst + (size_t)(m+8)*ldD + coff + col)
                = make_float2(acc[nt][2]+bsh[col], acc[nt][3]+bsh[col+1]);
    }
}

// ---------------- attention scores + segment max -----------------------------
__global__ void score_kernel(const int* __restrict__ ei) {
    int gw = (blockIdx.x*blockDim.x + threadIdx.x) >> 5;
    int lane = threadIdx.x & 31;
    if (gw >= NREL*NEDGE) return;
    int r = gw / NEDGE, w = gw - r*NEDGE;
    const int* base = ei + (size_t)r*2*NEDGE;
    int hsrc = base[w] + c_off[c_tsrc[r]];
    int hdst = base[NEDGE + w] + c_off[c_tdst[r]];
    int h = lane >> 4, l4 = lane & 15;
    float4 a = ((const float4*)(g_q + (size_t)hdst*128 + h*64))[l4];
    float4 b = ((const float4*)(g_k + (size_t)hsrc*128 + h*64))[l4];
    float p = a.x*b.x + a.y*b.y + a.z*b.z + a.w*b.w;
    p += __shfl_xor_sync(0xffffffffu, p, 8);
    p += __shfl_xor_sync(0xffffffffu, p, 4);
    p += __shfl_xor_sync(0xffffffffu, p, 2);
    p += __shfl_xor_sync(0xffffffffu, p, 1);
    if (l4 == 0) {
        float s = p * 0.125f;
        g_score[(size_t)gw*2 + h] = s;
        unsigned u = __float_as_uint(s);
        unsigned key = (u & 0x80000000u) ? ~u : (u | 0x80000000u);
        atomicMax(&g_smax[hdst*2 + h], key);
    }
}

// ---------------- attention exp + weighted-v scatter -------------------------
__global__ void attn_kernel(const int* __restrict__ ei) {
    int gw = (blockIdx.x*blockDim.x + threadIdx.x) >> 5;
    int lane = threadIdx.x & 31;
    if (gw >= NREL*NEDGE) return;
    int r = gw / NEDGE, w = gw - r*NEDGE;
    const int* base = ei + (size_t)r*2*NEDGE;
    int hsrc = base[w] + c_off[c_tsrc[r]];
    int hdst = base[NEDGE + w] + c_off[c_tdst[r]];
    int h = lane >> 4, l4 = lane & 15;
    float s = g_score[(size_t)gw*2 + h];
    unsigned key = g_smax[hdst*2 + h];
    float m = (key & 0x80000000u) ? __uint_as_float(key ^ 0x80000000u)
                                  : __uint_as_float(~key);
    float a = __expf(s - m);
    float4 v = ((const float4*)(g_v + (size_t)hsrc*128 + h*64))[l4];
    red_add_v4(g_num + (size_t)hdst*128 + h*64 + l4*4,
               make_float4(a*v.x, a*v.y, a*v.z, a*v.w));
    if (l4 == 0) atomicAdd(&g_den[hdst*2 + h], a);
}

// ---------------- finalize rows + channel stats ------------------------------
__global__ void reduce_kernel() {
    int c = threadIdx.x & 63;
    int sub = threadIdx.x >> 6;
    int base = blockIdx.x * 256;
    double s = 0.0, s2 = 0.0;
    for (int i = 0; i < 64; i++) {
        int m = base + sub*64 + i;
        if (m < NH) {
            float d0 = g_den[m*2]     + 1e-16f;
            float d1 = g_den[m*2 + 1] + 1e-16f;
            float val = g_outb[(size_t)m*64 + c]
                      + 0.5f * (g_num[(size_t)m*128 + c] / d0
                              + g_num[(size_t)m*128 + 64 + c] / d1);
            g_outb[(size_t)m*64 + c] = val;
            s += val;
            s2 += (double)val * (double)val;
        }
    }
    __shared__ double ss[256], sq[256];
    ss[threadIdx.x] = s; sq[threadIdx.x] = s2;
    __syncthreads();
    if (threadIdx.x < 64) {
        double ts = ss[threadIdx.x] + ss[threadIdx.x+64] + ss[threadIdx.x+128] + ss[threadIdx.x+192];
        double tq = sq[threadIdx.x] + sq[threadIdx.x+64] + sq[threadIdx.x+128] + sq[threadIdx.x+192];
        atomicAdd(&g_sum[c], ts);
        atomicAdd(&g_sumsq[c], tq);
    }
}

__global__ void stats_kernel() {
    int c = threadIdx.x;
    double mu = g_sum[c] / (double)NH;
    double var = g_sumsq[c] / (double)NH - mu*mu;
    g_mu[c] = (float)mu;
    g_rstd[c] = rsqrtf((float)var + 1e-5f);
}

// ---------------- layernorm + leaky relu + permuted output -------------------
__global__ void final_kernel(const float* __restrict__ gamma,
                             const float* __restrict__ beta,
                             float* __restrict__ out) {
    int idx = blockIdx.x*blockDim.x + threadIdx.x;
    if (idx >= 3*NPER*CH) return;
    int c = idx & 63;
    int rown = idx >> 6;
    int b = rown / NPER, n = rown - b*NPER;
    int srow = (b == 0) ? n : ((b == 1) ? (2*NPER + n) : (NPER + n));
    float v = g_outb[(size_t)srow*CH + c];
    v = gamma[c] * (v - g_mu[c]) * g_rstd[c] + beta[c];
    out[idx] = (v >= 0.f) ? v : 0.01f * v;
}

// ---------------- host orchestration -----------------------------------------
extern "C" void kernel_launch(void* const* d_in, const int* in_sizes, int n_in,
                              void* d_out, int out_size) {
    const float* x     = (const float*)d_in[0];
    const int*   ei    = (const int*)  d_in[1];
    const float* Wlin  = (const float*)d_in[2];
    const float* blin  = (const float*)d_in[3];
    const float* Wa    = (const float*)d_in[4];
    const float* ba    = (const float*)d_in[5];
    const float* Wq    = (const float*)d_in[6];
    const float* bq    = (const float*)d_in[7];
    const float* Wk    = (const float*)d_in[8];
    const float* bk    = (const float*)d_in[9];
    const float* Wv    = (const float*)d_in[10];
    const float* bv    = (const float*)d_in[11];
    const float* Wskip = (const float*)d_in[12];
    const float* bskip = (const float*)d_in[13];
    const float* gamma = (const float*)d_in[14];
    const float* beta  = (const float*)d_in[15];
    float* out = (float*)d_out;

    cudaFuncSetAttribute(lin_mma_kernel, cudaFuncAttributeMaxDynamicSharedMemorySize, DSMEM_BYTES);
    cudaFuncSetAttribute(qkv_mma_kernel, cudaFuncAttributeMaxDynamicSharedMemorySize, DSMEM_BYTES);

    void *p_cnt, *p_acc, *p_num, *p_den, *p_smax, *p_sum, *p_sumsq, *p_xd, *p_hx;
    cudaGetSymbolAddress(&p_cnt, g_cnt);
    cudaGetSymbolAddress(&p_acc, g_acc);
    cudaGetSymbolAddress(&p_num, g_num);
    cudaGetSymbolAddress(&p_den, g_den);
    cudaGetSymbolAddress(&p_smax, g_smax);
    cudaGetSymbolAddress(&p_sum, g_sum);
    cudaGetSymbolAddress(&p_sumsq, g_sumsq);
    cudaGetSymbolAddress(&p_xd, g_xd);
    cudaGetSymbolAddress(&p_hx, g_hx);

    cudaMemsetAsync(p_cnt, 0, sizeof(float)*NREL*NPER);
    cnt_kernel<<<(NREL*NEDGE + 255)/256, 256>>>(ei);
    icnt_kernel<<<(NREL*NPER + 255)/256, 256>>>();

    for (int l = 0; l < 2; l++) {
        const float* xin = (l == 0) ? x : (const float*)p_xd;
        const float* Wlin_l = Wlin + (size_t)l*NREL*4096;
        const float* blin_l = blin + (size_t)l*NREL*64;
        const float* Wa_l   = Wa   + (size_t)l*NREL*128;
        const float* ba_l   = ba   + (size_t)l*NREL;
        prep_u_kernel<<<1, 64>>>(Wlin_l, blin_l, Wa_l);
        lin_mma_kernel<<<dim3(313, 15), 256, DSMEM_BYTES>>>(xin, Wlin_l, blin_l, Wa_l, ba_l);
        ad_cross_kernel<<<dim3(2500, 6), 256>>>(xin, ba_l);
        cudaMemsetAsync(p_acc, 0, sizeof(float)*3*NPER*CH);
        edge_scatter_kernel<<<28125, 256>>>(ei);
        relu_kernel<<<(3*NPER*16 + 255)/256, 256>>>(l, l == 0 ? (float*)p_xd : (float*)p_hx);
    }
    cudaMemsetAsync(p_num, 0, sizeof(float)*(size_t)NH*128);
    cudaMemsetAsync(p_den, 0, sizeof(float)*NH*2);
    cudaMemsetAsync(p_smax, 0, sizeof(unsigned)*NH*2);
    cudaMemsetAsync(p_sum, 0, sizeof(double)*CH);
    cudaMemsetAsync(p_sumsq, 0, sizeof(double)*CH);

    qkv_mma_kernel<<<dim3(938, 7), 256, DSMEM_BYTES>>>(Wq, bq, Wk, bk, Wv, bv, Wskip, bskip);
    score_kernel<<<56250, 256>>>(ei);
    attn_kernel<<<56250, 256>>>(ei);
    reduce_kernel<<<235, 256>>>();
    stats_kernel<<<1, 64>>>();
    final_kernel<<<15000, 256>>>(gamma, beta, out);
}

// round 7
// speedup vs baseline: 1.1637x; 1.1637x over previous
#include <cuda_runtime.h>
#include <cuda_bf16.h>
#include <math.h>

#define NPER 20000
#define CH 64
#define NREL 15
#define NEDGE 30000
#define NH 60000

__constant__ int c_tsrc[NREL] = {0,1,2,0,1,2,0,1,2,0,0,1,1,2,2};
__constant__ int c_tdst[NREL] = {0,1,2,0,1,2,0,1,2,1,2,0,2,0,1};
__constant__ int c_off[3] = {0, 2*NPER, NPER};

// ---------------- scratch (device globals; no allocs allowed) ----------------
__device__ float    g_hs[(size_t)NREL*NPER*CH];
__device__ float    g_as[NREL*NPER];
__device__ float    g_ad[NREL*NPER];
__device__ float    g_cnt[NREL*NPER];
__device__ float    g_icnt[NREL*NPER];
__device__ float    g_acc[3*NPER*CH];
__device__ float    g_xd[3*NPER*CH];       // layer-1 output (type-major)
__device__ float    g_hx[3*NPER*CH];       // layer-2 output (attention row order)
__device__ float    g_u0[6*CH];
__device__ float    g_cd[6];
__device__ float    g_q[(size_t)NH*128];
__device__ float    g_k[(size_t)NH*128];
__device__ float    g_v[(size_t)NH*128];
__device__ float    g_outb[(size_t)NH*CH];
__device__ float    g_score[(size_t)NREL*NEDGE*2];
__device__ unsigned g_smax[NH*2];
__device__ float    g_den[NH*2];
__device__ float    g_num[(size_t)NH*128];
__device__ double   g_sum[CH];
__device__ double   g_sumsq[CH];
__device__ float    g_mu[CH];
__device__ float    g_rstd[CH];

__device__ __forceinline__ void red_add_v4(float* p, float4 v) {
    asm volatile("red.global.add.v4.f32 [%0], {%1,%2,%3,%4};"
                 :: "l"(p), "f"(v.x), "f"(v.y), "f"(v.z), "f"(v.w) : "memory");
}
__device__ __forceinline__ void mma_bf16(float c[4], unsigned a0, unsigned a1,
                                         unsigned a2, unsigned a3,
                                         unsigned b0, unsigned b1) {
    asm volatile("mma.sync.aligned.m16n8k16.row.col.f32.bf16.bf16.f32 "
                 "{%0,%1,%2,%3}, {%4,%5,%6,%7}, {%8,%9}, {%0,%1,%2,%3};"
                 : "+f"(c[0]), "+f"(c[1]), "+f"(c[2]), "+f"(c[3])
                 : "r"(a0), "r"(a1), "r"(a2), "r"(a3), "r"(b0), "r"(b1));
}
// pack two floats' bf16 roundings: lo in bits[0:16), hi in bits[16:32)
__device__ __forceinline__ unsigned pack_hi2(float lo, float hi) {
    __nv_bfloat162 b = __floats2bfloat162_rn(lo, hi);
    return *(unsigned*)&b;
}
__device__ __forceinline__ unsigned pack_lo2(float lo, float hi, unsigned hw) {
    __nv_bfloat162 b = *(__nv_bfloat162*)&hw;
    __nv_bfloat162 r = __floats2bfloat162_rn(lo - __bfloat162float(b.x),
                                             hi - __bfloat162float(b.y));
    return *(unsigned*)&r;
}

#define LDP 36   // plane row stride in u32 (64 bf16 = 32 u32, +4 pad)

// ---------------- edge counts (static across layers) -------------------------
__global__ void cnt_kernel(const int* __restrict__ ei) {
    int e = blockIdx.x*blockDim.x + threadIdx.x;
    if (e >= NREL*NEDGE) return;
    int r = e / NEDGE, w = e - r*NEDGE;
    int dst = ei[(size_t)r*2*NEDGE + NEDGE + w];
    atomicAdd(&g_cnt[r*NPER + dst], 1.0f);
}
__global__ void icnt_kernel() {
    int i = blockIdx.x*blockDim.x + threadIdx.x;
    if (i < NREL*NPER) g_icnt[i] = 0.2f / fmaxf(g_cnt[i], 1.0f);
}

// ---------------- prep: u0 = Wlin @ wa0, cd = blin . wa0 (cross relations) ---
__global__ void prep_u_kernel(const float* __restrict__ Wlin_l,
                              const float* __restrict__ blin_l,
                              const float* __restrict__ Wa_l) {
    int k = threadIdx.x; // 64
    for (int j = 0; j < 6; j++) {
        int r = 9 + j;
        const float* W = Wlin_l + r*4096 + k*64;
        const float* wa0 = Wa_l + r*128;
        float s = 0.f;
        #pragma unroll 8
        for (int c = 0; c < 64; c++) s += W[c] * wa0[c];
        g_u0[j*64 + k] = s;
    }
    if (k < 6) {
        int r = 9 + k;
        float s = 0.f;
        for (int c = 0; c < 64; c++) s += blin_l[r*64 + c] * Wa_l[r*128 + c];
        g_cd[k] = s;
    }
}

// ---------------- hs = x[tsrc] @ Wlin + blin  (bf16x2-split MMA) -------------
// 64-row tile, 8 warps = 4 row-groups x 2 col-halves. Fused a_s/a_d epilogue.
__global__ void lin_mma_kernel(const float* __restrict__ x,
                               const float* __restrict__ Wlin_l,
                               const float* __restrict__ blin_l,
                               const float* __restrict__ Wa_l,
                               const float* __restrict__ ba_l) {
    __shared__ unsigned xp0[64][LDP], xp1[64][LDP];   // x planes, [row][k-pairs]
    __shared__ unsigned wp0[64][LDP], wp1[64][LDP];   // W^T planes, [n][k-pairs]
    __shared__ float bsh[64], wa0s[64], wa1s[64];
    __shared__ float red_s[64][2], red_d[64][2];
    int r = blockIdx.y;
    int tid = threadIdx.x;
    const float* W = Wlin_l + r*4096;
    // W transpose + split: B[n][k] = W[k][n]
    for (int i = tid; i < 4096; i += 256) {
        int k = i >> 6, n = i & 63;        // coalesced global read over n
        float v = W[i];
        __nv_bfloat16 b0 = __float2bfloat16(v);
        ((__nv_bfloat16*)wp0)[n*(2*LDP) + k] = b0;
        ((__nv_bfloat16*)wp1)[n*(2*LDP) + k] = __float2bfloat16(v - __bfloat162float(b0));
    }
    if (tid < 64) {
        bsh[tid]  = blin_l[r*64 + tid];
        wa0s[tid] = Wa_l[r*128 + tid];
        wa1s[tid] = Wa_l[r*128 + 64 + tid];
    }
    int t = c_tsrc[r];
    int row0 = blockIdx.x*64;
    const float* xb = x + ((size_t)t*NPER + row0)*CH;
    for (int i = tid; i < 1024; i += 256) {
        int rr = i >> 4, cu = (i & 15)*2;  // u32 (bf16-pair) column
        float4 v = (row0 + rr < NPER) ? ((const float4*)xb)[i]
                                      : make_float4(0.f,0.f,0.f,0.f);
        unsigned h0 = pack_hi2(v.x, v.y), h1 = pack_hi2(v.z, v.w);
        xp0[rr][cu]   = h0;
        xp0[rr][cu+1] = h1;
        xp1[rr][cu]   = pack_lo2(v.x, v.y, h0);
        xp1[rr][cu+1] = pack_lo2(v.z, v.w, h1);
    }
    __syncthreads();

    int warp = tid >> 5, lane = tid & 31;
    int wr = warp >> 1, wc = warp & 1;
    int gid = lane >> 2, tig = lane & 3;
    int rA = wr*16 + gid;
    float acc[4][4];
    #pragma unroll
    for (int nt = 0; nt < 4; nt++)
        #pragma unroll
        for (int j = 0; j < 4; j++) acc[nt][j] = 0.f;

    #pragma unroll
    for (int kk = 0; kk < 4; kk++) {
        int ku = kk*8;
        unsigned a0h = xp0[rA][ku+tig],   a1h = xp0[rA+8][ku+tig];
        unsigned a2h = xp0[rA][ku+tig+4], a3h = xp0[rA+8][ku+tig+4];
        unsigned a0l = xp1[rA][ku+tig],   a1l = xp1[rA+8][ku+tig];
        unsigned a2l = xp1[rA][ku+tig+4], a3l = xp1[rA+8][ku+tig+4];
        #pragma unroll
        for (int nt = 0; nt < 4; nt++) {
            int n0 = wc*32 + nt*8 + gid;
            unsigned b0h = wp0[n0][ku+tig], b1h = wp0[n0][ku+tig+4];
            unsigned b0l = wp1[n0][ku+tig], b1l = wp1[n0][ku+tig+4];
            mma_bf16(acc[nt], a0h, a1h, a2h, a3h, b0h, b1h);
            mma_bf16(acc[nt], a0l, a1l, a2l, a3l, b0h, b1h);
            mma_bf16(acc[nt], a0h, a1h, a2h, a3h, b0l, b1l);
        }
    }
    // bias + store hs + fused a_s/a_d partial dots
    int n = row0 + rA;
    float* base = g_hs + ((size_t)r*NPER + n)*CH;
    float sA = 0.f, sB = 0.f, dA = 0.f, dB = 0.f;
    #pragma unroll
    for (int nt = 0; nt < 4; nt++) {
        int col = wc*32 + nt*8 + 2*tig;
        float c0 = acc[nt][0] + bsh[col], c1 = acc[nt][1] + bsh[col+1];
        float c2 = acc[nt][2] + bsh[col], c3 = acc[nt][3] + bsh[col+1];
        if (n < NPER)     *(float2*)(base + col)        = make_float2(c0, c1);
        if (n + 8 < NPER) *(float2*)(base + 8*CH + col) = make_float2(c2, c3);
        sA += c0*wa1s[col] + c1*wa1s[col+1];
        sB += c2*wa1s[col] + c3*wa1s[col+1];
        dA += c0*wa0s[col] + c1*wa0s[col+1];
        dB += c2*wa0s[col] + c3*wa0s[col+1];
    }
    sA += __shfl_xor_sync(0xffffffffu, sA, 1); sA += __shfl_xor_sync(0xffffffffu, sA, 2);
    sB += __shfl_xor_sync(0xffffffffu, sB, 1); sB += __shfl_xor_sync(0xffffffffu, sB, 2);
    dA += __shfl_xor_sync(0xffffffffu, dA, 1); dA += __shfl_xor_sync(0xffffffffu, dA, 2);
    dB += __shfl_xor_sync(0xffffffffu, dB, 1); dB += __shfl_xor_sync(0xffffffffu, dB, 2);
    if (tig == 0) {
        red_s[rA][wc] = sA;   red_s[rA+8][wc] = sB;
        red_d[rA][wc] = dA;   red_d[rA+8][wc] = dB;
    }
    __syncthreads();
    if (tid < 64 && row0 + tid < NPER) {
        g_as[r*NPER + row0 + tid] = red_s[tid][0] + red_s[tid][1];
        if (r < 9)
            g_ad[r*NPER + row0 + tid] = red_d[tid][0] + red_d[tid][1] + ba_l[r];
    }
}

// ---------------- a_d for the 6 cross-type relations -------------------------
__global__ void ad_cross_kernel(const float* __restrict__ x,
                                const float* __restrict__ ba_l) {
    int j = blockIdx.y;
    int r = 9 + j;
    int warp = threadIdx.x >> 5, lane = threadIdx.x & 31;
    int n = blockIdx.x*8 + warp;
    int t = c_tdst[r];
    const float* xrow = x + ((size_t)t*NPER + n)*CH;
    float p = xrow[lane]*g_u0[j*64 + lane] + xrow[lane+32]*g_u0[j*64 + lane + 32];
    #pragma unroll
    for (int s = 16; s; s >>= 1) p += __shfl_xor_sync(0xffffffffu, p, s);
    if (lane == 0) g_ad[r*NPER + n] = p + g_cd[j] + ba_l[r];
}

// ---------------- per-edge gated message scatter (direct to type accum) ------
__global__ void edge_scatter_kernel(const int* __restrict__ ei) {
    int idx = blockIdx.x*blockDim.x + threadIdx.x;
    int e = idx >> 4, lane = idx & 15;
    if (e >= NREL*NEDGE) return;
    int r = e / NEDGE, w = e - r*NEDGE;
    const int* base = ei + (size_t)r*2*NEDGE;
    int src = base[w], dst = base[NEDGE + w];
    float g = 0.f;
    if (lane == 0)
        g = tanhf(g_ad[r*NPER + dst] + g_as[r*NPER + src]) * g_icnt[r*NPER + dst];
    g = __shfl_sync(0xffffffffu, g, threadIdx.x & 16);
    float4 h = ((const float4*)(g_hs + ((size_t)r*NPER + src)*CH))[lane];
    int t = c_tdst[r];
    red_add_v4(g_acc + ((size_t)t*NPER + dst)*CH + lane*4,
               make_float4(g*h.x, g*h.y, g*h.z, g*h.w));
}

// ---------------- relu + store layer output ----------------------------------
__global__ void relu_kernel(int mode, float* __restrict__ dst) {
    int idx = blockIdx.x*blockDim.x + threadIdx.x;
    if (idx >= 3*NPER*16) return;
    int lane = idx & 15, tn = idx >> 4;
    int t = tn / NPER, n = tn - t*NPER;
    float4 a = ((const float4*)(g_acc + (size_t)tn*CH))[lane];
    a.x = fmaxf(a.x, 0.f); a.y = fmaxf(a.y, 0.f);
    a.z = fmaxf(a.z, 0.f); a.w = fmaxf(a.w, 0.f);
    int row = mode ? (c_off[t] + n) : tn;
    ((float4*)(dst + (size_t)row*CH))[lane] = a;
}

// ---------------- q/k/v/skip GEMM via bf16x2-split MMA (7 chunks) ------------
__global__ void qkv_mma_kernel(const float* __restrict__ Wq, const float* __restrict__ bq,
                               const float* __restrict__ Wk, const float* __restrict__ bk,
                               const float* __restrict__ Wv, const float* __restrict__ bv,
                               const float* __restrict__ Wskip, const float* __restrict__ bskip) {
    __shared__ unsigned xp0[64][LDP], xp1[64][LDP];
    __shared__ unsigned wp0[64][LDP], wp1[64][LDP];
    __shared__ float bsh[64];
    int chunk = blockIdx.y;
    const float *Wsrc, *bsrc;
    float* dst;
    int ldW, coff, ldD;
    if (chunk < 2)      { Wsrc = Wq;    bsrc = bq;    dst = g_q;    ldW = 128; coff = chunk*64;     ldD = 128; }
    else if (chunk < 4) { Wsrc = Wk;    bsrc = bk;    dst = g_k;    ldW = 128; coff = (chunk-2)*64; ldD = 128; }
    else if (chunk < 6) { Wsrc = Wv;    bsrc = bv;    dst = g_v;    ldW = 128; coff = (chunk-4)*64; ldD = 128; }
    else                { Wsrc = Wskip; bsrc = bskip; dst = g_outb; ldW = 64;  coff = 0;            ldD = 64;  }
    int tid = threadIdx.x;
    for (int i = tid; i < 4096; i += 256) {
        int k = i >> 6, n = i & 63;
        float v = Wsrc[k*ldW + coff + n];
        __nv_bfloat16 b0 = __float2bfloat16(v);
        ((__nv_bfloat16*)wp0)[n*(2*LDP) + k] = b0;
        ((__nv_bfloat16*)wp1)[n*(2*LDP) + k] = __float2bfloat16(v - __bfloat162float(b0));
    }
    if (tid < 64) bsh[tid] = bsrc[coff + tid];
    int m0 = blockIdx.x*64;
    const float* xb = g_hx + (size_t)m0*CH;
    for (int i = tid; i < 1024; i += 256) {
        int rr = i >> 4, cu = (i & 15)*2;
        float4 v = (m0 + rr < NH) ? ((const float4*)xb)[i]
                                  : make_float4(0.f,0.f,0.f,0.f);
        unsigned h0 = pack_hi2(v.x, v.y), h1 = pack_hi2(v.z, v.w);
        xp0[rr][cu]   = h0;
        xp0[rr][cu+1] = h1;
        xp1[rr][cu]   = pack_lo2(v.x, v.y, h0);
        xp1[rr][cu+1] = pack_lo2(v.z, v.w, h1);
    }
    __syncthreads();

    int warp = tid >> 5, lane = tid & 31;
    int wr = warp >> 1, wc = warp & 1;
    int gid = lane >> 2, tig = lane & 3;
    int rA = wr*16 + gid;
    float acc[4][4];
    #pragma unroll
    for (int nt = 0; nt < 4; nt++)
        #pragma unroll
        for (int j = 0; j < 4; j++) acc[nt][j] = 0.f;

    #pragma unroll
    for (int kk = 0; kk < 4; kk++) {
        int ku = kk*8;
        unsigned a0h = xp0[rA][ku+tig],   a1h = xp0[rA+8][ku+tig];
        unsigned a2h = xp0[rA][ku+tig+4], a3h = xp0[rA+8][ku+tig+4];
        unsigned a0l = xp1[rA][ku+tig],   a1l = xp1[rA+8][ku+tig];
        unsigned a2l = xp1[rA][ku+tig+4], a3l = xp1[rA+8][ku+tig+4];
        #pragma unroll
        for (int nt = 0; nt < 4; nt++) {
            int n0 = wc*32 + nt*8 + gid;
            unsigned b0h = wp0[n0][ku+tig], b1h = wp0[n0][ku+tig+4];
            unsigned b0l = wp1[n0][ku+tig], b1l = wp1[n0][ku+tig+4];
            mma_bf16(acc[nt], a0h, a1h, a2h, a3h, b0h, b1h);
            mma_bf16(acc[nt], a0l, a1l, a2l, a3l, b0h, b1h);
            mma_bf16(acc[nt], a0h, a1h, a2h, a3h, b0l, b1l);
        }
    }
    int m = m0 + rA;
    #pragma unroll
    for (int nt = 0; nt < 4; nt++) {
        int col = wc*32 + nt*8 + 2*tig;
        if (m < NH)
            *(float2*)(dst + (size_t)m*ldD + coff + col)
                = make_float2(acc[nt][0]+bsh[col], acc[nt][1]+bsh[col+1]);
        if (m + 8 < NH)
            *(float2*)(dst + (size_t)(m+8)*ldD + coff + col)
                = make_float2(acc[nt][2]+bsh[col], acc[nt][3]+bsh[col+1]);
    }
}

// ---------------- attention scores + segment max -----------------------------
__global__ void score_kernel(const int* __restrict__ ei) {
    int gw = (blockIdx.x*blockDim.x + threadIdx.x) >> 5;
    int lane = threadIdx.x & 31;
    if (gw >= NREL*NEDGE) return;
    int r = gw / NEDGE, w = gw - r*NEDGE;
    const int* base = ei + (size_t)r*2*NEDGE;
    int hsrc = base[w] + c_off[c_tsrc[r]];
    int hdst = base[NEDGE + w] + c_off[c_tdst[r]];
    int h = lane >> 4, l4 = lane & 15;
    float4 a = ((const float4*)(g_q + (size_t)hdst*128 + h*64))[l4];
    float4 b = ((const float4*)(g_k + (size_t)hsrc*128 + h*64))[l4];
    float p = a.x*b.x + a.y*b.y + a.z*b.z + a.w*b.w;
    p += __shfl_xor_sync(0xffffffffu, p, 8);
    p += __shfl_xor_sync(0xffffffffu, p, 4);
    p += __shfl_xor_sync(0xffffffffu, p, 2);
    p += __shfl_xor_sync(0xffffffffu, p, 1);
    if (l4 == 0) {
        float s = p * 0.125f;
        g_score[(size_t)gw*2 + h] = s;
        unsigned u = __float_as_uint(s);
        unsigned key = (u & 0x80000000u) ? ~u : (u | 0x80000000u);
        atomicMax(&g_smax[hdst*2 + h], key);
    }
}

// ---------------- attention exp + weighted-v scatter -------------------------
__global__ void attn_kernel(const int* __restrict__ ei) {
    int gw = (blockIdx.x*blockDim.x + threadIdx.x) >> 5;
    int lane = threadIdx.x & 31;
    if (gw >= NREL*NEDGE) return;
    int r = gw / NEDGE, w = gw - r*NEDGE;
    const int* base = ei + (size_t)r*2*NEDGE;
    int hsrc = base[w] + c_off[c_tsrc[r]];
    int hdst = base[NEDGE + w] + c_off[c_tdst[r]];
    int h = lane >> 4, l4 = lane & 15;
    float s = g_score[(size_t)gw*2 + h];
    unsigned key = g_smax[hdst*2 + h];
    float m = (key & 0x80000000u) ? __uint_as_float(key ^ 0x80000000u)
                                  : __uint_as_float(~key);
    float a = __expf(s - m);
    float4 v = ((const float4*)(g_v + (size_t)hsrc*128 + h*64))[l4];
    red_add_v4(g_num + (size_t)hdst*128 + h*64 + l4*4,
               make_float4(a*v.x, a*v.y, a*v.z, a*v.w));
    if (l4 == 0) atomicAdd(&g_den[hdst*2 + h], a);
}

// ---------------- finalize rows + channel stats ------------------------------
__global__ void reduce_kernel() {
    int c = threadIdx.x & 63;
    int sub = threadIdx.x >> 6;
    int base = blockIdx.x * 256;
    double s = 0.0, s2 = 0.0;
    for (int i = 0; i < 64; i++) {
        int m = base + sub*64 + i;
        if (m < NH) {
            float d0 = g_den[m*2]     + 1e-16f;
            float d1 = g_den[m*2 + 1] + 1e-16f;
            float val = g_outb[(size_t)m*64 + c]
                      + 0.5f * (g_num[(size_t)m*128 + c] / d0
                              + g_num[(size_t)m*128 + 64 + c] / d1);
            g_outb[(size_t)m*64 + c] = val;
            s += val;
            s2 += (double)val * (double)val;
        }
    }
    __shared__ double ss[256], sq[256];
    ss[threadIdx.x] = s; sq[threadIdx.x] = s2;
    __syncthreads();
    if (threadIdx.x < 64) {
        double ts = ss[threadIdx.x] + ss[threadIdx.x+64] + ss[threadIdx.x+128] + ss[threadIdx.x+192];
        double tq = sq[threadIdx.x] + sq[threadIdx.x+64] + sq[threadIdx.x+128] + sq[threadIdx.x+192];
        atomicAdd(&g_sum[c], ts);
        atomicAdd(&g_sumsq[c], tq);
    }
}

__global__ void stats_kernel() {
    int c = threadIdx.x;
    double mu = g_sum[c] / (double)NH;
    double var = g_sumsq[c] / (double)NH - mu*mu;
    g_mu[c] = (float)mu;
    g_rstd[c] = rsqrtf((float)var + 1e-5f);
}

// ---------------- layernorm + leaky relu + permuted output -------------------
__global__ void final_kernel(const float* __restrict__ gamma,
                             const float* __restrict__ beta,
                             float* __restrict__ out) {
    int idx = blockIdx.x*blockDim.x + threadIdx.x;
    if (idx >= 3*NPER*CH) return;
    int c = idx & 63;
    int rown = idx >> 6;
    int b = rown / NPER, n = rown - b*NPER;
    int srow = (b == 0) ? n : ((b == 1) ? (2*NPER + n) : (NPER + n));
    float v = g_outb[(size_t)srow*CH + c];
    v = gamma[c] * (v - g_mu[c]) * g_rstd[c] + beta[c];
    out[idx] = (v >= 0.f) ? v : 0.01f * v;
}

// ---------------- host orchestration -----------------------------------------
extern "C" void kernel_launch(void* const* d_in, const int* in_sizes, int n_in,
                              void* d_out, int out_size) {
    const float* x     = (const float*)d_in[0];
    const int*   ei    = (const int*)  d_in[1];
    const float* Wlin  = (const float*)d_in[2];
    const float* blin  = (const float*)d_in[3];
    const float* Wa    = (const float*)d_in[4];
    const float* ba    = (const float*)d_in[5];
    const float* Wq    = (const float*)d_in[6];
    const float* bq    = (const float*)d_in[7];
    const float* Wk    = (const float*)d_in[8];
    const float* bk    = (const float*)d_in[9];
    const float* Wv    = (const float*)d_in[10];
    const float* bv    = (const float*)d_in[11];
    const float* Wskip = (const float*)d_in[12];
    const float* bskip = (const float*)d_in[13];
    const float* gamma = (const float*)d_in[14];
    const float* beta  = (const float*)d_in[15];
    float* out = (float*)d_out;

    void *p_cnt, *p_acc, *p_num, *p_den, *p_smax, *p_sum, *p_sumsq, *p_xd, *p_hx;
    cudaGetSymbolAddress(&p_cnt, g_cnt);
    cudaGetSymbolAddress(&p_acc, g_acc);
    cudaGetSymbolAddress(&p_num, g_num);
    cudaGetSymbolAddress(&p_den, g_den);
    cudaGetSymbolAddress(&p_smax, g_smax);
    cudaGetSymbolAddress(&p_sum, g_sum);
    cudaGetSymbolAddress(&p_sumsq, g_sumsq);
    cudaGetSymbolAddress(&p_xd, g_xd);
    cudaGetSymbolAddress(&p_hx, g_hx);

    cudaMemsetAsync(p_cnt, 0, sizeof(float)*NREL*NPER);
    cnt_kernel<<<(NREL*NEDGE + 255)/256, 256>>>(ei);
    icnt_kernel<<<(NREL*NPER + 255)/256, 256>>>();

    for (int l = 0; l < 2; l++) {
        const float* xin = (l == 0) ? x : (const float*)p_xd;
        const float* Wlin_l = Wlin + (size_t)l*NREL*4096;
        const float* blin_l = blin + (size_t)l*NREL*64;
        const float* Wa_l   = Wa   + (size_t)l*NREL*128;
        const float* ba_l   = ba   + (size_t)l*NREL;
        prep_u_kernel<<<1, 64>>>(Wlin_l, blin_l, Wa_l);
        lin_mma_kernel<<<dim3(313, 15), 256>>>(xin, Wlin_l, blin_l, Wa_l, ba_l);
        ad_cross_kernel<<<dim3(2500, 6), 256>>>(xin, ba_l);
        cudaMemsetAsync(p_acc, 0, sizeof(float)*3*NPER*CH);
        edge_scatter_kernel<<<28125, 256>>>(ei);
        relu_kernel<<<(3*NPER*16 + 255)/256, 256>>>(l, l == 0 ? (float*)p_xd : (float*)p_hx);
    }
    cudaMemsetAsync(p_num, 0, sizeof(float)*(size_t)NH*128);
    cudaMemsetAsync(p_den, 0, sizeof(float)*NH*2);
    cudaMemsetAsync(p_smax, 0, sizeof(unsigned)*NH*2);
    cudaMemsetAsync(p_sum, 0, sizeof(double)*CH);
    cudaMemsetAsync(p_sumsq, 0, sizeof(double)*CH);

    qkv_mma_kernel<<<dim3(938, 7), 256>>>(Wq, bq, Wk, bk, Wv, bv, Wskip, bskip);
    score_kernel<<<56250, 256>>>(ei);
    attn_kernel<<<56250, 256>>>(ei);
    reduce_kernel<<<235, 256>>>();
    stats_kernel<<<1, 64>>>();
    final_kernel<<<15000, 256>>>(gamma, beta, out);
}

// round 8
// speedup vs baseline: 1.2134x; 1.0427x over previous
#include <cuda_runtime.h>
#include <cuda_bf16.h>
#include <math.h>

#define NPER 20000
#define CH 64
#define NREL 15
#define NEDGE 30000
#define NH 60000

__constant__ int c_tsrc[NREL] = {0,1,2,0,1,2,0,1,2,0,0,1,1,2,2};
__constant__ int c_tdst[NREL] = {0,1,2,0,1,2,0,1,2,1,2,0,2,0,1};
__constant__ int c_off[3] = {0, 2*NPER, NPER};

// ---------------- scratch (device globals; no allocs allowed) ----------------
__device__ float    g_hs[(size_t)NREL*NPER*CH];
__device__ float    g_as[NREL*NPER];
__device__ float    g_ad[NREL*NPER];
__device__ float    g_cnt[NREL*NPER];
__device__ float    g_icnt[NREL*NPER];
__device__ float    g_acc[3*NPER*CH];
__device__ float    g_xd[3*NPER*CH];       // layer-1 output (type-major)
__device__ float    g_hx[3*NPER*CH];       // layer-2 output (attention row order)
__device__ float    g_u0[6*CH];
__device__ float    g_cd[6];
__device__ float    g_q[(size_t)NH*128];
__device__ float    g_k[(size_t)NH*128];
__device__ float    g_v[(size_t)NH*128];
__device__ float    g_outb[(size_t)NH*CH];
__device__ float    g_score[(size_t)NREL*NEDGE*2];
__device__ unsigned g_smax[NH*2];
__device__ float    g_den[NH*2];
__device__ float    g_num[(size_t)NH*128];
__device__ double   g_sum[CH];
__device__ double   g_sumsq[CH];
__device__ float    g_mu[CH];
__device__ float    g_rstd[CH];
// bf16 plane buffers (hi/lo splits)
__device__ unsigned g_wl0[NREL*64*32], g_wl1[NREL*64*32];   // lin W^T planes, per layer
__device__ unsigned g_wq0[7*64*32],    g_wq1[7*64*32];      // qkv W^T planes (once)
__device__ unsigned g_xb0[3*NPER*32],  g_xb1[3*NPER*32];    // lin input planes (type-major)
__device__ unsigned g_hxb0[NH*32],     g_hxb1[NH*32];       // qkv input planes (hx order)

__device__ __forceinline__ void red_add_v4(float* p, float4 v) {
    asm volatile("red.global.add.v4.f32 [%0], {%1,%2,%3,%4};"
                 :: "l"(p), "f"(v.x), "f"(v.y), "f"(v.z), "f"(v.w) : "memory");
}
__device__ __forceinline__ void mma_bf16(float c[4], unsigned a0, unsigned a1,
                                         unsigned a2, unsigned a3,
                                         unsigned b0, unsigned b1) {
    asm volatile("mma.sync.aligned.m16n8k16.row.col.f32.bf16.bf16.f32 "
                 "{%0,%1,%2,%3}, {%4,%5,%6,%7}, {%8,%9}, {%0,%1,%2,%3};"
                 : "+f"(c[0]), "+f"(c[1]), "+f"(c[2]), "+f"(c[3])
                 : "r"(a0), "r"(a1), "r"(a2), "r"(a3), "r"(b0), "r"(b1));
}
__device__ __forceinline__ unsigned pack_hi2(float lo, float hi) {
    __nv_bfloat162 b = __floats2bfloat162_rn(lo, hi);
    return *(unsigned*)&b;
}
__device__ __forceinline__ unsigned pack_lo2(float lo, float hi, unsigned hw) {
    __nv_bfloat162 b = *(__nv_bfloat162*)&hw;
    __nv_bfloat162 r = __floats2bfloat162_rn(lo - __bfloat162float(b.x),
                                             hi - __bfloat162float(b.y));
    return *(unsigned*)&r;
}

#define LDP 36   // smem plane row stride in u32 (32 data + 4 pad)

// ---------------- edge counts (static across layers) -------------------------
__global__ void cnt_kernel(const int* __restrict__ ei) {
    int e = blockIdx.x*blockDim.x + threadIdx.x;
    if (e >= NREL*NEDGE) return;
    int r = e / NEDGE, w = e - r*NEDGE;
    int dst = ei[(size_t)r*2*NEDGE + NEDGE + w];
    atomicAdd(&g_cnt[r*NPER + dst], 1.0f);
}
__global__ void icnt_kernel() {
    int i = blockIdx.x*blockDim.x + threadIdx.x;
    if (i < NREL*NPER) g_icnt[i] = 0.2f / fmaxf(g_cnt[i], 1.0f);
}

// ---------------- prep: u0 = Wlin @ wa0, cd = blin . wa0 (cross relations) ---
__global__ void prep_u_kernel(const float* __restrict__ Wlin_l,
                              const float* __restrict__ blin_l,
                              const float* __restrict__ Wa_l) {
    int k = threadIdx.x; // 64
    for (int j = 0; j < 6; j++) {
        int r = 9 + j;
        const float* W = Wlin_l + r*4096 + k*64;
        const float* wa0 = Wa_l + r*128;
        float s = 0.f;
        #pragma unroll 8
        for (int c = 0; c < 64; c++) s += W[c] * wa0[c];
        g_u0[j*64 + k] = s;
    }
    if (k < 6) {
        int r = 9 + k;
        float s = 0.f;
        for (int c = 0; c < 64; c++) s += blin_l[r*64 + c] * Wa_l[r*128 + c];
        g_cd[k] = s;
    }
}

// ---------------- W split kernels (transpose + bf16 hi/lo planes) ------------
__global__ void wsplit_lin_kernel(const float* __restrict__ Wlin_l) {
    int r = blockIdx.x;
    const float* W = Wlin_l + r*4096;
    for (int i = threadIdx.x; i < 4096; i += 256) {
        int k = i >> 6, n = i & 63;
        float v = W[i];
        __nv_bfloat16 b0 = __float2bfloat16(v);
        ((__nv_bfloat16*)g_wl0)[(r*64 + n)*64 + k] = b0;
        ((__nv_bfloat16*)g_wl1)[(r*64 + n)*64 + k] = __float2bfloat16(v - __bfloat162float(b0));
    }
}
__global__ void wsplit_qkv_kernel(const float* __restrict__ Wq,
                                  const float* __restrict__ Wk,
                                  const float* __restrict__ Wv,
                                  const float* __restrict__ Wskip) {
    int chunk = blockIdx.x;
    const float* Wsrc; int ldW, coff;
    if (chunk < 2)      { Wsrc = Wq;    ldW = 128; coff = chunk*64; }
    else if (chunk < 4) { Wsrc = Wk;    ldW = 128; coff = (chunk-2)*64; }
    else if (chunk < 6) { Wsrc = Wv;    ldW = 128; coff = (chunk-4)*64; }
    else                { Wsrc = Wskip; ldW = 64;  coff = 0; }
    for (int i = threadIdx.x; i < 4096; i += 256) {
        int k = i >> 6, n = i & 63;
        float v = Wsrc[k*ldW + coff + n];
        __nv_bfloat16 b0 = __float2bfloat16(v);
        ((__nv_bfloat16*)g_wq0)[(chunk*64 + n)*64 + k] = b0;
        ((__nv_bfloat16*)g_wq1)[(chunk*64 + n)*64 + k] = __float2bfloat16(v - __bfloat162float(b0));
    }
}

// ---------------- x split (layer-1 input) ------------------------------------
__global__ void xsplit_kernel(const float* __restrict__ x) {
    int idx = blockIdx.x*blockDim.x + threadIdx.x;
    if (idx >= 3*NPER*16) return;
    int lane = idx & 15, tn = idx >> 4;
    float4 v = ((const float4*)x)[idx];
    unsigned h0 = pack_hi2(v.x, v.y), h1 = pack_hi2(v.z, v.w);
    g_xb0[tn*32 + lane*2]     = h0;
    g_xb0[tn*32 + lane*2 + 1] = h1;
    g_xb1[tn*32 + lane*2]     = pack_lo2(v.x, v.y, h0);
    g_xb1[tn*32 + lane*2 + 1] = pack_lo2(v.z, v.w, h1);
}

// ---------------- hs = x[tsrc] @ Wlin + blin  (bf16x2-split MMA) -------------
__global__ void lin_mma_kernel(const float* __restrict__ blin_l,
                               const float* __restrict__ Wa_l,
                               const float* __restrict__ ba_l) {
    __shared__ unsigned xp0[64][LDP], xp1[64][LDP];
    __shared__ unsigned wp0[64][LDP], wp1[64][LDP];
    __shared__ float bsh[64], wa0s[64], wa1s[64];
    __shared__ float red_s[64][2], red_d[64][2];
    int r = blockIdx.y;
    int tid = threadIdx.x;
    // copy pre-split planes into smem (pure uint4 copies, no cvt)
    const uint4* wl0 = (const uint4*)(g_wl0 + r*2048);
    const uint4* wl1 = (const uint4*)(g_wl1 + r*2048);
    for (int i = tid; i < 512; i += 256) {
        int rr = i >> 3, c4 = (i & 7)*4;
        uint4 a = wl0[i], b = wl1[i];
        wp0[rr][c4]=a.x; wp0[rr][c4+1]=a.y; wp0[rr][c4+2]=a.z; wp0[rr][c4+3]=a.w;
        wp1[rr][c4]=b.x; wp1[rr][c4+1]=b.y; wp1[rr][c4+2]=b.z; wp1[rr][c4+3]=b.w;
    }
    if (tid < 64) {
        bsh[tid]  = blin_l[r*64 + tid];
        wa0s[tid] = Wa_l[r*128 + tid];
        wa1s[tid] = Wa_l[r*128 + 64 + tid];
    }
    int t = c_tsrc[r];
    int row0 = blockIdx.x*64;
    for (int i = tid; i < 512; i += 256) {
        int rr = i >> 3, c4 = (i & 7)*4;
        int row = row0 + rr; if (row > NPER-1) row = NPER-1;  // clamp (unused rows)
        size_t base = ((size_t)t*NPER + row)*8 + (i & 7);
        uint4 a = ((const uint4*)g_xb0)[base];
        uint4 b = ((const uint4*)g_xb1)[base];
        xp0[rr][c4]=a.x; xp0[rr][c4+1]=a.y; xp0[rr][c4+2]=a.z; xp0[rr][c4+3]=a.w;
        xp1[rr][c4]=b.x; xp1[rr][c4+1]=b.y; xp1[rr][c4+2]=b.z; xp1[rr][c4+3]=b.w;
    }
    __syncthreads();

    int warp = tid >> 5, lane = tid & 31;
    int wr = warp >> 1, wc = warp & 1;
    int gid = lane >> 2, tig = lane & 3;
    int rA = wr*16 + gid;
    float acc[4][4];
    #pragma unroll
    for (int nt = 0; nt < 4; nt++)
        #pragma unroll
        for (int j = 0; j < 4; j++) acc[nt][j] = 0.f;

    #pragma unroll
    for (int kk = 0; kk < 4; kk++) {
        int ku = kk*8;
        unsigned a0h = xp0[rA][ku+tig],   a1h = xp0[rA+8][ku+tig];
        unsigned a2h = xp0[rA][ku+tig+4], a3h = xp0[rA+8][ku+tig+4];
        unsigned a0l = xp1[rA][ku+tig],   a1l = xp1[rA+8][ku+tig];
        unsigned a2l = xp1[rA][ku+tig+4], a3l = xp1[rA+8][ku+tig+4];
        #pragma unroll
        for (int nt = 0; nt < 4; nt++) {
            int n0 = wc*32 + nt*8 + gid;
            unsigned b0h = wp0[n0][ku+tig], b1h = wp0[n0][ku+tig+4];
            unsigned b0l = wp1[n0][ku+tig], b1l = wp1[n0][ku+tig+4];
            mma_bf16(acc[nt], a0h, a1h, a2h, a3h, b0h, b1h);
            mma_bf16(acc[nt], a0l, a1l, a2l, a3l, b0h, b1h);
            mma_bf16(acc[nt], a0h, a1h, a2h, a3h, b0l, b1l);
        }
    }
    int n = row0 + rA;
    float* base = g_hs + ((size_t)r*NPER + n)*CH;
    float sA = 0.f, sB = 0.f, dA = 0.f, dB = 0.f;
    #pragma unroll
    for (int nt = 0; nt < 4; nt++) {
        int col = wc*32 + nt*8 + 2*tig;
        float c0 = acc[nt][0] + bsh[col], c1 = acc[nt][1] + bsh[col+1];
        float c2 = acc[nt][2] + bsh[col], c3 = acc[nt][3] + bsh[col+1];
        if (n < NPER)     *(float2*)(base + col)        = make_float2(c0, c1);
        if (n + 8 < NPER) *(float2*)(base + 8*CH + col) = make_float2(c2, c3);
        sA += c0*wa1s[col] + c1*wa1s[col+1];
        sB += c2*wa1s[col] + c3*wa1s[col+1];
        dA += c0*wa0s[col] + c1*wa0s[col+1];
        dB += c2*wa0s[col] + c3*wa0s[col+1];
    }
    sA += __shfl_xor_sync(0xffffffffu, sA, 1); sA += __shfl_xor_sync(0xffffffffu, sA, 2);
    sB += __shfl_xor_sync(0xffffffffu, sB, 1); sB += __shfl_xor_sync(0xffffffffu, sB, 2);
    dA += __shfl_xor_sync(0xffffffffu, dA, 1); dA += __shfl_xor_sync(0xffffffffu, dA, 2);
    dB += __shfl_xor_sync(0xffffffffu, dB, 1); dB += __shfl_xor_sync(0xffffffffu, dB, 2);
    if (tig == 0) {
        red_s[rA][wc] = sA;   red_s[rA+8][wc] = sB;
        red_d[rA][wc] = dA;   red_d[rA+8][wc] = dB;
    }
    __syncthreads();
    if (tid < 64 && row0 + tid < NPER) {
        g_as[r*NPER + row0 + tid] = red_s[tid][0] + red_s[tid][1];
        if (r < 9)
            g_ad[r*NPER + row0 + tid] = red_d[tid][0] + red_d[tid][1] + ba_l[r];
    }
}

// ---------------- a_d for the 6 cross-type relations -------------------------
__global__ void ad_cross_kernel(const float* __restrict__ x,
                                const float* __restrict__ ba_l) {
    int j = blockIdx.y;
    int r = 9 + j;
    int warp = threadIdx.x >> 5, lane = threadIdx.x & 31;
    int n = blockIdx.x*8 + warp;
    int t = c_tdst[r];
    const float* xrow = x + ((size_t)t*NPER + n)*CH;
    float p = xrow[lane]*g_u0[j*64 + lane] + xrow[lane+32]*g_u0[j*64 + lane + 32];
    #pragma unroll
    for (int s = 16; s; s >>= 1) p += __shfl_xor_sync(0xffffffffu, p, s);
    if (lane == 0) g_ad[r*NPER + n] = p + g_cd[j] + ba_l[r];
}

// ---------------- per-edge gated message scatter (direct to type accum) ------
__global__ void edge_scatter_kernel(const int* __restrict__ ei) {
    int idx = blockIdx.x*blockDim.x + threadIdx.x;
    int e = idx >> 4, lane = idx & 15;
    if (e >= NREL*NEDGE) return;
    int r = e / NEDGE, w = e - r*NEDGE;
    const int* base = ei + (size_t)r*2*NEDGE;
    int src = base[w], dst = base[NEDGE + w];
    float g = 0.f;
    if (lane == 0)
        g = tanhf(g_ad[r*NPER + dst] + g_as[r*NPER + src]) * g_icnt[r*NPER + dst];
    g = __shfl_sync(0xffffffffu, g, threadIdx.x & 16);
    float4 h = ((const float4*)(g_hs + ((size_t)r*NPER + src)*CH))[lane];
    int t = c_tdst[r];
    red_add_v4(g_acc + ((size_t)t*NPER + dst)*CH + lane*4,
               make_float4(g*h.x, g*h.y, g*h.z, g*h.w));
}

// ---------------- relu + store layer output (+ bf16 planes) ------------------
// mode 0: f32 -> g_xd row tn;            planes -> g_xb  row tn
// mode 1: f32 -> g_hx row c_off[t]+n;    planes -> g_hxb row c_off[t]+n
__global__ void relu_kernel(int mode, float* __restrict__ dst) {
    int idx = blockIdx.x*blockDim.x + threadIdx.x;
    if (idx >= 3*NPER*16) return;
    int lane = idx & 15, tn = idx >> 4;
    int t = tn / NPER, n = tn - t*NPER;
    float4 a = ((const float4*)(g_acc + (size_t)tn*CH))[lane];
    a.x = fmaxf(a.x, 0.f); a.y = fmaxf(a.y, 0.f);
    a.z = fmaxf(a.z, 0.f); a.w = fmaxf(a.w, 0.f);
    int row = mode ? (c_off[t] + n) : tn;
    ((float4*)(dst + (size_t)row*CH))[lane] = a;
    unsigned h0 = pack_hi2(a.x, a.y), h1 = pack_hi2(a.z, a.w);
    unsigned l0 = pack_lo2(a.x, a.y, h0), l1 = pack_lo2(a.z, a.w, h1);
    unsigned *p0 = mode ? g_hxb0 : g_xb0;
    unsigned *p1 = mode ? g_hxb1 : g_xb1;
    p0[(size_t)row*32 + lane*2]     = h0;
    p0[(size_t)row*32 + lane*2 + 1] = h1;
    p1[(size_t)row*32 + lane*2]     = l0;
    p1[(size_t)row*32 + lane*2 + 1] = l1;
}

// ---------------- q/k/v/skip GEMM via bf16x2-split MMA (7 chunks) ------------
__global__ void qkv_mma_kernel(const float* __restrict__ bq, const float* __restrict__ bk,
                               const float* __restrict__ bv, const float* __restrict__ bskip) {
    __shared__ unsigned xp0[64][LDP], xp1[64][LDP];
    __shared__ unsigned wp0[64][LDP], wp1[64][LDP];
    __shared__ float bsh[64];
    int chunk = blockIdx.y;
    const float* bsrc;
    float* dst;
    int coff, ldD;
    if (chunk < 2)      { bsrc = bq;    dst = g_q;    coff = chunk*64;     ldD = 128; }
    else if (chunk < 4) { bsrc = bk;    dst = g_k;    coff = (chunk-2)*64; ldD = 128; }
    else if (chunk < 6) { bsrc = bv;    dst = g_v;    coff = (chunk-4)*64; ldD = 128; }
    else                { bsrc = bskip; dst = g_outb; coff = 0;            ldD = 64;  }
    int tid = threadIdx.x;
    const uint4* wq0 = (const uint4*)(g_wq0 + chunk*2048);
    const uint4* wq1 = (const uint4*)(g_wq1 + chunk*2048);
    for (int i = tid; i < 512; i += 256) {
        int rr = i >> 3, c4 = (i & 7)*4;
        uint4 a = wq0[i], b = wq1[i];
        wp0[rr][c4]=a.x; wp0[rr][c4+1]=a.y; wp0[rr][c4+2]=a.z; wp0[rr][c4+3]=a.w;
        wp1[rr][c4]=b.x; wp1[rr][c4+1]=b.y; wp1[rr][c4+2]=b.z; wp1[rr][c4+3]=b.w;
    }
    if (tid < 64) bsh[tid] = bsrc[coff + tid];
    int m0 = blockIdx.x*64;
    for (int i = tid; i < 512; i += 256) {
        int rr = i >> 3, c4 = (i & 7)*4;
        int row = m0 + rr; if (row > NH-1) row = NH-1;
        size_t base = (size_t)row*8 + (i & 7);
        uint4 a = ((const uint4*)g_hxb0)[base];
        uint4 b = ((const uint4*)g_hxb1)[base];
        xp0[rr][c4]=a.x; xp0[rr][c4+1]=a.y; xp0[rr][c4+2]=a.z; xp0[rr][c4+3]=a.w;
        xp1[rr][c4]=b.x; xp1[rr][c4+1]=b.y; xp1[rr][c4+2]=b.z; xp1[rr][c4+3]=b.w;
    }
    __syncthreads();

    int warp = tid >> 5, lane = tid & 31;
    int wr = warp >> 1, wc = warp & 1;
    int gid = lane >> 2, tig = lane & 3;
    int rA = wr*16 + gid;
    float acc[4][4];
    #pragma unroll
    for (int nt = 0; nt < 4; nt++)
        #pragma unroll
        for (int j = 0; j < 4; j++) acc[nt][j] = 0.f;

    #pragma unroll
    for (int kk = 0; kk < 4; kk++) {
        int ku = kk*8;
        unsigned a0h = xp0[rA][ku+tig],   a1h = xp0[rA+8][ku+tig];
        unsigned a2h = xp0[rA][ku+tig+4], a3h = xp0[rA+8][ku+tig+4];
        unsigned a0l = xp1[rA][ku+tig],   a1l = xp1[rA+8][ku+tig];
        unsigned a2l = xp1[rA][ku+tig+4], a3l = xp1[rA+8][ku+tig+4];
        #pragma unroll
        for (int nt = 0; nt < 4; nt++) {
            int n0 = wc*32 + nt*8 + gid;
            unsigned b0h = wp0[n0][ku+tig], b1h = wp0[n0][ku+tig+4];
            unsigned b0l = wp1[n0][ku+tig], b1l = wp1[n0][ku+tig+4];
            mma_bf16(acc[nt], a0h, a1h, a2h, a3h, b0h, b1h);
            mma_bf16(acc[nt], a0l, a1l, a2l, a3l, b0h, b1h);
            mma_bf16(acc[nt], a0h, a1h, a2h, a3h, b0l, b1l);
        }
    }
    int m = m0 + rA;
    #pragma unroll
    for (int nt = 0; nt < 4; nt++) {
        int col = wc*32 + nt*8 + 2*tig;
        if (m < NH)
            *(float2*)(dst + (size_t)m*ldD + coff + col)
                = make_float2(acc[nt][0]+bsh[col], acc[nt][1]+bsh[col+1]);
        if (m + 8 < NH)
            *(float2*)(dst + (size_t)(m+8)*ldD + coff + col)
                = make_float2(acc[nt][2]+bsh[col], acc[nt][3]+bsh[col+1]);
    }
}

// ---------------- attention scores + segment max -----------------------------
__global__ void score_kernel(const int* __restrict__ ei) {
    int gw = (blockIdx.x*blockDim.x + threadIdx.x) >> 5;
    int lane = threadIdx.x & 31;
    if (gw >= NREL*NEDGE) return;
    int r = gw / NEDGE, w = gw - r*NEDGE;
    const int* base = ei + (size_t)r*2*NEDGE;
    int hsrc = base[w] + c_off[c_tsrc[r]];
    int hdst = base[NEDGE + w] + c_off[c_tdst[r]];
    int h = lane >> 4, l4 = lane & 15;
    float4 a = ((const float4*)(g_q + (size_t)hdst*128 + h*64))[l4];
    float4 b = ((const float4*)(g_k + (size_t)hsrc*128 + h*64))[l4];
    float p = a.x*b.x + a.y*b.y + a.z*b.z + a.w*b.w;
    p += __shfl_xor_sync(0xffffffffu, p, 8);
    p += __shfl_xor_sync(0xffffffffu, p, 4);
    p += __shfl_xor_sync(0xffffffffu, p, 2);
    p += __shfl_xor_sync(0xffffffffu, p, 1);
    if (l4 == 0) {
        float s = p * 0.125f;
        g_score[(size_t)gw*2 + h] = s;
        unsigned u = __float_as_uint(s);
        unsigned key = (u & 0x80000000u) ? ~u : (u | 0x80000000u);
        atomicMax(&g_smax[hdst*2 + h], key);
    }
}

// ---------------- attention exp + weighted-v scatter -------------------------
__global__ void attn_kernel(const int* __restrict__ ei) {
    int gw = (blockIdx.x*blockDim.x + threadIdx.x) >> 5;
    int lane = threadIdx.x & 31;
    if (gw >= NREL*NEDGE) return;
    int r = gw / NEDGE, w = gw - r*NEDGE;
    const int* base = ei + (size_t)r*2*NEDGE;
    int hsrc = base[w] + c_off[c_tsrc[r]];
    int hdst = base[NEDGE + w] + c_off[c_tdst[r]];
    int h = lane >> 4, l4 = lane & 15;
    float s = g_score[(size_t)gw*2 + h];
    unsigned key = g_smax[hdst*2 + h];
    float m = (key & 0x80000000u) ? __uint_as_float(key ^ 0x80000000u)
                                  : __uint_as_float(~key);
    float a = __expf(s - m);
    float4 v = ((const float4*)(g_v + (size_t)hsrc*128 + h*64))[l4];
    red_add_v4(g_num + (size_t)hdst*128 + h*64 + l4*4,
               make_float4(a*v.x, a*v.y, a*v.z, a*v.w));
    if (l4 == 0) atomicAdd(&g_den[hdst*2 + h], a);
}

// ---------------- finalize rows + channel stats ------------------------------
__global__ void reduce_kernel() {
    int c = threadIdx.x & 63;
    int sub = threadIdx.x >> 6;
    int base = blockIdx.x * 256;
    double s = 0.0, s2 = 0.0;
    for (int i = 0; i < 64; i++) {
        int m = base + sub*64 + i;
        if (m < NH) {
            float d0 = g_den[m*2]     + 1e-16f;
            float d1 = g_den[m*2 + 1] + 1e-16f;
            float val = g_outb[(size_t)m*64 + c]
                      + 0.5f * (g_num[(size_t)m*128 + c] / d0
                              + g_num[(size_t)m*128 + 64 + c] / d1);
            g_outb[(size_t)m*64 + c] = val;
            s += val;
            s2 += (double)val * (double)val;
        }
    }
    __shared__ double ss[256], sq[256];
    ss[threadIdx.x] = s; sq[threadIdx.x] = s2;
    __syncthreads();
    if (threadIdx.x < 64) {
        double ts = ss[threadIdx.x] + ss[threadIdx.x+64] + ss[threadIdx.x+128] + ss[threadIdx.x+192];
        double tq = sq[threadIdx.x] + sq[threadIdx.x+64] + sq[threadIdx.x+128] + sq[threadIdx.x+192];
        atomicAdd(&g_sum[c], ts);
        atomicAdd(&g_sumsq[c], tq);
    }
}

__global__ void stats_kernel() {
    int c = threadIdx.x;
    double mu = g_sum[c] / (double)NH;
    double var = g_sumsq[c] / (double)NH - mu*mu;
    g_mu[c] = (float)mu;
    g_rstd[c] = rsqrtf((float)var + 1e-5f);
}

// ---------------- layernorm + leaky relu + permuted output -------------------
__global__ void final_kernel(const float* __restrict__ gamma,
                             const float* __restrict__ beta,
                             float* __restrict__ out) {
    int idx = blockIdx.x*blockDim.x + threadIdx.x;
    if (idx >= 3*NPER*CH) return;
    int c = idx & 63;
    int rown = idx >> 6;
    int b = rown / NPER, n = rown - b*NPER;
    int srow = (b == 0) ? n : ((b == 1) ? (2*NPER + n) : (NPER + n));
    float v = g_outb[(size_t)srow*CH + c];
    v = gamma[c] * (v - g_mu[c]) * g_rstd[c] + beta[c];
    out[idx] = (v >= 0.f) ? v : 0.01f * v;
}

// ---------------- host orchestration -----------------------------------------
extern "C" void kernel_launch(void* const* d_in, const int* in_sizes, int n_in,
                              void* d_out, int out_size) {
    const float* x     = (const float*)d_in[0];
    const int*   ei    = (const int*)  d_in[1];
    const float* Wlin  = (const float*)d_in[2];
    const float* blin  = (const float*)d_in[3];
    const float* Wa    = (const float*)d_in[4];
    const float* ba    = (const float*)d_in[5];
    const float* Wq    = (const float*)d_in[6];
    const float* bq    = (const float*)d_in[7];
    const float* Wk    = (const float*)d_in[8];
    const float* bk    = (const float*)d_in[9];
    const float* Wv    = (const float*)d_in[10];
    const float* bv    = (const float*)d_in[11];
    const float* Wskip = (const float*)d_in[12];
    const float* bskip = (const float*)d_in[13];
    const float* gamma = (const float*)d_in[14];
    const float* beta  = (const float*)d_in[15];
    float* out = (float*)d_out;

    void *p_cnt, *p_acc, *p_num, *p_den, *p_smax, *p_sum, *p_sumsq, *p_xd, *p_hx;
    cudaGetSymbolAddress(&p_cnt, g_cnt);
    cudaGetSymbolAddress(&p_acc, g_acc);
    cudaGetSymbolAddress(&p_num, g_num);
    cudaGetSymbolAddress(&p_den, g_den);
    cudaGetSymbolAddress(&p_smax, g_smax);
    cudaGetSymbolAddress(&p_sum, g_sum);
    cudaGetSymbolAddress(&p_sumsq, g_sumsq);
    cudaGetSymbolAddress(&p_xd, g_xd);
    cudaGetSymbolAddress(&p_hx, g_hx);

    cudaMemsetAsync(p_cnt, 0, sizeof(float)*NREL*NPER);
    cnt_kernel<<<(NREL*NEDGE + 255)/256, 256>>>(ei);
    icnt_kernel<<<(NREL*NPER + 255)/256, 256>>>();
    wsplit_qkv_kernel<<<7, 256>>>(Wq, Wk, Wv, Wskip);
    xsplit_kernel<<<(3*NPER*16 + 255)/256, 256>>>(x);

    for (int l = 0; l < 2; l++) {
        const float* xin = (l == 0) ? x : (const float*)p_xd;
        const float* Wlin_l = Wlin + (size_t)l*NREL*4096;
        const float* blin_l = blin + (size_t)l*NREL*64;
        const float* Wa_l   = Wa   + (size_t)l*NREL*128;
        const float* ba_l   = ba   + (size_t)l*NREL;
        prep_u_kernel<<<1, 64>>>(Wlin_l, blin_l, Wa_l);
        wsplit_lin_kernel<<<15, 256>>>(Wlin_l);
        lin_mma_kernel<<<dim3(313, 15), 256>>>(blin_l, Wa_l, ba_l);
        ad_cross_kernel<<<dim3(2500, 6), 256>>>(xin, ba_l);
        cudaMemsetAsync(p_acc, 0, sizeof(float)*3*NPER*CH);
        edge_scatter_kernel<<<28125, 256>>>(ei);
        relu_kernel<<<(3*NPER*16 + 255)/256, 256>>>(l, l == 0 ? (float*)p_xd : (float*)p_hx);
    }
    cudaMemsetAsync(p_num, 0, sizeof(float)*(size_t)NH*128);
    cudaMemsetAsync(p_den, 0, sizeof(float)*NH*2);
    cudaMemsetAsync(p_smax, 0, sizeof(unsigned)*NH*2);
    cudaMemsetAsync(p_sum, 0, sizeof(double)*CH);
    cudaMemsetAsync(p_sumsq, 0, sizeof(double)*CH);

    qkv_mma_kernel<<<dim3(938, 7), 256>>>(bq, bk, bv, bskip);
    score_kernel<<<56250, 256>>>(ei);
    attn_kernel<<<56250, 256>>>(ei);
    reduce_kernel<<<235, 256>>>();
    stats_kernel<<<1, 64>>>();
    final_kernel<<<15000, 256>>>(gamma, beta, out);
}

// round 11
// speedup vs baseline: 1.2475x; 1.0281x over previous
#include <cuda_runtime.h>
#include <cuda_bf16.h>
#include <math.h>

#define NPER 20000
#define CH 64
#define NREL 15
#define NEDGE 30000
#define NH 60000

__constant__ int c_tsrc[NREL] = {0,1,2,0,1,2,0,1,2,0,0,1,1,2,2};
__constant__ int c_tdst[NREL] = {0,1,2,0,1,2,0,1,2,1,2,0,2,0,1};
__constant__ int c_off[3] = {0, 2*NPER, NPER};

// ---------------- scratch (device globals; no allocs allowed) ----------------
__device__ float    g_hs[(size_t)NREL*NPER*CH];
__device__ float    g_as[NREL*NPER];
__device__ float    g_ad[NREL*NPER];
__device__ float    g_cnt[NREL*NPER];
__device__ float    g_icnt[NREL*NPER];
__device__ float    g_acc[3*NPER*CH];
__device__ float    g_xd[3*NPER*CH];
__device__ float    g_hx[3*NPER*CH];
__device__ float    g_u0[6*CH];
__device__ float    g_cd[6];
__device__ float    g_q[(size_t)NH*128];
__device__ float    g_k[(size_t)NH*128];
__device__ float    g_v[(size_t)NH*128];
__device__ float    g_outb[(size_t)NH*CH];
__device__ float    g_score[(size_t)NREL*NEDGE*2];
__device__ unsigned g_smax[NH*2];
__device__ float    g_den[NH*2];
__device__ float    g_num[(size_t)NH*128];
__device__ double   g_sum[CH];
__device__ double   g_sumsq[CH];
__device__ float    g_mu[CH];
__device__ float    g_rstd[CH];
// bf16 plane buffers (hi/lo splits)
__device__ unsigned g_wl0[NREL*64*32], g_wl1[NREL*64*32];
__device__ unsigned g_wq0[7*64*32],    g_wq1[7*64*32];
__device__ unsigned g_xb0[3*NPER*32],  g_xb1[3*NPER*32];
__device__ unsigned g_hxb0[NH*32],     g_hxb1[NH*32];

__device__ __forceinline__ void red_add_v4(float* p, float4 v) {
    asm volatile("red.global.add.v4.f32 [%0], {%1,%2,%3,%4};"
                 :: "l"(p), "f"(v.x), "f"(v.y), "f"(v.z), "f"(v.w) : "memory");
}
__device__ __forceinline__ void mma_bf16(float c[4], unsigned a0, unsigned a1,
                                         unsigned a2, unsigned a3,
                                         unsigned b0, unsigned b1) {
    asm volatile("mma.sync.aligned.m16n8k16.row.col.f32.bf16.bf16.f32 "
                 "{%0,%1,%2,%3}, {%4,%5,%6,%7}, {%8,%9}, {%0,%1,%2,%3};"
                 : "+f"(c[0]), "+f"(c[1]), "+f"(c[2]), "+f"(c[3])
                 : "r"(a0), "r"(a1), "r"(a2), "r"(a3), "r"(b0), "r"(b1));
}
__device__ __forceinline__ unsigned pack_hi2(float lo, float hi) {
    __nv_bfloat162 b = __floats2bfloat162_rn(lo, hi);
    return *(unsigned*)&b;
}
__device__ __forceinline__ unsigned pack_lo2(float lo, float hi, unsigned hw) {
    __nv_bfloat162 b = *(__nv_bfloat162*)&hw;
    __nv_bfloat162 r = __floats2bfloat162_rn(lo - __bfloat162float(b.x),
                                             hi - __bfloat162float(b.y));
    return *(unsigned*)&r;
}

#define LDP 36

// ---------------- edge counts ------------------------------------------------
__global__ void cnt_kernel(const int* __restrict__ ei) {
    int e = blockIdx.x*blockDim.x + threadIdx.x;
    if (e >= NREL*NEDGE) return;
    int r = e / NEDGE, w = e - r*NEDGE;
    int dst = ei[(size_t)r*2*NEDGE + NEDGE + w];
    atomicAdd(&g_cnt[r*NPER + dst], 1.0f);
}
__global__ void icnt_kernel() {
    int i = blockIdx.x*blockDim.x + threadIdx.x;
    if (i < NREL*NPER) g_icnt[i] = 0.2f / fmaxf(g_cnt[i], 1.0f);
}

// ---------------- prep: u0 = Wlin @ wa0, cd = blin . wa0 ---------------------
__global__ void prep_u_kernel(const float* __restrict__ Wlin_l,
                              const float* __restrict__ blin_l,
                              const float* __restrict__ Wa_l) {
    int k = threadIdx.x;
    for (int j = 0; j < 6; j++) {
        int r = 9 + j;
        const float* W = Wlin_l + r*4096 + k*64;
        const float* wa0 = Wa_l + r*128;
        float s = 0.f;
        #pragma unroll 8
        for (int c = 0; c < 64; c++) s += W[c] * wa0[c];
        g_u0[j*64 + k] = s;
    }
    if (k < 6) {
        int r = 9 + k;
        float s = 0.f;
        for (int c = 0; c < 64; c++) s += blin_l[r*64 + c] * Wa_l[r*128 + c];
        g_cd[k] = s;
    }
}

// ---------------- W split kernels --------------------------------------------
__global__ void wsplit_lin_kernel(const float* __restrict__ Wlin_l) {
    int r = blockIdx.x;
    const float* W = Wlin_l + r*4096;
    for (int i = threadIdx.x; i < 4096; i += 256) {
        int k = i >> 6, n = i & 63;
        float v = W[i];
        __nv_bfloat16 b0 = __float2bfloat16(v);
        ((__nv_bfloat16*)g_wl0)[(r*64 + n)*64 + k] = b0;
        ((__nv_bfloat16*)g_wl1)[(r*64 + n)*64 + k] = __float2bfloat16(v - __bfloat162float(b0));
    }
}
__global__ void wsplit_qkv_kernel(const float* __restrict__ Wq,
                                  const float* __restrict__ Wk,
                                  const float* __restrict__ Wv,
                                  const float* __restrict__ Wskip) {
    int chunk = blockIdx.x;
    const float* Wsrc; int ldW, coff;
    if (chunk < 2)      { Wsrc = Wq;    ldW = 128; coff = chunk*64; }
    else if (chunk < 4) { Wsrc = Wk;    ldW = 128; coff = (chunk-2)*64; }
    else if (chunk < 6) { Wsrc = Wv;    ldW = 128; coff = (chunk-4)*64; }
    else                { Wsrc = Wskip; ldW = 64;  coff = 0; }
    for (int i = threadIdx.x; i < 4096; i += 256) {
        int k = i >> 6, n = i & 63;
        float v = Wsrc[k*ldW + coff + n];
        __nv_bfloat16 b0 = __float2bfloat16(v);
        ((__nv_bfloat16*)g_wq0)[(chunk*64 + n)*64 + k] = b0;
        ((__nv_bfloat16*)g_wq1)[(chunk*64 + n)*64 + k] = __float2bfloat16(v - __bfloat162float(b0));
    }
}

// ---------------- x split (layer-1 input) ------------------------------------
__global__ void xsplit_kernel(const float* __restrict__ x) {
    int idx = blockIdx.x*blockDim.x + threadIdx.x;
    if (idx >= 3*NPER*16) return;
    int lane = idx & 15, tn = idx >> 4;
    float4 v = ((const float4*)x)[idx];
    unsigned h0 = pack_hi2(v.x, v.y), h1 = pack_hi2(v.z, v.w);
    g_xb0[tn*32 + lane*2]     = h0;
    g_xb0[tn*32 + lane*2 + 1] = h1;
    g_xb1[tn*32 + lane*2]     = pack_lo2(v.x, v.y, h0);
    g_xb1[tn*32 + lane*2 + 1] = pack_lo2(v.z, v.w, h1);
}

// ---------------- hs = x[tsrc] @ Wlin + blin  (128-row tile) -----------------
// 8 warps; warp w owns rows [w*16, w*16+16) x all 64 cols. Warp-local epilogue.
__global__ void lin_mma_kernel(const float* __restrict__ blin_l,
                               const float* __restrict__ Wa_l,
                               const float* __restrict__ ba_l) {
    __shared__ unsigned xp0[128][LDP], xp1[128][LDP];
    __shared__ unsigned wp0[64][LDP],  wp1[64][LDP];
    __shared__ float bsh[64], wa0s[64], wa1s[64];
    int r = blockIdx.y;
    int tid = threadIdx.x;
    const uint4* wl0 = (const uint4*)(g_wl0 + r*2048);
    const uint4* wl1 = (const uint4*)(g_wl1 + r*2048);
    for (int i = tid; i < 512; i += 256) {
        int rr = i >> 3, c4 = (i & 7)*4;
        uint4 a = wl0[i], b = wl1[i];
        wp0[rr][c4]=a.x; wp0[rr][c4+1]=a.y; wp0[rr][c4+2]=a.z; wp0[rr][c4+3]=a.w;
        wp1[rr][c4]=b.x; wp1[rr][c4+1]=b.y; wp1[rr][c4+2]=b.z; wp1[rr][c4+3]=b.w;
    }
    if (tid < 64) {
        bsh[tid]  = blin_l[r*64 + tid];
        wa0s[tid] = Wa_l[r*128 + tid];
        wa1s[tid] = Wa_l[r*128 + 64 + tid];
    }
    int t = c_tsrc[r];
    int row0 = blockIdx.x*128;
    for (int i = tid; i < 1024; i += 256) {
        int rr = i >> 3, c4 = (i & 7)*4;
        int row = row0 + rr; if (row > NPER-1) row = NPER-1;
        size_t base = ((size_t)t*NPER + row)*8 + (i & 7);
        uint4 a = ((const uint4*)g_xb0)[base];
        uint4 b = ((const uint4*)g_xb1)[base];
        xp0[rr][c4]=a.x; xp0[rr][c4+1]=a.y; xp0[rr][c4+2]=a.z; xp0[rr][c4+3]=a.w;
        xp1[rr][c4]=b.x; xp1[rr][c4+1]=b.y; xp1[rr][c4+2]=b.z; xp1[rr][c4+3]=b.w;
    }
    __syncthreads();

    int warp = tid >> 5, lane = tid & 31;
    int gid = lane >> 2, tig = lane & 3;
    int rA = warp*16 + gid;
    float acc[8][4];
    #pragma unroll
    for (int nt = 0; nt < 8; nt++)
        #pragma unroll
        for (int j = 0; j < 4; j++) acc[nt][j] = 0.f;

    #pragma unroll
    for (int kk = 0; kk < 4; kk++) {
        int ku = kk*8;
        unsigned a0h = xp0[rA][ku+tig],   a1h = xp0[rA+8][ku+tig];
        unsigned a2h = xp0[rA][ku+tig+4], a3h = xp0[rA+8][ku+tig+4];
        unsigned a0l = xp1[rA][ku+tig],   a1l = xp1[rA+8][ku+tig];
        unsigned a2l = xp1[rA][ku+tig+4], a3l = xp1[rA+8][ku+tig+4];
        #pragma unroll
        for (int nt = 0; nt < 8; nt++) {
            int n0 = nt*8 + gid;
            unsigned b0h = wp0[n0][ku+tig], b1h = wp0[n0][ku+tig+4];
            unsigned b0l = wp1[n0][ku+tig], b1l = wp1[n0][ku+tig+4];
            mma_bf16(acc[nt], a0h, a1h, a2h, a3h, b0h, b1h);
            mma_bf16(acc[nt], a0l, a1l, a2l, a3l, b0h, b1h);
            mma_bf16(acc[nt], a0h, a1h, a2h, a3h, b0l, b1l);
        }
    }
    // bias + store + warp-local a_s/a_d
    int n = row0 + rA;
    float* base = g_hs + ((size_t)r*NPER + n)*CH;
    float sA = 0.f, sB = 0.f, dA = 0.f, dB = 0.f;
    #pragma unroll
    for (int nt = 0; nt < 8; nt++) {
        int col = nt*8 + 2*tig;
        float c0 = acc[nt][0] + bsh[col], c1 = acc[nt][1] + bsh[col+1];
        float c2 = acc[nt][2] + bsh[col], c3 = acc[nt][3] + bsh[col+1];
        if (n < NPER)     *(float2*)(base + col)        = make_float2(c0, c1);
        if (n + 8 < NPER) *(float2*)(base + 8*CH + col) = make_float2(c2, c3);
        sA += c0*wa1s[col] + c1*wa1s[col+1];
        sB += c2*wa1s[col] + c3*wa1s[col+1];
        dA += c0*wa0s[col] + c1*wa0s[col+1];
        dB += c2*wa0s[col] + c3*wa0s[col+1];
    }
    sA += __shfl_xor_sync(0xffffffffu, sA, 1); sA += __shfl_xor_sync(0xffffffffu, sA, 2);
    sB += __shfl_xor_sync(0xffffffffu, sB, 1); sB += __shfl_xor_sync(0xffffffffu, sB, 2);
    dA += __shfl_xor_sync(0xffffffffu, dA, 1); dA += __shfl_xor_sync(0xffffffffu, dA, 2);
    dB += __shfl_xor_sync(0xffffffffu, dB, 1); dB += __shfl_xor_sync(0xffffffffu, dB, 2);
    if (tig == 0) {
        float ba = ba_l[r];
        if (n < NPER) {
            g_as[r*NPER + n] = sA;
            if (r < 9) g_ad[r*NPER + n] = dA + ba;
        }
        if (n + 8 < NPER) {
            g_as[r*NPER + n + 8] = sB;
            if (r < 9) g_ad[r*NPER + n + 8] = dB + ba;
        }
    }
}

// ---------------- a_d for the 6 cross-type relations -------------------------
__global__ void ad_cross_kernel(const float* __restrict__ x,
                                const float* __restrict__ ba_l) {
    int j = blockIdx.y;
    int r = 9 + j;
    int warp = threadIdx.x >> 5, lane = threadIdx.x & 31;
    int n = blockIdx.x*8 + warp;
    int t = c_tdst[r];
    const float* xrow = x + ((size_t)t*NPER + n)*CH;
    float p = xrow[lane]*g_u0[j*64 + lane] + xrow[lane+32]*g_u0[j*64 + lane + 32];
    #pragma unroll
    for (int s = 16; s; s >>= 1) p += __shfl_xor_sync(0xffffffffu, p, s);
    if (lane == 0) g_ad[r*NPER + n] = p + g_cd[j] + ba_l[r];
}

// ---------------- per-edge gated message scatter -----------------------------
__global__ void edge_scatter_kernel(const int* __restrict__ ei) {
    int idx = blockIdx.x*blockDim.x + threadIdx.x;
    int e = idx >> 4, lane = idx & 15;
    if (e >= NREL*NEDGE) return;
    int r = e / NEDGE, w = e - r*NEDGE;
    const int* base = ei + (size_t)r*2*NEDGE;
    int src = base[w], dst = base[NEDGE + w];
    float g = 0.f;
    if (lane == 0)
        g = tanhf(g_ad[r*NPER + dst] + g_as[r*NPER + src]) * g_icnt[r*NPER + dst];
    g = __shfl_sync(0xffffffffu, g, threadIdx.x & 16);
    float4 h = ((const float4*)(g_hs + ((size_t)r*NPER + src)*CH))[lane];
    int t = c_tdst[r];
    red_add_v4(g_acc + ((size_t)t*NPER + dst)*CH + lane*4,
               make_float4(g*h.x, g*h.y, g*h.z, g*h.w));
}

// ---------------- relu + store layer output (+ bf16 planes) ------------------
__global__ void relu_kernel(int mode, float* __restrict__ dst) {
    int idx = blockIdx.x*blockDim.x + threadIdx.x;
    if (idx >= 3*NPER*16) return;
    int lane = idx & 15, tn = idx >> 4;
    int t = tn / NPER, n = tn - t*NPER;
    float4 a = ((const float4*)(g_acc + (size_t)tn*CH))[lane];
    a.x = fmaxf(a.x, 0.f); a.y = fmaxf(a.y, 0.f);
    a.z = fmaxf(a.z, 0.f); a.w = fmaxf(a.w, 0.f);
    int row = mode ? (c_off[t] + n) : tn;
    ((float4*)(dst + (size_t)row*CH))[lane] = a;
    unsigned h0 = pack_hi2(a.x, a.y), h1 = pack_hi2(a.z, a.w);
    unsigned l0 = pack_lo2(a.x, a.y, h0), l1 = pack_lo2(a.z, a.w, h1);
    unsigned *p0 = mode ? g_hxb0 : g_xb0;
    unsigned *p1 = mode ? g_hxb1 : g_xb1;
    p0[(size_t)row*32 + lane*2]     = h0;
    p0[(size_t)row*32 + lane*2 + 1] = h1;
    p1[(size_t)row*32 + lane*2]     = l0;
    p1[(size_t)row*32 + lane*2 + 1] = l1;
}

// ---------------- q/k/v/skip GEMM (128-row tile) -----------------------------
__global__ void qkv_mma_kernel(const float* __restrict__ bq, const float* __restrict__ bk,
                               const float* __restrict__ bv, const float* __restrict__ bskip) {
    __shared__ unsigned xp0[128][LDP], xp1[128][LDP];
    __shared__ unsigned wp0[64][LDP],  wp1[64][LDP];
    __shared__ float bsh[64];
    int chunk = blockIdx.y;
    const float* bsrc;
    float* dst;
    int coff, ldD;
    if (chunk < 2)      { bsrc = bq;    dst = g_q;    coff = chunk*64;     ldD = 128; }
    else if (chunk < 4) { bsrc = bk;    dst = g_k;    coff = (chunk-2)*64; ldD = 128; }
    else if (chunk < 6) { bsrc = bv;    dst = g_v;    coff = (chunk-4)*64; ldD = 128; }
    else                { bsrc = bskip; dst = g_outb; coff = 0;            ldD = 64;  }
    int tid = threadIdx.x;
    const uint4* wq0 = (const uint4*)(g_wq0 + chunk*2048);
    const uint4* wq1 = (const uint4*)(g_wq1 + chunk*2048);
    for (int i = tid; i < 512; i += 256) {
        int rr = i >> 3, c4 = (i & 7)*4;
        uint4 a = wq0[i], b = wq1[i];
        wp0[rr][c4]=a.x; wp0[rr][c4+1]=a.y; wp0[rr][c4+2]=a.z; wp0[rr][c4+3]=a.w;
        wp1[rr][c4]=b.x; wp1[rr][c4+1]=b.y; wp1[rr][c4+2]=b.z; wp1[rr][c4+3]=b.w;
    }
    if (tid < 64) bsh[tid] = bsrc[coff + tid];
    int m0 = blockIdx.x*128;
    for (int i = tid; i < 1024; i += 256) {
        int rr = i >> 3, c4 = (i & 7)*4;
        int row = m0 + rr; if (row > NH-1) row = NH-1;
        size_t base = (size_t)row*8 + (i & 7);
        uint4 a = ((const uint4*)g_hxb0)[base];
        uint4 b = ((const uint4*)g_hxb1)[base];
        xp0[rr][c4]=a.x; xp0[rr][c4+1]=a.y; xp0[rr][c4+2]=a.z; xp0[rr][c4+3]=a.w;
        xp1[rr][c4]=b.x; xp1[rr][c4+1]=b.y; xp1[rr][c4+2]=b.z; xp1[rr][c4+3]=b.w;
    }
    __syncthreads();

    int warp = tid >> 5, lane = tid & 31;
    int gid = lane >> 2, tig = lane & 3;
    int rA = warp*16 + gid;
    float acc[8][4];
    #pragma unroll
    for (int nt = 0; nt < 8; nt++)
        #pragma unroll
        for (int j = 0; j < 4; j++) acc[nt][j] = 0.f;

    #pragma unroll
    for (int kk = 0; kk < 4; kk++) {
        int ku = kk*8;
        unsigned a0h = xp0[rA][ku+tig],   a1h = xp0[rA+8][ku+tig];
        unsigned a2h = xp0[rA][ku+tig+4], a3h = xp0[rA+8][ku+tig+4];
        unsigned a0l = xp1[rA][ku+tig],   a1l = xp1[rA+8][ku+tig];
        unsigned a2l = xp1[rA][ku+tig+4], a3l = xp1[rA+8][ku+tig+4];
        #pragma unroll
        for (int nt = 0; nt < 8; nt++) {
            int n0 = nt*8 + gid;
            unsigned b0h = wp0[n0][ku+tig], b1h = wp0[n0][ku+tig+4];
            unsigned b0l = wp1[n0][ku+tig], b1l = wp1[n0][ku+tig+4];
            mma_bf16(acc[nt], a0h, a1h, a2h, a3h, b0h, b1h);
            mma_bf16(acc[nt], a0l, a1l, a2l, a3l, b0h, b1h);
            mma_bf16(acc[nt], a0h, a1h, a2h, a3h, b0l, b1l);
        }
    }
    int m = m0 + rA;
    #pragma unroll
    for (int nt = 0; nt < 8; nt++) {
        int col = nt*8 + 2*tig;
        if (m < NH)
            *(float2*)(dst + (size_t)m*ldD + coff + col)
                = make_float2(acc[nt][0]+bsh[col], acc[nt][1]+bsh[col+1]);
        if (m + 8 < NH)
            *(float2*)(dst + (size_t)(m+8)*ldD + coff + col)
                = make_float2(acc[nt][2]+bsh[col], acc[nt][3]+bsh[col+1]);
    }
}

// ---------------- attention scores + segment max -----------------------------
__global__ void score_kernel(const int* __restrict__ ei) {
    int gw = (blockIdx.x*blockDim.x + threadIdx.x) >> 5;
    int lane = threadIdx.x & 31;
    if (gw >= NREL*NEDGE) return;
    int r = gw / NEDGE, w = gw - r*NEDGE;
    const int* base = ei + (size_t)r*2*NEDGE;
    int hsrc = base[w] + c_off[c_tsrc[r]];
    int hdst = base[NEDGE + w] + c_off[c_tdst[r]];
    int h = lane >> 4, l4 = lane & 15;
    float4 a = ((const float4*)(g_q + (size_t)hdst*128 + h*64))[l4];
    float4 b = ((const float4*)(g_k + (size_t)hsrc*128 + h*64))[l4];
    float p = a.x*b.x + a.y*b.y + a.z*b.z + a.w*b.w;
    p += __shfl_xor_sync(0xffffffffu, p, 8);
    p += __shfl_xor_sync(0xffffffffu, p, 4);
    p += __shfl_xor_sync(0xffffffffu, p, 2);
    p += __shfl_xor_sync(0xffffffffu, p, 1);
    if (l4 == 0) {
        float s = p * 0.125f;
        g_score[(size_t)gw*2 + h] = s;
        unsigned u = __float_as_uint(s);
        unsigned key = (u & 0x80000000u) ? ~u : (u | 0x80000000u);
        atomicMax(&g_smax[hdst*2 + h], key);
    }
}

// ---------------- attention exp + weighted-v scatter -------------------------
__global__ void attn_kernel(const int* __restrict__ ei) {
    int gw = (blockIdx.x*blockDim.x + threadIdx.x) >> 5;
    int lane = threadIdx.x & 31;
    if (gw >= NREL*NEDGE) return;
    int r = gw / NEDGE, w = gw - r*NEDGE;
    const int* base = ei + (size_t)r*2*NEDGE;
    int hsrc = base[w] + c_off[c_tsrc[r]];
    int hdst = base[NEDGE + w] + c_off[c_tdst[r]];
    int h = lane >> 4, l4 = lane & 15;
    float s = g_score[(size_t)gw*2 + h];
    unsigned key = g_smax[hdst*2 + h];
    float m = (key & 0x80000000u) ? __uint_as_float(key ^ 0x80000000u)
                                  : __uint_as_float(~key);
    float a = __expf(s - m);
    float4 v = ((const float4*)(g_v + (size_t)hsrc*128 + h*64))[l4];
    red_add_v4(g_num + (size_t)hdst*128 + h*64 + l4*4,
               make_float4(a*v.x, a*v.y, a*v.z, a*v.w));
    if (l4 == 0) atomicAdd(&g_den[hdst*2 + h], a);
}

// ---------------- finalize rows + channel stats ------------------------------
__global__ void reduce_kernel() {
    int c = threadIdx.x & 63;
    int sub = threadIdx.x >> 6;
    int base = blockIdx.x * 256;
    double s = 0.0, s2 = 0.0;
    for (int i = 0; i < 64; i++) {
        int m = base + sub*64 + i;
        if (m < NH) {
            float d0 = g_den[m*2]     + 1e-16f;
            float d1 = g_den[m*2 + 1] + 1e-16f;
            float val = g_outb[(size_t)m*64 + c]
                      + 0.5f * (g_num[(size_t)m*128 + c] / d0
                              + g_num[(size_t)m*128 + 64 + c] / d1);
            g_outb[(size_t)m*64 + c] = val;
            s += val;
            s2 += (double)val * (double)val;
        }
    }
    __shared__ double ss[256], sq[256];
    ss[threadIdx.x] = s; sq[threadIdx.x] = s2;
    __syncthreads();
    if (threadIdx.x < 64) {
        double ts = ss[threadIdx.x] + ss[threadIdx.x+64] + ss[threadIdx.x+128] + ss[threadIdx.x+192];
        double tq = sq[threadIdx.x] + sq[threadIdx.x+64] + sq[threadIdx.x+128] + sq[threadIdx.x+192];
        atomicAdd(&g_sum[c], ts);
        atomicAdd(&g_sumsq[c], tq);
    }
}

__global__ void stats_kernel() {
    int c = threadIdx.x;
    double mu = g_sum[c] / (double)NH;
    double var = g_sumsq[c] / (double)NH - mu*mu;
    g_mu[c] = (float)mu;
    g_rstd[c] = rsqrtf((float)var + 1e-5f);
}

// ---------------- layernorm + leaky relu + permuted output -------------------
__global__ void final_kernel(const float* __restrict__ gamma,
                             const float* __restrict__ beta,
                             float* __restrict__ out) {
    int idx = blockIdx.x*blockDim.x + threadIdx.x;
    if (idx >= 3*NPER*CH) return;
    int c = idx & 63;
    int rown = idx >> 6;
    int b = rown / NPER, n = rown - b*NPER;
    int srow = (b == 0) ? n : ((b == 1) ? (2*NPER + n) : (NPER + n));
    float v = g_outb[(size_t)srow*CH + c];
    v = gamma[c] * (v - g_mu[c]) * g_rstd[c] + beta[c];
    out[idx] = (v >= 0.f) ? v : 0.01f * v;
}

// ---------------- host orchestration -----------------------------------------
extern "C" void kernel_launch(void* const* d_in, const int* in_sizes, int n_in,
                              void* d_out, int out_size) {
    const float* x     = (const float*)d_in[0];
    const int*   ei    = (const int*)  d_in[1];
    const float* Wlin  = (const float*)d_in[2];
    const float* blin  = (const float*)d_in[3];
    const float* Wa    = (const float*)d_in[4];
    const float* ba    = (const float*)d_in[5];
    const float* Wq    = (const float*)d_in[6];
    const float* bq    = (const float*)d_in[7];
    const float* Wk    = (const float*)d_in[8];
    const float* bk    = (const float*)d_in[9];
    const float* Wv    = (const float*)d_in[10];
    const float* bv    = (const float*)d_in[11];
    const float* Wskip = (const float*)d_in[12];
    const float* bskip = (const float*)d_in[13];
    const float* gamma = (const float*)d_in[14];
    const float* beta  = (const float*)d_in[15];
    float* out = (float*)d_out;

    void *p_cnt, *p_acc, *p_num, *p_den, *p_smax, *p_sum, *p_sumsq, *p_xd, *p_hx;
    cudaGetSymbolAddress(&p_cnt, g_cnt);
    cudaGetSymbolAddress(&p_acc, g_acc);
    cudaGetSymbolAddress(&p_num, g_num);
    cudaGetSymbolAddress(&p_den, g_den);
    cudaGetSymbolAddress(&p_smax, g_smax);
    cudaGetSymbolAddress(&p_sum, g_sum);
    cudaGetSymbolAddress(&p_sumsq, g_sumsq);
    cudaGetSymbolAddress(&p_xd, g_xd);
    cudaGetSymbolAddress(&p_hx, g_hx);

    cudaMemsetAsync(p_cnt, 0, sizeof(float)*NREL*NPER);
    cnt_kernel<<<(NREL*NEDGE + 255)/256, 256>>>(ei);
    icnt_kernel<<<(NREL*NPER + 255)/256, 256>>>();
    wsplit_qkv_kernel<<<7, 256>>>(Wq, Wk, Wv, Wskip);
    xsplit_kernel<<<(3*NPER*16 + 255)/256, 256>>>(x);

    for (int l = 0; l < 2; l++) {
        const float* xin = (l == 0) ? x : (const float*)p_xd;
        const float* Wlin_l = Wlin + (size_t)l*NREL*4096;
        const float* blin_l = blin + (size_t)l*NREL*64;
        const float* Wa_l   = Wa   + (size_t)l*NREL*128;
        const float* ba_l   = ba   + (size_t)l*NREL;
        prep_u_kernel<<<1, 64>>>(Wlin_l, blin_l, Wa_l);
        wsplit_lin_kernel<<<15, 256>>>(Wlin_l);
        lin_mma_kernel<<<dim3(157, 15), 256>>>(blin_l, Wa_l, ba_l);
        ad_cross_kernel<<<dim3(2500, 6), 256>>>(xin, ba_l);
        cudaMemsetAsync(p_acc, 0, sizeof(float)*3*NPER*CH);
        edge_scatter_kernel<<<28125, 256>>>(ei);
        relu_kernel<<<(3*NPER*16 + 255)/256, 256>>>(l, l == 0 ? (float*)p_xd : (float*)p_hx);
    }
    cudaMemsetAsync(p_num, 0, sizeof(float)*(size_t)NH*128);
    cudaMemsetAsync(p_den, 0, sizeof(float)*NH*2);
    cudaMemsetAsync(p_smax, 0, sizeof(unsigned)*NH*2);
    cudaMemsetAsync(p_sum, 0, sizeof(double)*CH);
    cudaMemsetAsync(p_sumsq, 0, sizeof(double)*CH);

    qkv_mma_kernel<<<dim3(469, 7), 256>>>(bq, bk, bv, bskip);
    score_kernel<<<56250, 256>>>(ei);
    attn_kernel<<<56250, 256>>>(ei);
    reduce_kernel<<<235, 256>>>();
    stats_kernel<<<1, 64>>>();
    final_kernel<<<15000, 256>>>(gamma, beta, out);
}

// round 14
// speedup vs baseline: 1.3107x; 1.0507x over previous
#include <cuda_runtime.h>
#include <cuda_bf16.h>
#include <math.h>

#define NPER 20000
#define CH 64
#define NREL 15
#define NEDGE 30000
#define NH 60000

__constant__ int c_tsrc[NREL] = {0,1,2,0,1,2,0,1,2,0,0,1,1,2,2};
__constant__ int c_tdst[NREL] = {0,1,2,0,1,2,0,1,2,1,2,0,2,0,1};
__constant__ int c_off[3] = {0, 2*NPER, NPER};

// ---------------- scratch (device globals; no allocs allowed) ----------------
__device__ float    g_hs[(size_t)NREL*NPER*CH];
__device__ float    g_as[NREL*NPER];
__device__ float    g_ad[NREL*NPER];
__device__ float    g_cnt[NREL*NPER];
__device__ float    g_icnt[NREL*NPER];
__device__ float    g_acc[3*NPER*CH];
__device__ float    g_xd[3*NPER*CH];
__device__ float    g_hx[3*NPER*CH];
__device__ float    g_u0[6*CH];
__device__ float    g_cd[6];
__device__ float    g_q[(size_t)NH*128];
__device__ float    g_k[(size_t)NH*128];
__device__ float    g_v[(size_t)NH*128];
__device__ float    g_outb[(size_t)NH*CH];
__device__ float    g_den[NH*2];
__device__ float    g_num[(size_t)NH*128];
__device__ double   g_sum[CH];
__device__ double   g_sumsq[CH];
__device__ float    g_mu[CH];
__device__ float    g_rstd[CH];
// bf16 plane buffers (hi/lo splits)
__device__ unsigned g_wl0[NREL*64*32], g_wl1[NREL*64*32];
__device__ unsigned g_wq0[7*64*32],    g_wq1[7*64*32];
__device__ unsigned g_xb0[3*NPER*32],  g_xb1[3*NPER*32];
__device__ unsigned g_hxb0[NH*32],     g_hxb1[NH*32];

__device__ __forceinline__ void red_add_v4(float* p, float4 v) {
    asm volatile("red.global.add.v4.f32 [%0], {%1,%2,%3,%4};"
                 :: "l"(p), "f"(v.x), "f"(v.y), "f"(v.z), "f"(v.w) : "memory");
}
__device__ __forceinline__ void mma_bf16(float c[4], unsigned a0, unsigned a1,
                                         unsigned a2, unsigned a3,
                                         unsigned b0, unsigned b1) {
    asm volatile("mma.sync.aligned.m16n8k16.row.col.f32.bf16.bf16.f32 "
                 "{%0,%1,%2,%3}, {%4,%5,%6,%7}, {%8,%9}, {%0,%1,%2,%3};"
                 : "+f"(c[0]), "+f"(c[1]), "+f"(c[2]), "+f"(c[3])
                 : "r"(a0), "r"(a1), "r"(a2), "r"(a3), "r"(b0), "r"(b1));
}
__device__ __forceinline__ unsigned pack_hi2(float lo, float hi) {
    __nv_bfloat162 b = __floats2bfloat162_rn(lo, hi);
    return *(unsigned*)&b;
}
__device__ __forceinline__ unsigned pack_lo2(float lo, float hi, unsigned hw) {
    __nv_bfloat162 b = *(__nv_bfloat162*)&hw;
    __nv_bfloat162 r = __floats2bfloat162_rn(lo - __bfloat162float(b.x),
                                             hi - __bfloat162float(b.y));
    return *(unsigned*)&r;
}

#define LDP 36

// ---------------- edge counts ------------------------------------------------
__global__ void cnt_kernel(const int* __restrict__ ei) {
    int e = blockIdx.x*blockDim.x + threadIdx.x;
    if (e >= NREL*NEDGE) return;
    int r = e / NEDGE, w = e - r*NEDGE;
    int dst = ei[(size_t)r*2*NEDGE + NEDGE + w];
    atomicAdd(&g_cnt[r*NPER + dst], 1.0f);
}
__global__ void icnt_kernel() {
    int i = blockIdx.x*blockDim.x + threadIdx.x;
    if (i < NREL*NPER) g_icnt[i] = 0.2f / fmaxf(g_cnt[i], 1.0f);
}

// ---------------- prep: u0 = Wlin @ wa0, cd = blin . wa0 ---------------------
__global__ void prep_u_kernel(const float* __restrict__ Wlin_l,
                              const float* __restrict__ blin_l,
                              const float* __restrict__ Wa_l) {
    int k = threadIdx.x;
    for (int j = 0; j < 6; j++) {
        int r = 9 + j;
        const float* W = Wlin_l + r*4096 + k*64;
        const float* wa0 = Wa_l + r*128;
        float s = 0.f;
        #pragma unroll 8
        for (int c = 0; c < 64; c++) s += W[c] * wa0[c];
        g_u0[j*64 + k] = s;
    }
    if (k < 6) {
        int r = 9 + k;
        float s = 0.f;
        for (int c = 0; c < 64; c++) s += blin_l[r*64 + c] * Wa_l[r*128 + c];
        g_cd[k] = s;
    }
}

// ---------------- W split kernels --------------------------------------------
__global__ void wsplit_lin_kernel(const float* __restrict__ Wlin_l) {
    int r = blockIdx.x;
    const float* W = Wlin_l + r*4096;
    for (int i = threadIdx.x; i < 4096; i += 256) {
        int k = i >> 6, n = i & 63;
        float v = W[i];
        __nv_bfloat16 b0 = __float2bfloat16(v);
        ((__nv_bfloat16*)g_wl0)[(r*64 + n)*64 + k] = b0;
        ((__nv_bfloat16*)g_wl1)[(r*64 + n)*64 + k] = __float2bfloat16(v - __bfloat162float(b0));
    }
}
__global__ void wsplit_qkv_kernel(const float* __restrict__ Wq,
                                  const float* __restrict__ Wk,
                                  const float* __restrict__ Wv,
                                  const float* __restrict__ Wskip) {
    int chunk = blockIdx.x;
    const float* Wsrc; int ldW, coff;
    if (chunk < 2)      { Wsrc = Wq;    ldW = 128; coff = chunk*64; }
    else if (chunk < 4) { Wsrc = Wk;    ldW = 128; coff = (chunk-2)*64; }
    else if (chunk < 6) { Wsrc = Wv;    ldW = 128; coff = (chunk-4)*64; }
    else                { Wsrc = Wskip; ldW = 64;  coff = 0; }
    for (int i = threadIdx.x; i < 4096; i += 256) {
        int k = i >> 6, n = i & 63;
        float v = Wsrc[k*ldW + coff + n];
        __nv_bfloat16 b0 = __float2bfloat16(v);
        ((__nv_bfloat16*)g_wq0)[(chunk*64 + n)*64 + k] = b0;
        ((__nv_bfloat16*)g_wq1)[(chunk*64 + n)*64 + k] = __float2bfloat16(v - __bfloat162float(b0));
    }
}

// ---------------- x split (layer-1 input) ------------------------------------
__global__ void xsplit_kernel(const float* __restrict__ x) {
    int idx = blockIdx.x*blockDim.x + threadIdx.x;
    if (idx >= 3*NPER*16) return;
    int lane = idx & 15, tn = idx >> 4;
    float4 v = ((const float4*)x)[idx];
    unsigned h0 = pack_hi2(v.x, v.y), h1 = pack_hi2(v.z, v.w);
    g_xb0[tn*32 + lane*2]     = h0;
    g_xb0[tn*32 + lane*2 + 1] = h1;
    g_xb1[tn*32 + lane*2]     = pack_lo2(v.x, v.y, h0);
    g_xb1[tn*32 + lane*2 + 1] = pack_lo2(v.z, v.w, h1);
}

// ---------------- hs = x[tsrc] @ Wlin + blin  (128-row tile) -----------------
__global__ void lin_mma_kernel(const float* __restrict__ blin_l,
                               const float* __restrict__ Wa_l,
                               const float* __restrict__ ba_l) {
    __shared__ unsigned xp0[128][LDP], xp1[128][LDP];
    __shared__ unsigned wp0[64][LDP],  wp1[64][LDP];
    __shared__ float bsh[64], wa0s[64], wa1s[64];
    int r = blockIdx.y;
    int tid = threadIdx.x;
    const uint4* wl0 = (const uint4*)(g_wl0 + r*2048);
    const uint4* wl1 = (const uint4*)(g_wl1 + r*2048);
    for (int i = tid; i < 512; i += 256) {
        int rr = i >> 3, c4 = (i & 7)*4;
        uint4 a = wl0[i], b = wl1[i];
        wp0[rr][c4]=a.x; wp0[rr][c4+1]=a.y; wp0[rr][c4+2]=a.z; wp0[rr][c4+3]=a.w;
        wp1[rr][c4]=b.x; wp1[rr][c4+1]=b.y; wp1[rr][c4+2]=b.z; wp1[rr][c4+3]=b.w;
    }
    if (tid < 64) {
        bsh[tid]  = blin_l[r*64 + tid];
        wa0s[tid] = Wa_l[r*128 + tid];
        wa1s[tid] = Wa_l[r*128 + 64 + tid];
    }
    int t = c_tsrc[r];
    int row0 = blockIdx.x*128;
    for (int i = tid; i < 1024; i += 256) {
        int rr = i >> 3, c4 = (i & 7)*4;
        int row = row0 + rr; if (row > NPER-1) row = NPER-1;
        size_t base = ((size_t)t*NPER + row)*8 + (i & 7);
        uint4 a = ((const uint4*)g_xb0)[base];
        uint4 b = ((const uint4*)g_xb1)[base];
        xp0[rr][c4]=a.x; xp0[rr][c4+1]=a.y; xp0[rr][c4+2]=a.z; xp0[rr][c4+3]=a.w;
        xp1[rr][c4]=b.x; xp1[rr][c4+1]=b.y; xp1[rr][c4+2]=b.z; xp1[rr][c4+3]=b.w;
    }
    __syncthreads();

    int warp = tid >> 5, lane = tid & 31;
    int gid = lane >> 2, tig = lane & 3;
    int rA = warp*16 + gid;
    float acc[8][4];
    #pragma unroll
    for (int nt = 0; nt < 8; nt++)
        #pragma unroll
        for (int j = 0; j < 4; j++) acc[nt][j] = 0.f;

    #pragma unroll
    for (int kk = 0; kk < 4; kk++) {
        int ku = kk*8;
        unsigned a0h = xp0[rA][ku+tig],   a1h = xp0[rA+8][ku+tig];
        unsigned a2h = xp0[rA][ku+tig+4], a3h = xp0[rA+8][ku+tig+4];
        unsigned a0l = xp1[rA][ku+tig],   a1l = xp1[rA+8][ku+tig];
        unsigned a2l = xp1[rA][ku+tig+4], a3l = xp1[rA+8][ku+tig+4];
        #pragma unroll
        for (int nt = 0; nt < 8; nt++) {
            int n0 = nt*8 + gid;
            unsigned b0h = wp0[n0][ku+tig], b1h = wp0[n0][ku+tig+4];
            unsigned b0l = wp1[n0][ku+tig], b1l = wp1[n0][ku+tig+4];
            mma_bf16(acc[nt], a0h, a1h, a2h, a3h, b0h, b1h);
            mma_bf16(acc[nt], a0l, a1l, a2l, a3l, b0h, b1h);
            mma_bf16(acc[nt], a0h, a1h, a2h, a3h, b0l, b1l);
        }
    }
    // bias + store + warp-local a_s/a_d
    int n = row0 + rA;
    float* base = g_hs + ((size_t)r*NPER + n)*CH;
    float sA = 0.f, sB = 0.f, dA = 0.f, dB = 0.f;
    #pragma unroll
    for (int nt = 0; nt < 8; nt++) {
        int col = nt*8 + 2*tig;
        float c0 = acc[nt][0] + bsh[col], c1 = acc[nt][1] + bsh[col+1];
        float c2 = acc[nt][2] + bsh[col], c3 = acc[nt][3] + bsh[col+1];
        if (n < NPER)     *(float2*)(base + col)        = make_float2(c0, c1);
        if (n + 8 < NPER) *(float2*)(base + 8*CH + col) = make_float2(c2, c3);
        sA += c0*wa1s[col] + c1*wa1s[col+1];
        sB += c2*wa1s[col] + c3*wa1s[col+1];
        dA += c0*wa0s[col] + c1*wa0s[col+1];
        dB += c2*wa0s[col] + c3*wa0s[col+1];
    }
    sA += __shfl_xor_sync(0xffffffffu, sA, 1); sA += __shfl_xor_sync(0xffffffffu, sA, 2);
    sB += __shfl_xor_sync(0xffffffffu, sB, 1); sB += __shfl_xor_sync(0xffffffffu, sB, 2);
    dA += __shfl_xor_sync(0xffffffffu, dA, 1); dA += __shfl_xor_sync(0xffffffffu, dA, 2);
    dB += __shfl_xor_sync(0xffffffffu, dB, 1); dB += __shfl_xor_sync(0xffffffffu, dB, 2);
    if (tig == 0) {
        float ba = ba_l[r];
        if (n < NPER) {
            g_as[r*NPER + n] = sA;
            if (r < 9) g_ad[r*NPER + n] = dA + ba;
        }
        if (n + 8 < NPER) {
            g_as[r*NPER + n + 8] = sB;
            if (r < 9) g_ad[r*NPER + n + 8] = dB + ba;
        }
    }
}

// ---------------- a_d for the 6 cross-type relations -------------------------
__global__ void ad_cross_kernel(const float* __restrict__ x,
                                const float* __restrict__ ba_l) {
    int j = blockIdx.y;
    int r = 9 + j;
    int warp = threadIdx.x >> 5, lane = threadIdx.x & 31;
    int n = blockIdx.x*8 + warp;
    int t = c_tdst[r];
    const float* xrow = x + ((size_t)t*NPER + n)*CH;
    float p = xrow[lane]*g_u0[j*64 + lane] + xrow[lane+32]*g_u0[j*64 + lane + 32];
    #pragma unroll
    for (int s = 16; s; s >>= 1) p += __shfl_xor_sync(0xffffffffu, p, s);
    if (lane == 0) g_ad[r*NPER + n] = p + g_cd[j] + ba_l[r];
}

// ---------------- per-edge gated message scatter -----------------------------
__global__ void edge_scatter_kernel(const int* __restrict__ ei) {
    int idx = blockIdx.x*blockDim.x + threadIdx.x;
    int e = idx >> 4, lane = idx & 15;
    if (e >= NREL*NEDGE) return;
    int r = e / NEDGE, w = e - r*NEDGE;
    const int* base = ei + (size_t)r*2*NEDGE;
    int src = base[w], dst = base[NEDGE + w];
    float g = 0.f;
    if (lane == 0)
        g = tanhf(g_ad[r*NPER + dst] + g_as[r*NPER + src]) * g_icnt[r*NPER + dst];
    g = __shfl_sync(0xffffffffu, g, threadIdx.x & 16);
    float4 h = ((const float4*)(g_hs + ((size_t)r*NPER + src)*CH))[lane];
    int t = c_tdst[r];
    red_add_v4(g_acc + ((size_t)t*NPER + dst)*CH + lane*4,
               make_float4(g*h.x, g*h.y, g*h.z, g*h.w));
}

// ---------------- relu + store layer output (+ bf16 planes) ------------------
__global__ void relu_kernel(int mode, float* __restrict__ dst) {
    int idx = blockIdx.x*blockDim.x + threadIdx.x;
    if (idx >= 3*NPER*16) return;
    int lane = idx & 15, tn = idx >> 4;
    int t = tn / NPER, n = tn - t*NPER;
    float4 a = ((const float4*)(g_acc + (size_t)tn*CH))[lane];
    a.x = fmaxf(a.x, 0.f); a.y = fmaxf(a.y, 0.f);
    a.z = fmaxf(a.z, 0.f); a.w = fmaxf(a.w, 0.f);
    int row = mode ? (c_off[t] + n) : tn;
    ((float4*)(dst + (size_t)row*CH))[lane] = a;
    unsigned h0 = pack_hi2(a.x, a.y), h1 = pack_hi2(a.z, a.w);
    unsigned l0 = pack_lo2(a.x, a.y, h0), l1 = pack_lo2(a.z, a.w, h1);
    unsigned *p0 = mode ? g_hxb0 : g_xb0;
    unsigned *p1 = mode ? g_hxb1 : g_xb1;
    p0[(size_t)row*32 + lane*2]     = h0;
    p0[(size_t)row*32 + lane*2 + 1] = h1;
    p1[(size_t)row*32 + lane*2]     = l0;
    p1[(size_t)row*32 + lane*2 + 1] = l1;
}

// ---------------- q/k/v/skip GEMM (128-row tile) -----------------------------
__global__ void qkv_mma_kernel(const float* __restrict__ bq, const float* __restrict__ bk,
                               const float* __restrict__ bv, const float* __restrict__ bskip) {
    __shared__ unsigned xp0[128][LDP], xp1[128][LDP];
    __shared__ unsigned wp0[64][LDP],  wp1[64][LDP];
    __shared__ float bsh[64];
    int chunk = blockIdx.y;
    const float* bsrc;
    float* dst;
    int coff, ldD;
    if (chunk < 2)      { bsrc = bq;    dst = g_q;    coff = chunk*64;     ldD = 128; }
    else if (chunk < 4) { bsrc = bk;    dst = g_k;    coff = (chunk-2)*64; ldD = 128; }
    else if (chunk < 6) { bsrc = bv;    dst = g_v;    coff = (chunk-4)*64; ldD = 128; }
    else                { bsrc = bskip; dst = g_outb; coff = 0;            ldD = 64;  }
    int tid = threadIdx.x;
    const uint4* wq0 = (const uint4*)(g_wq0 + chunk*2048);
    const uint4* wq1 = (const uint4*)(g_wq1 + chunk*2048);
    for (int i = tid; i < 512; i += 256) {
        int rr = i >> 3, c4 = (i & 7)*4;
        uint4 a = wq0[i], b = wq1[i];
        wp0[rr][c4]=a.x; wp0[rr][c4+1]=a.y; wp0[rr][c4+2]=a.z; wp0[rr][c4+3]=a.w;
        wp1[rr][c4]=b.x; wp1[rr][c4+1]=b.y; wp1[rr][c4+2]=b.z; wp1[rr][c4+3]=b.w;
    }
    if (tid < 64) bsh[tid] = bsrc[coff + tid];
    int m0 = blockIdx.x*128;
    for (int i = tid; i < 1024; i += 256) {
        int rr = i >> 3, c4 = (i & 7)*4;
        int row = m0 + rr; if (row > NH-1) row = NH-1;
        size_t base = (size_t)row*8 + (i & 7);
        uint4 a = ((const uint4*)g_hxb0)[base];
        uint4 b = ((const uint4*)g_hxb1)[base];
        xp0[rr][c4]=a.x; xp0[rr][c4+1]=a.y; xp0[rr][c4+2]=a.z; xp0[rr][c4+3]=a.w;
        xp1[rr][c4]=b.x; xp1[rr][c4+1]=b.y; xp1[rr][c4+2]=b.z; xp1[rr][c4+3]=b.w;
    }
    __syncthreads();

    int warp = tid >> 5, lane = tid & 31;
    int gid = lane >> 2, tig = lane & 3;
    int rA = warp*16 + gid;
    float acc[8][4];
    #pragma unroll
    for (int nt = 0; nt < 8; nt++)
        #pragma unroll
        for (int j = 0; j < 4; j++) acc[nt][j] = 0.f;

    #pragma unroll
    for (int kk = 0; kk < 4; kk++) {
        int ku = kk*8;
        unsigned a0h = xp0[rA][ku+tig],   a1h = xp0[rA+8][ku+tig];
        unsigned a2h = xp0[rA][ku+tig+4], a3h = xp0[rA+8][ku+tig+4];
        unsigned a0l = xp1[rA][ku+tig],   a1l = xp1[rA+8][ku+tig];
        unsigned a2l = xp1[rA][ku+tig+4], a3l = xp1[rA+8][ku+tig+4];
        #pragma unroll
        for (int nt = 0; nt < 8; nt++) {
            int n0 = nt*8 + gid;
            unsigned b0h = wp0[n0][ku+tig], b1h = wp0[n0][ku+tig+4];
            unsigned b0l = wp1[n0][ku+tig], b1l = wp1[n0][ku+tig+4];
            mma_bf16(acc[nt], a0h, a1h, a2h, a3h, b0h, b1h);
            mma_bf16(acc[nt], a0l, a1l, a2l, a3l, b0h, b1h);
            mma_bf16(acc[nt], a0h, a1h, a2h, a3h, b0l, b1l);
        }
    }
    int m = m0 + rA;
    #pragma unroll
    for (int nt = 0; nt < 8; nt++) {
        int col = nt*8 + 2*tig;
        if (m < NH)
            *(float2*)(dst + (size_t)m*ldD + coff + col)
                = make_float2(acc[nt][0]+bsh[col], acc[nt][1]+bsh[col+1]);
        if (m + 8 < NH)
            *(float2*)(dst + (size_t)(m+8)*ldD + coff + col)
                = make_float2(acc[nt][2]+bsh[col], acc[nt][3]+bsh[col+1]);
    }
}

// ---------------- fused attention: score + exp + weighted-v scatter ----------
// softmax is shift-invariant -> no segment-max pass needed (scores are O(1),
// far below f32 exp overflow).
__global__ void attn_fused_kernel(const int* __restrict__ ei) {
    int gw = (blockIdx.x*blockDim.x + threadIdx.x) >> 5;
    int lane = threadIdx.x & 31;
    if (gw >= NREL*NEDGE) return;
    int r = gw / NEDGE, w = gw - r*NEDGE;
    const int* base = ei + (size_t)r*2*NEDGE;
    int hsrc = base[w] + c_off[c_tsrc[r]];
    int hdst = base[NEDGE + w] + c_off[c_tdst[r]];
    int h = lane >> 4, l4 = lane & 15;
    float4 a = ((const float4*)(g_q + (size_t)hdst*128 + h*64))[l4];
    float4 b = ((const float4*)(g_k + (size_t)hsrc*128 + h*64))[l4];
    float p = a.x*b.x + a.y*b.y + a.z*b.z + a.w*b.w;
    p += __shfl_xor_sync(0xffffffffu, p, 8);
    p += __shfl_xor_sync(0xffffffffu, p, 4);
    p += __shfl_xor_sync(0xffffffffu, p, 2);
    p += __shfl_xor_sync(0xffffffffu, p, 1);
    float alpha = __expf(p * 0.125f);
    float4 v = ((const float4*)(g_v + (size_t)hsrc*128 + h*64))[l4];
    red_add_v4(g_num + (size_t)hdst*128 + h*64 + l4*4,
               make_float4(alpha*v.x, alpha*v.y, alpha*v.z, alpha*v.w));
    if (l4 == 0) atomicAdd(&g_den[hdst*2 + h], alpha);
}

// ---------------- finalize rows + channel stats ------------------------------
__global__ void reduce_kernel() {
    int c = threadIdx.x & 63;
    int sub = threadIdx.x >> 6;
    int base = blockIdx.x * 256;
    double s = 0.0, s2 = 0.0;
    for (int i = 0; i < 64; i++) {
        int m = base + sub*64 + i;
        if (m < NH) {
            float d0 = g_den[m*2]     + 1e-16f;
            float d1 = g_den[m*2 + 1] + 1e-16f;
            float val = g_outb[(size_t)m*64 + c]
                      + 0.5f * (g_num[(size_t)m*128 + c] / d0
                              + g_num[(size_t)m*128 + 64 + c] / d1);
            g_outb[(size_t)m*64 + c] = val;
            s += val;
            s2 += (double)val * (double)val;
        }
    }
    __shared__ double ss[256], sq[256];
    ss[threadIdx.x] = s; sq[threadIdx.x] = s2;
    __syncthreads();
    if (threadIdx.x < 64) {
        double ts = ss[threadIdx.x] + ss[threadIdx.x+64] + ss[threadIdx.x+128] + ss[threadIdx.x+192];
        double tq = sq[threadIdx.x] + sq[threadIdx.x+64] + sq[threadIdx.x+128] + sq[threadIdx.x+192];
        atomicAdd(&g_sum[c], ts);
        atomicAdd(&g_sumsq[c], tq);
    }
}

__global__ void stats_kernel() {
    int c = threadIdx.x;
    double mu = g_sum[c] / (double)NH;
    double var = g_sumsq[c] / (double)NH - mu*mu;
    g_mu[c] = (float)mu;
    g_rstd[c] = rsqrtf((float)var + 1e-5f);
}

// ---------------- layernorm + leaky relu + permuted output -------------------
__global__ void final_kernel(const float* __restrict__ gamma,
                             const float* __restrict__ beta,
                             float* __restrict__ out) {
    int idx = blockIdx.x*blockDim.x + threadIdx.x;
    if (idx >= 3*NPER*CH) return;
    int c = idx & 63;
    int rown = idx >> 6;
    int b = rown / NPER, n = rown - b*NPER;
    int srow = (b == 0) ? n : ((b == 1) ? (2*NPER + n) : (NPER + n));
    float v = g_outb[(size_t)srow*CH + c];
    v = gamma[c] * (v - g_mu[c]) * g_rstd[c] + beta[c];
    out[idx] = (v >= 0.f) ? v : 0.01f * v;
}

// ---------------- host orchestration -----------------------------------------
extern "C" void kernel_launch(void* const* d_in, const int* in_sizes, int n_in,
                              void* d_out, int out_size) {
    const float* x     = (const float*)d_in[0];
    const int*   ei    = (const int*)  d_in[1];
    const float* Wlin  = (const float*)d_in[2];
    const float* blin  = (const float*)d_in[3];
    const float* Wa    = (const float*)d_in[4];
    const float* ba    = (const float*)d_in[5];
    const float* Wq    = (const float*)d_in[6];
    const float* bq    = (const float*)d_in[7];
    const float* Wk    = (const float*)d_in[8];
    const float* bk    = (const float*)d_in[9];
    const float* Wv    = (const float*)d_in[10];
    const float* bv    = (const float*)d_in[11];
    const float* Wskip = (const float*)d_in[12];
    const float* bskip = (const float*)d_in[13];
    const float* gamma = (const float*)d_in[14];
    const float* beta  = (const float*)d_in[15];
    float* out = (float*)d_out;

    void *p_cnt, *p_acc, *p_num, *p_den, *p_sum, *p_sumsq, *p_xd, *p_hx;
    cudaGetSymbolAddress(&p_cnt, g_cnt);
    cudaGetSymbolAddress(&p_acc, g_acc);
    cudaGetSymbolAddress(&p_num, g_num);
    cudaGetSymbolAddress(&p_den, g_den);
    cudaGetSymbolAddress(&p_sum, g_sum);
    cudaGetSymbolAddress(&p_sumsq, g_sumsq);
    cudaGetSymbolAddress(&p_xd, g_xd);
    cudaGetSymbolAddress(&p_hx, g_hx);

    cudaMemsetAsync(p_cnt, 0, sizeof(float)*NREL*NPER);
    cnt_kernel<<<(NREL*NEDGE + 255)/256, 256>>>(ei);
    icnt_kernel<<<(NREL*NPER + 255)/256, 256>>>();
    wsplit_qkv_kernel<<<7, 256>>>(Wq, Wk, Wv, Wskip);
    xsplit_kernel<<<(3*NPER*16 + 255)/256, 256>>>(x);

    for (int l = 0; l < 2; l++) {
        const float* xin = (l == 0) ? x : (const float*)p_xd;
        const float* Wlin_l = Wlin + (size_t)l*NREL*4096;
        const float* blin_l = blin + (size_t)l*NREL*64;
        const float* Wa_l   = Wa   + (size_t)l*NREL*128;
        const float* ba_l   = ba   + (size_t)l*NREL;
        prep_u_kernel<<<1, 64>>>(Wlin_l, blin_l, Wa_l);
        wsplit_lin_kernel<<<15, 256>>>(Wlin_l);
        lin_mma_kernel<<<dim3(157, 15), 256>>>(blin_l, Wa_l, ba_l);
        ad_cross_kernel<<<dim3(2500, 6), 256>>>(xin, ba_l);
        cudaMemsetAsync(p_acc, 0, sizeof(float)*3*NPER*CH);
        edge_scatter_kernel<<<28125, 256>>>(ei);
        relu_kernel<<<(3*NPER*16 + 255)/256, 256>>>(l, l == 0 ? (float*)p_xd : (float*)p_hx);
    }
    cudaMemsetAsync(p_num, 0, sizeof(float)*(size_t)NH*128);
    cudaMemsetAsync(p_den, 0, sizeof(float)*NH*2);
    cudaMemsetAsync(p_sum, 0, sizeof(double)*CH);
    cudaMemsetAsync(p_sumsq, 0, sizeof(double)*CH);

    qkv_mma_kernel<<<dim3(469, 7), 256>>>(bq, bk, bv, bskip);
    attn_fused_kernel<<<56250, 256>>>(ei);
    reduce_kernel<<<235, 256>>>();
    stats_kernel<<<1, 64>>>();
    final_kernel<<<15000, 256>>>(gamma, beta, out);
}

// round 16
// speedup vs baseline: 1.4849x; 1.1329x over previous
#include <cuda_runtime.h>
#include <cuda_bf16.h>
#include <math.h>

#define NPER 20000
#define CH 64
#define NREL 15
#define NEDGE 30000
#define NH 60000

__constant__ int c_tsrc[NREL] = {0,1,2,0,1,2,0,1,2,0,0,1,1,2,2};
__constant__ int c_tdst[NREL] = {0,1,2,0,1,2,0,1,2,1,2,0,2,0,1};
__constant__ int c_off[3] = {0, 2*NPER, NPER};

// ---------------- scratch (device globals; no allocs allowed) ----------------
__device__ float    g_hs[(size_t)NREL*NPER*CH];
__device__ float    g_as[NREL*NPER];
__device__ float    g_ad[NREL*NPER];
__device__ float    g_cnt[NREL*NPER];
__device__ float    g_icnt[NREL*NPER];
__device__ float    g_acc[3*NPER*CH];
__device__ float    g_xd[3*NPER*CH];
__device__ float    g_hx[3*NPER*CH];
__device__ float    g_u0[2*6*CH];
__device__ float    g_cd[2*6];
__device__ float    g_q[(size_t)NH*128];
__device__ float    g_k[(size_t)NH*128];
__device__ float    g_v[(size_t)NH*128];
__device__ float    g_outb[(size_t)NH*CH];
__device__ float    g_numden[(size_t)NH*128 + NH*2];   // num | den
__device__ double   g_stats[2*CH];                     // sum | sumsq
__device__ float    g_mu[CH];
__device__ float    g_rstd[CH];
// bf16 plane buffers (hi/lo splits); lin planes hold BOTH layers
__device__ unsigned g_wl0[2*NREL*64*32], g_wl1[2*NREL*64*32];
__device__ unsigned g_wq0[7*64*32],      g_wq1[7*64*32];
__device__ unsigned g_xb0[3*NPER*32],    g_xb1[3*NPER*32];
__device__ unsigned g_hxb0[NH*32],       g_hxb1[NH*32];

__device__ __forceinline__ void red_add_v4(float* p, float4 v) {
    asm volatile("red.global.add.v4.f32 [%0], {%1,%2,%3,%4};"
                 :: "l"(p), "f"(v.x), "f"(v.y), "f"(v.z), "f"(v.w) : "memory");
}
__device__ __forceinline__ void mma_bf16(float c[4], unsigned a0, unsigned a1,
                                         unsigned a2, unsigned a3,
                                         unsigned b0, unsigned b1) {
    asm volatile("mma.sync.aligned.m16n8k16.row.col.f32.bf16.bf16.f32 "
                 "{%0,%1,%2,%3}, {%4,%5,%6,%7}, {%8,%9}, {%0,%1,%2,%3};"
                 : "+f"(c[0]), "+f"(c[1]), "+f"(c[2]), "+f"(c[3])
                 : "r"(a0), "r"(a1), "r"(a2), "r"(a3), "r"(b0), "r"(b1));
}
__device__ __forceinline__ unsigned pack_hi2(float lo, float hi) {
    __nv_bfloat162 b = __floats2bfloat162_rn(lo, hi);
    return *(unsigned*)&b;
}
__device__ __forceinline__ unsigned pack_lo2(float lo, float hi, unsigned hw) {
    __nv_bfloat162 b = *(__nv_bfloat162*)&hw;
    __nv_bfloat162 r = __floats2bfloat162_rn(lo - __bfloat162float(b.x),
                                             hi - __bfloat162float(b.y));
    return *(unsigned*)&r;
}
// tanh(s) = 1 - 2/(e^{2s}+1): single fast exp, no overflow, ~1e-6 error
__device__ __forceinline__ float fast_tanh(float s) {
    return 1.0f - 2.0f / (__expf(2.0f*s) + 1.0f);
}

#define LDP 36

// ---------------- edge counts ------------------------------------------------
__global__ void cnt_kernel(const int* __restrict__ ei) {
    int e = blockIdx.x*blockDim.x + threadIdx.x;
    if (e >= NREL*NEDGE) return;
    int r = e / NEDGE, w = e - r*NEDGE;
    int dst = ei[(size_t)r*2*NEDGE + NEDGE + w];
    atomicAdd(&g_cnt[r*NPER + dst], 1.0f);
}

// ---------------- weights prep: all W splits + u0/cd, both layers ------------
// blocks [0,30): wsplit_lin (layer, r); [30,37): wsplit_qkv chunk; [37,49): prep_u.
__global__ void weights_prep_kernel(const float* __restrict__ Wlin,
                                    const float* __restrict__ blin,
                                    const float* __restrict__ Wa,
                                    const float* __restrict__ Wq,
                                    const float* __restrict__ Wk,
                                    const float* __restrict__ Wv,
                                    const float* __restrict__ Wskip) {
    int b = blockIdx.x;
    int tid = threadIdx.x;
    if (b < 30) {
        int l = b / 15, r = b % 15;
        const float* W = Wlin + (size_t)l*NREL*4096 + r*4096;
        int slot = l*15 + r;
        for (int i = tid; i < 4096; i += 256) {
            int k = i >> 6, n = i & 63;
            float v = W[i];
            __nv_bfloat16 b0 = __float2bfloat16(v);
            ((__nv_bfloat16*)g_wl0)[((size_t)slot*64 + n)*64 + k] = b0;
            ((__nv_bfloat16*)g_wl1)[((size_t)slot*64 + n)*64 + k] =
                __float2bfloat16(v - __bfloat162float(b0));
        }
    } else if (b < 37) {
        int chunk = b - 30;
        const float* Wsrc; int ldW, coff;
        if (chunk < 2)      { Wsrc = Wq;    ldW = 128; coff = chunk*64; }
        else if (chunk < 4) { Wsrc = Wk;    ldW = 128; coff = (chunk-2)*64; }
        else if (chunk < 6) { Wsrc = Wv;    ldW = 128; coff = (chunk-4)*64; }
        else                { Wsrc = Wskip; ldW = 64;  coff = 0; }
        for (int i = tid; i < 4096; i += 256) {
            int k = i >> 6, n = i & 63;
            float v = Wsrc[k*ldW + coff + n];
            __nv_bfloat16 b0 = __float2bfloat16(v);
            ((__nv_bfloat16*)g_wq0)[(chunk*64 + n)*64 + k] = b0;
            ((__nv_bfloat16*)g_wq1)[(chunk*64 + n)*64 + k] =
                __float2bfloat16(v - __bfloat162float(b0));
        }
    } else {
        int idx = b - 37;
        int l = idx / 6, j = idx % 6;
        int r = 9 + j;
        const float* Wl = Wlin + (size_t)l*NREL*4096 + r*4096;
        const float* wa0 = Wa + (size_t)l*NREL*128 + r*128;
        if (tid < 64) {
            const float* Wrow = Wl + tid*64;
            float s = 0.f;
            #pragma unroll 8
            for (int c = 0; c < 64; c++) s += Wrow[c] * wa0[c];
            g_u0[l*384 + j*64 + tid] = s;
        }
        if (tid == 0) {
            const float* bl = blin + (size_t)l*NREL*64 + r*64;
            float s = 0.f;
            for (int c = 0; c < 64; c++) s += bl[c] * wa0[c];
            g_cd[l*6 + j] = s;
        }
    }
}

// ---------------- x split + icnt + zero acc/stats ----------------------------
__global__ void xsplit_kernel(const float* __restrict__ x) {
    int idx = blockIdx.x*blockDim.x + threadIdx.x;
    if (idx >= 3*NPER*16) return;
    int lane = idx & 15, tn = idx >> 4;
    float4 v = ((const float4*)x)[idx];
    unsigned h0 = pack_hi2(v.x, v.y), h1 = pack_hi2(v.z, v.w);
    g_xb0[tn*32 + lane*2]     = h0;
    g_xb0[tn*32 + lane*2 + 1] = h1;
    g_xb1[tn*32 + lane*2]     = pack_lo2(v.x, v.y, h0);
    g_xb1[tn*32 + lane*2 + 1] = pack_lo2(v.z, v.w, h1);
    ((float4*)g_acc)[idx] = make_float4(0.f, 0.f, 0.f, 0.f);
    if (idx < NREL*NPER) g_icnt[idx] = 0.2f / fmaxf(g_cnt[idx], 1.0f);
    if (idx < 2*CH) g_stats[idx] = 0.0;
}

// ---------------- hs = x[tsrc] @ Wlin + blin  (128-row tile) -----------------
__global__ void lin_mma_kernel(int l,
                               const float* __restrict__ blin_l,
                               const float* __restrict__ Wa_l,
                               const float* __restrict__ ba_l) {
    __shared__ unsigned xp0[128][LDP], xp1[128][LDP];
    __shared__ unsigned wp0[64][LDP],  wp1[64][LDP];
    __shared__ float bsh[64], wa0s[64], wa1s[64];
    int r = blockIdx.y;
    int tid = threadIdx.x;
    int slot = l*15 + r;
    const uint4* wl0 = (const uint4*)(g_wl0 + (size_t)slot*2048);
    const uint4* wl1 = (const uint4*)(g_wl1 + (size_t)slot*2048);
    for (int i = tid; i < 512; i += 256) {
        int rr = i >> 3, c4 = (i & 7)*4;
        uint4 a = wl0[i], b = wl1[i];
        wp0[rr][c4]=a.x; wp0[rr][c4+1]=a.y; wp0[rr][c4+2]=a.z; wp0[rr][c4+3]=a.w;
        wp1[rr][c4]=b.x; wp1[rr][c4+1]=b.y; wp1[rr][c4+2]=b.z; wp1[rr][c4+3]=b.w;
    }
    if (tid < 64) {
        bsh[tid]  = blin_l[r*64 + tid];
        wa0s[tid] = Wa_l[r*128 + tid];
        wa1s[tid] = Wa_l[r*128 + 64 + tid];
    }
    int t = c_tsrc[r];
    int row0 = blockIdx.x*128;
    for (int i = tid; i < 1024; i += 256) {
        int rr = i >> 3, c4 = (i & 7)*4;
        int row = row0 + rr; if (row > NPER-1) row = NPER-1;
        size_t base = ((size_t)t*NPER + row)*8 + (i & 7);
        uint4 a = ((const uint4*)g_xb0)[base];
        uint4 b = ((const uint4*)g_xb1)[base];
        xp0[rr][c4]=a.x; xp0[rr][c4+1]=a.y; xp0[rr][c4+2]=a.z; xp0[rr][c4+3]=a.w;
        xp1[rr][c4]=b.x; xp1[rr][c4+1]=b.y; xp1[rr][c4+2]=b.z; xp1[rr][c4+3]=b.w;
    }
    __syncthreads();

    int warp = tid >> 5, lane = tid & 31;
    int gid = lane >> 2, tig = lane & 3;
    int rA = warp*16 + gid;
    float acc[8][4];
    #pragma unroll
    for (int nt = 0; nt < 8; nt++)
        #pragma unroll
        for (int j = 0; j < 4; j++) acc[nt][j] = 0.f;

    #pragma unroll
    for (int kk = 0; kk < 4; kk++) {
        int ku = kk*8;
        unsigned a0h = xp0[rA][ku+tig],   a1h = xp0[rA+8][ku+tig];
        unsigned a2h = xp0[rA][ku+tig+4], a3h = xp0[rA+8][ku+tig+4];
        unsigned a0l = xp1[rA][ku+tig],   a1l = xp1[rA+8][ku+tig];
        unsigned a2l = xp1[rA][ku+tig+4], a3l = xp1[rA+8][ku+tig+4];
        #pragma unroll
        for (int nt = 0; nt < 8; nt++) {
            int n0 = nt*8 + gid;
            unsigned b0h = wp0[n0][ku+tig], b1h = wp0[n0][ku+tig+4];
            unsigned b0l = wp1[n0][ku+tig], b1l = wp1[n0][ku+tig+4];
            mma_bf16(acc[nt], a0h, a1h, a2h, a3h, b0h, b1h);
            mma_bf16(acc[nt], a0l, a1l, a2l, a3l, b0h, b1h);
            mma_bf16(acc[nt], a0h, a1h, a2h, a3h, b0l, b1l);
        }
    }
    // bias + store + warp-local a_s/a_d
    int n = row0 + rA;
    float* base = g_hs + ((size_t)r*NPER + n)*CH;
    float sA = 0.f, sB = 0.f, dA = 0.f, dB = 0.f;
    #pragma unroll
    for (int nt = 0; nt < 8; nt++) {
        int col = nt*8 + 2*tig;
        float c0 = acc[nt][0] + bsh[col], c1 = acc[nt][1] + bsh[col+1];
        float c2 = acc[nt][2] + bsh[col], c3 = acc[nt][3] + bsh[col+1];
        if (n < NPER)     *(float2*)(base + col)        = make_float2(c0, c1);
        if (n + 8 < NPER) *(float2*)(base + 8*CH + col) = make_float2(c2, c3);
        sA += c0*wa1s[col] + c1*wa1s[col+1];
        sB += c2*wa1s[col] + c3*wa1s[col+1];
        dA += c0*wa0s[col] + c1*wa0s[col+1];
        dB += c2*wa0s[col] + c3*wa0s[col+1];
    }
    sA += __shfl_xor_sync(0xffffffffu, sA, 1); sA += __shfl_xor_sync(0xffffffffu, sA, 2);
    sB += __shfl_xor_sync(0xffffffffu, sB, 1); sB += __shfl_xor_sync(0xffffffffu, sB, 2);
    dA += __shfl_xor_sync(0xffffffffu, dA, 1); dA += __shfl_xor_sync(0xffffffffu, dA, 2);
    dB += __shfl_xor_sync(0xffffffffu, dB, 1); dB += __shfl_xor_sync(0xffffffffu, dB, 2);
    if (tig == 0) {
        float ba = ba_l[r];
        if (n < NPER) {
            g_as[r*NPER + n] = sA;
            if (r < 9) g_ad[r*NPER + n] = dA + ba;
        }
        if (n + 8 < NPER) {
            g_as[r*NPER + n + 8] = sB;
            if (r < 9) g_ad[r*NPER + n + 8] = dB + ba;
        }
    }
}

// ---------------- a_d for the 6 cross-type relations -------------------------
__global__ void ad_cross_kernel(int l, const float* __restrict__ x,
                                const float* __restrict__ ba_l) {
    int j = blockIdx.y;
    int r = 9 + j;
    int warp = threadIdx.x >> 5, lane = threadIdx.x & 31;
    int n = blockIdx.x*8 + warp;
    int t = c_tdst[r];
    const float* xrow = x + ((size_t)t*NPER + n)*CH;
    const float* u0 = g_u0 + l*384 + j*64;
    float p = xrow[lane]*u0[lane] + xrow[lane+32]*u0[lane+32];
    #pragma unroll
    for (int s = 16; s; s >>= 1) p += __shfl_xor_sync(0xffffffffu, p, s);
    if (lane == 0) g_ad[r*NPER + n] = p + g_cd[l*6 + j] + ba_l[r];
}

// ---------------- per-edge gated message scatter -----------------------------
__global__ void edge_scatter_kernel(const int* __restrict__ ei) {
    int idx = blockIdx.x*blockDim.x + threadIdx.x;
    int e = idx >> 4, lane = idx & 15;
    if (e >= NREL*NEDGE) return;
    int r = e / NEDGE, w = e - r*NEDGE;
    const int* base = ei + (size_t)r*2*NEDGE;
    int src = base[w], dst = base[NEDGE + w];
    float g = 0.f;
    if (lane == 0)
        g = fast_tanh(g_ad[r*NPER + dst] + g_as[r*NPER + src]) * g_icnt[r*NPER + dst];
    g = __shfl_sync(0xffffffffu, g, threadIdx.x & 16);
    float4 h = ((const float4*)(g_hs + ((size_t)r*NPER + src)*CH))[lane];
    int t = c_tdst[r];
    red_add_v4(g_acc + ((size_t)t*NPER + dst)*CH + lane*4,
               make_float4(g*h.x, g*h.y, g*h.z, g*h.w));
}

// ---------------- relu + store layer output (+ bf16 planes, + re-zero acc) ---
__global__ void relu_kernel(int mode, float* __restrict__ dst) {
    int idx = blockIdx.x*blockDim.x + threadIdx.x;
    if (idx >= 3*NPER*16) return;
    int lane = idx & 15, tn = idx >> 4;
    int t = tn / NPER, n = tn - t*NPER;
    float4 a = ((const float4*)(g_acc + (size_t)tn*CH))[lane];
    if (mode == 0)   // reset accumulator for layer 2
        ((float4*)(g_acc + (size_t)tn*CH))[lane] = make_float4(0.f, 0.f, 0.f, 0.f);
    a.x = fmaxf(a.x, 0.f); a.y = fmaxf(a.y, 0.f);
    a.z = fmaxf(a.z, 0.f); a.w = fmaxf(a.w, 0.f);
    int row = mode ? (c_off[t] + n) : tn;
    ((float4*)(dst + (size_t)row*CH))[lane] = a;
    unsigned h0 = pack_hi2(a.x, a.y), h1 = pack_hi2(a.z, a.w);
    unsigned l0 = pack_lo2(a.x, a.y, h0), l1 = pack_lo2(a.z, a.w, h1);
    unsigned *p0 = mode ? g_hxb0 : g_xb0;
    unsigned *p1 = mode ? g_hxb1 : g_xb1;
    p0[(size_t)row*32 + lane*2]     = h0;
    p0[(size_t)row*32 + lane*2 + 1] = h1;
    p1[(size_t)row*32 + lane*2]     = l0;
    p1[(size_t)row*32 + lane*2 + 1] = l1;
}

// ---------------- q/k/v/skip GEMM (128-row tile) -----------------------------
__global__ void qkv_mma_kernel(const float* __restrict__ bq, const float* __restrict__ bk,
                               const float* __restrict__ bv, const float* __restrict__ bskip) {
    __shared__ unsigned xp0[128][LDP], xp1[128][LDP];
    __shared__ unsigned wp0[64][LDP],  wp1[64][LDP];
    __shared__ float bsh[64];
    int chunk = blockIdx.y;
    const float* bsrc;
    float* dst;
    int coff, ldD;
    if (chunk < 2)      { bsrc = bq;    dst = g_q;    coff = chunk*64;     ldD = 128; }
    else if (chunk < 4) { bsrc = bk;    dst = g_k;    coff = (chunk-2)*64; ldD = 128; }
    else if (chunk < 6) { bsrc = bv;    dst = g_v;    coff = (chunk-4)*64; ldD = 128; }
    else                { bsrc = bskip; dst = g_outb; coff = 0;            ldD = 64;  }
    int tid = threadIdx.x;
    const uint4* wq0 = (const uint4*)(g_wq0 + chunk*2048);
    const uint4* wq1 = (const uint4*)(g_wq1 + chunk*2048);
    for (int i = tid; i < 512; i += 256) {
        int rr = i >> 3, c4 = (i & 7)*4;
        uint4 a = wq0[i], b = wq1[i];
        wp0[rr][c4]=a.x; wp0[rr][c4+1]=a.y; wp0[rr][c4+2]=a.z; wp0[rr][c4+3]=a.w;
        wp1[rr][c4]=b.x; wp1[rr][c4+1]=b.y; wp1[rr][c4+2]=b.z; wp1[rr][c4+3]=b.w;
    }
    if (tid < 64) bsh[tid] = bsrc[coff + tid];
    int m0 = blockIdx.x*128;
    for (int i = tid; i < 1024; i += 256) {
        int rr = i >> 3, c4 = (i & 7)*4;
        int row = m0 + rr; if (row > NH-1) row = NH-1;
        size_t base = (size_t)row*8 + (i & 7);
        uint4 a = ((const uint4*)g_hxb0)[base];
        uint4 b = ((const uint4*)g_hxb1)[base];
        xp0[rr][c4]=a.x; xp0[rr][c4+1]=a.y; xp0[rr][c4+2]=a.z; xp0[rr][c4+3]=a.w;
        xp1[rr][c4]=b.x; xp1[rr][c4+1]=b.y; xp1[rr][c4+2]=b.z; xp1[rr][c4+3]=b.w;
    }
    __syncthreads();

    int warp = tid >> 5, lane = tid & 31;
    int gid = lane >> 2, tig = lane & 3;
    int rA = warp*16 + gid;
    float acc[8][4];
    #pragma unroll
    for (int nt = 0; nt < 8; nt++)
        #pragma unroll
        for (int j = 0; j < 4; j++) acc[nt][j] = 0.f;

    #pragma unroll
    for (int kk = 0; kk < 4; kk++) {
        int ku = kk*8;
        unsigned a0h = xp0[rA][ku+tig],   a1h = xp0[rA+8][ku+tig];
        unsigned a2h = xp0[rA][ku+tig+4], a3h = xp0[rA+8][ku+tig+4];
        unsigned a0l = xp1[rA][ku+tig],   a1l = xp1[rA+8][ku+tig];
        unsigned a2l = xp1[rA][ku+tig+4], a3l = xp1[rA+8][ku+tig+4];
        #pragma unroll
        for (int nt = 0; nt < 8; nt++) {
            int n0 = nt*8 + gid;
            unsigned b0h = wp0[n0][ku+tig], b1h = wp0[n0][ku+tig+4];
            unsigned b0l = wp1[n0][ku+tig], b1l = wp1[n0][ku+tig+4];
            mma_bf16(acc[nt], a0h, a1h, a2h, a3h, b0h, b1h);
            mma_bf16(acc[nt], a0l, a1l, a2l, a3l, b0h, b1h);
            mma_bf16(acc[nt], a0h, a1h, a2h, a3h, b0l, b1l);
        }
    }
    int m = m0 + rA;
    #pragma unroll
    for (int nt = 0; nt < 8; nt++) {
        int col = nt*8 + 2*tig;
        if (m < NH)
            *(float2*)(dst + (size_t)m*ldD + coff + col)
                = make_float2(acc[nt][0]+bsh[col], acc[nt][1]+bsh[col+1]);
        if (m + 8 < NH)
            *(float2*)(dst + (size_t)(m+8)*ldD + coff + col)
                = make_float2(acc[nt][2]+bsh[col], acc[nt][3]+bsh[col+1]);
    }
}

// ---------------- fused attention: score + exp + weighted-v scatter ----------
__global__ void attn_fused_kernel(const int* __restrict__ ei) {
    int gw = (blockIdx.x*blockDim.x + threadIdx.x) >> 5;
    int lane = threadIdx.x & 31;
    if (gw >= NREL*NEDGE) return;
    int r = gw / NEDGE, w = gw - r*NEDGE;
    const int* base = ei + (size_t)r*2*NEDGE;
    int hsrc = base[w] + c_off[c_tsrc[r]];
    int hdst = base[NEDGE + w] + c_off[c_tdst[r]];
    int h = lane >> 4, l4 = lane & 15;
    float4 a = ((const float4*)(g_q + (size_t)hdst*128 + h*64))[l4];
    float4 b = ((const float4*)(g_k + (size_t)hsrc*128 + h*64))[l4];
    float p = a.x*b.x + a.y*b.y + a.z*b.z + a.w*b.w;
    p += __shfl_xor_sync(0xffffffffu, p, 8);
    p += __shfl_xor_sync(0xffffffffu, p, 4);
    p += __shfl_xor_sync(0xffffffffu, p, 2);
    p += __shfl_xor_sync(0xffffffffu, p, 1);
    float alpha = __expf(p * 0.125f);
    float4 v = ((const float4*)(g_v + (size_t)hsrc*128 + h*64))[l4];
    red_add_v4(g_numden + (size_t)hdst*128 + h*64 + l4*4,
               make_float4(alpha*v.x, alpha*v.y, alpha*v.z, alpha*v.w));
    if (l4 == 0) atomicAdd(&g_numden[(size_t)NH*128 + hdst*2 + h], alpha);
}

// ---------------- finalize rows + channel stats ------------------------------
__global__ void reduce_kernel() {
    const float* num = g_numden;
    const float* den = g_numden + (size_t)NH*128;
    int c = threadIdx.x & 63;
    int sub = threadIdx.x >> 6;
    int base = blockIdx.x * 256;
    double s = 0.0, s2 = 0.0;
    for (int i = 0; i < 64; i++) {
        int m = base + sub*64 + i;
        if (m < NH) {
            float d0 = den[m*2]     + 1e-16f;
            float d1 = den[m*2 + 1] + 1e-16f;
            float val = g_outb[(size_t)m*64 + c]
                      + 0.5f * (num[(size_t)m*128 + c] / d0
                              + num[(size_t)m*128 + 64 + c] / d1);
            g_outb[(size_t)m*64 + c] = val;
            s += val;
            s2 += (double)val * (double)val;
        }
    }
    __shared__ double ss[256], sq[256];
    ss[threadIdx.x] = s; sq[threadIdx.x] = s2;
    __syncthreads();
    if (threadIdx.x < 64) {
        double ts = ss[threadIdx.x] + ss[threadIdx.x+64] + ss[threadIdx.x+128] + ss[threadIdx.x+192];
        double tq = sq[threadIdx.x] + sq[threadIdx.x+64] + sq[threadIdx.x+128] + sq[threadIdx.x+192];
        atomicAdd(&g_stats[c], ts);
        atomicAdd(&g_stats[64 + c], tq);
    }
}

__global__ void stats_kernel() {
    int c = threadIdx.x;
    double mu = g_stats[c] / (double)NH;
    double var = g_stats[64 + c] / (double)NH - mu*mu;
    g_mu[c] = (float)mu;
    g_rstd[c] = rsqrtf((float)var + 1e-5f);
}

// ---------------- layernorm + leaky relu + permuted output -------------------
__global__ void final_kernel(const float* __restrict__ gamma,
                             const float* __restrict__ beta,
                             float* __restrict__ out) {
    int idx = blockIdx.x*blockDim.x + threadIdx.x;
    if (idx >= 3*NPER*CH) return;
    int c = idx & 63;
    int rown = idx >> 6;
    int b = rown / NPER, n = rown - b*NPER;
    int srow = (b == 0) ? n : ((b == 1) ? (2*NPER + n) : (NPER + n));
    float v = g_outb[(size_t)srow*CH + c];
    v = gamma[c] * (v - g_mu[c]) * g_rstd[c] + beta[c];
    out[idx] = (v >= 0.f) ? v : 0.01f * v;
}

// ---------------- host orchestration -----------------------------------------
extern "C" void kernel_launch(void* const* d_in, const int* in_sizes, int n_in,
                              void* d_out, int out_size) {
    const float* x     = (const float*)d_in[0];
    const int*   ei    = (const int*)  d_in[1];
    const float* Wlin  = (const float*)d_in[2];
    const float* blin  = (const float*)d_in[3];
    const float* Wa    = (const float*)d_in[4];
    const float* ba    = (const float*)d_in[5];
    const float* Wq    = (const float*)d_in[6];
    const float* bq    = (const float*)d_in[7];
    const float* Wk    = (const float*)d_in[8];
    const float* bk    = (const float*)d_in[9];
    const float* Wv    = (const float*)d_in[10];
    const float* bv    = (const float*)d_in[11];
    const float* Wskip = (const float*)d_in[12];
    const float* bskip = (const float*)d_in[13];
    const float* gamma = (const float*)d_in[14];
    const float* beta  = (const float*)d_in[15];
    float* out = (float*)d_out;

    void *p_cnt, *p_numden, *p_xd, *p_hx;
    cudaGetSymbolAddress(&p_cnt, g_cnt);
    cudaGetSymbolAddress(&p_numden, g_numden);
    cudaGetSymbolAddress(&p_xd, g_xd);
    cudaGetSymbolAddress(&p_hx, g_hx);

    cudaMemsetAsync(p_cnt, 0, sizeof(float)*NREL*NPER);
    cnt_kernel<<<(NREL*NEDGE + 255)/256, 256>>>(ei);
    weights_prep_kernel<<<49, 256>>>(Wlin, blin, Wa, Wq, Wk, Wv, Wskip);
    xsplit_kernel<<<(3*NPER*16 + 255)/256, 256>>>(x);   // + icnt + zero acc/stats

    for (int l = 0; l < 2; l++) {
        const float* xin = (l == 0) ? x : (const float*)p_xd;
        const float* blin_l = blin + (size_t)l*NREL*64;
        const float* Wa_l   = Wa   + (size_t)l*NREL*128;
        const float* ba_l   = ba   + (size_t)l*NREL;
        lin_mma_kernel<<<dim3(157, 15), 256>>>(l, blin_l, Wa_l, ba_l);
        ad_cross_kernel<<<dim3(2500, 6), 256>>>(l, xin, ba_l);
        edge_scatter_kernel<<<28125, 256>>>(ei);
        relu_kernel<<<(3*NPER*16 + 255)/256, 256>>>(l, l == 0 ? (float*)p_xd : (float*)p_hx);
    }
    cudaMemsetAsync(p_numden, 0, sizeof(float)*((size_t)NH*128 + NH*2));

    qkv_mma_kernel<<<dim3(469, 7), 256>>>(bq, bk, bv, bskip);
    attn_fused_kernel<<<56250, 256>>>(ei);
    reduce_kernel<<<235, 256>>>();
    stats_kernel<<<1, 64>>>();
    final_kernel<<<15000, 256>>>(gamma, beta, out);
}

// round 17
// speedup vs baseline: 1.6185x; 1.0900x over previous
#include <cuda_runtime.h>
#include <cuda_bf16.h>
#include <math.h>

#define NPER 20000
#define CH 64
#define NREL 15
#define NEDGE 30000
#define NH 60000
#define NUMDEN_SZ ((size_t)NH*128 + NH*2)

__constant__ int c_tsrc[NREL] = {0,1,2,0,1,2,0,1,2,0,0,1,1,2,2};
__constant__ int c_tdst[NREL] = {0,1,2,0,1,2,0,1,2,1,2,0,2,0,1};
__constant__ int c_off[3] = {0, 2*NPER, NPER};
__constant__ int c_crossrel[3][2] = {{11,13},{9,14},{10,12}};  // r with tdst==type

// ---------------- scratch (device globals; no allocs allowed) ----------------
__device__ float    g_hs[(size_t)NREL*NPER*CH];
__device__ float    g_as[NREL*NPER];
__device__ float    g_ad[NREL*NPER];
__device__ float    g_cnt[NREL*NPER];
__device__ float    g_icnt[NREL*NPER];
__device__ float    g_acc[3*NPER*CH];
__device__ float    g_xd[3*NPER*CH];
__device__ float    g_hx[3*NPER*CH];
__device__ float    g_u0[2*6*CH];
__device__ float    g_cd[2*6];
__device__ float    g_q[(size_t)NH*128];
__device__ float    g_k[(size_t)NH*128];
__device__ float    g_v[(size_t)NH*128];
__device__ float    g_outb[(size_t)NH*CH];
__device__ float    g_numden[NUMDEN_SZ];   // num | den
__device__ double   g_stats[2*CH];         // sum | sumsq
__device__ float    g_mu[CH];
__device__ float    g_rstd[CH];
// bf16 plane buffers (hi/lo splits); lin planes hold BOTH layers
__device__ unsigned g_wl0[2*NREL*64*32], g_wl1[2*NREL*64*32];
__device__ unsigned g_wq0[7*64*32],      g_wq1[7*64*32];
__device__ unsigned g_xb0[3*NPER*32],    g_xb1[3*NPER*32];
__device__ unsigned g_hxb0[NH*32],       g_hxb1[NH*32];

__device__ __forceinline__ void red_add_v4(float* p, float4 v) {
    asm volatile("red.global.add.v4.f32 [%0], {%1,%2,%3,%4};"
                 :: "l"(p), "f"(v.x), "f"(v.y), "f"(v.z), "f"(v.w) : "memory");
}
__device__ __forceinline__ void mma_bf16(float c[4], unsigned a0, unsigned a1,
                                         unsigned a2, unsigned a3,
                                         unsigned b0, unsigned b1) {
    asm volatile("mma.sync.aligned.m16n8k16.row.col.f32.bf16.bf16.f32 "
                 "{%0,%1,%2,%3}, {%4,%5,%6,%7}, {%8,%9}, {%0,%1,%2,%3};"
                 : "+f"(c[0]), "+f"(c[1]), "+f"(c[2]), "+f"(c[3])
                 : "r"(a0), "r"(a1), "r"(a2), "r"(a3), "r"(b0), "r"(b1));
}
__device__ __forceinline__ unsigned pack_hi2(float lo, float hi) {
    __nv_bfloat162 b = __floats2bfloat162_rn(lo, hi);
    return *(unsigned*)&b;
}
__device__ __forceinline__ unsigned pack_lo2(float lo, float hi, unsigned hw) {
    __nv_bfloat162 b = *(__nv_bfloat162*)&hw;
    __nv_bfloat162 r = __floats2bfloat162_rn(lo - __bfloat162float(b.x),
                                             hi - __bfloat162float(b.y));
    return *(unsigned*)&r;
}
__device__ __forceinline__ float fast_tanh(float s) {
    return 1.0f - 2.0f / (__expf(2.0f*s) + 1.0f);
}
// reduce a value over the 16-lane half-group that owns one row
__device__ __forceinline__ float red16(float p) {
    p += __shfl_xor_sync(0xffffffffu, p, 1);
    p += __shfl_xor_sync(0xffffffffu, p, 2);
    p += __shfl_xor_sync(0xffffffffu, p, 4);
    p += __shfl_xor_sync(0xffffffffu, p, 8);
    return p;
}
// cross-relation a_d from a row held across 16 lanes (4 channels each)
__device__ __forceinline__ void cross_ad_from_row(int l, int t, int n, int lane4,
                                                  float vx, float vy, float vz, float vw,
                                                  const float* ba_l) {
    #pragma unroll
    for (int i = 0; i < 2; i++) {
        int r = c_crossrel[t][i];
        int j = r - 9;
        const float* u0 = g_u0 + l*384 + j*64 + lane4*4;
        float p = vx*u0[0] + vy*u0[1] + vz*u0[2] + vw*u0[3];
        p = red16(p);
        if (lane4 == 0)
            g_ad[r*NPER + n] = p + g_cd[l*6 + j] + ba_l[r];
    }
}

#define LDP 36

// ---------------- edge counts ------------------------------------------------
__global__ void cnt_kernel(const int* __restrict__ ei) {
    int e = blockIdx.x*blockDim.x + threadIdx.x;
    if (e >= NREL*NEDGE) return;
    int r = e / NEDGE, w = e - r*NEDGE;
    int dst = ei[(size_t)r*2*NEDGE + NEDGE + w];
    atomicAdd(&g_cnt[r*NPER + dst], 1.0f);
}

// ---------------- weights prep: all W splits + u0/cd, both layers ------------
__global__ void weights_prep_kernel(const float* __restrict__ Wlin,
                                    const float* __restrict__ blin,
                                    const float* __restrict__ Wa,
                                    const float* __restrict__ Wq,
                                    const float* __restrict__ Wk,
                                    const float* __restrict__ Wv,
                                    const float* __restrict__ Wskip) {
    int b = blockIdx.x;
    int tid = threadIdx.x;
    if (b < 30) {
        int l = b / 15, r = b % 15;
        const float* W = Wlin + (size_t)l*NREL*4096 + r*4096;
        int slot = l*15 + r;
        for (int i = tid; i < 4096; i += 256) {
            int k = i >> 6, n = i & 63;
            float v = W[i];
            __nv_bfloat16 b0 = __float2bfloat16(v);
            ((__nv_bfloat16*)g_wl0)[((size_t)slot*64 + n)*64 + k] = b0;
            ((__nv_bfloat16*)g_wl1)[((size_t)slot*64 + n)*64 + k] =
                __float2bfloat16(v - __bfloat162float(b0));
        }
    } else if (b < 37) {
        int chunk = b - 30;
        const float* Wsrc; int ldW, coff;
        if (chunk < 2)      { Wsrc = Wq;    ldW = 128; coff = chunk*64; }
        else if (chunk < 4) { Wsrc = Wk;    ldW = 128; coff = (chunk-2)*64; }
        else if (chunk < 6) { Wsrc = Wv;    ldW = 128; coff = (chunk-4)*64; }
        else                { Wsrc = Wskip; ldW = 64;  coff = 0; }
        for (int i = tid; i < 4096; i += 256) {
            int k = i >> 6, n = i & 63;
            float v = Wsrc[k*ldW + coff + n];
            __nv_bfloat16 b0 = __float2bfloat16(v);
            ((__nv_bfloat16*)g_wq0)[(chunk*64 + n)*64 + k] = b0;
            ((__nv_bfloat16*)g_wq1)[(chunk*64 + n)*64 + k] =
                __float2bfloat16(v - __bfloat162float(b0));
        }
    } else {
        int idx = b - 37;
        int l = idx / 6, j = idx % 6;
        int r = 9 + j;
        const float* Wl = Wlin + (size_t)l*NREL*4096 + r*4096;
        const float* wa0 = Wa + (size_t)l*NREL*128 + r*128;
        if (tid < 64) {
            const float* Wrow = Wl + tid*64;
            float s = 0.f;
            #pragma unroll 8
            for (int c = 0; c < 64; c++) s += Wrow[c] * wa0[c];
            g_u0[l*384 + j*64 + tid] = s;
        }
        if (tid == 0) {
            const float* bl = blin + (size_t)l*NREL*64 + r*64;
            float s = 0.f;
            for (int c = 0; c < 64; c++) s += bl[c] * wa0[c];
            g_cd[l*6 + j] = s;
        }
    }
}

// ---------------- x split + icnt + zero acc/stats + layer-0 cross a_d --------
__global__ void xsplit_kernel(const float* __restrict__ x,
                              const float* __restrict__ ba0) {
    int idx = blockIdx.x*blockDim.x + threadIdx.x;
    if (idx >= 3*NPER*16) return;
    int lane = idx & 15, tn = idx >> 4;
    int t = tn / NPER, n = tn - t*NPER;
    float4 v = ((const float4*)x)[idx];
    unsigned h0 = pack_hi2(v.x, v.y), h1 = pack_hi2(v.z, v.w);
    g_xb0[tn*32 + lane*2]     = h0;
    g_xb0[tn*32 + lane*2 + 1] = h1;
    g_xb1[tn*32 + lane*2]     = pack_lo2(v.x, v.y, h0);
    g_xb1[tn*32 + lane*2 + 1] = pack_lo2(v.z, v.w, h1);
    ((float4*)g_acc)[idx] = make_float4(0.f, 0.f, 0.f, 0.f);
    if (idx < NREL*NPER) g_icnt[idx] = 0.2f / fmaxf(g_cnt[idx], 1.0f);
    if (idx < 2*CH) g_stats[idx] = 0.0;
    cross_ad_from_row(0, t, n, lane, v.x, v.y, v.z, v.w, ba0);
}

// ---------------- hs = x[tsrc] @ Wlin + blin  (128-row tile) -----------------
__global__ void lin_mma_kernel(int l,
                               const float* __restrict__ blin_l,
                               const float* __restrict__ Wa_l,
                               const float* __restrict__ ba_l) {
    __shared__ unsigned xp0[128][LDP], xp1[128][LDP];
    __shared__ unsigned wp0[64][LDP],  wp1[64][LDP];
    __shared__ float bsh[64], wa0s[64], wa1s[64];
    int r = blockIdx.y;
    int tid = threadIdx.x;
    int slot = l*15 + r;
    const uint4* wl0 = (const uint4*)(g_wl0 + (size_t)slot*2048);
    const uint4* wl1 = (const uint4*)(g_wl1 + (size_t)slot*2048);
    for (int i = tid; i < 512; i += 256) {
        int rr = i >> 3, c4 = (i & 7)*4;
        uint4 a = wl0[i], b = wl1[i];
        wp0[rr][c4]=a.x; wp0[rr][c4+1]=a.y; wp0[rr][c4+2]=a.z; wp0[rr][c4+3]=a.w;
        wp1[rr][c4]=b.x; wp1[rr][c4+1]=b.y; wp1[rr][c4+2]=b.z; wp1[rr][c4+3]=b.w;
    }
    if (tid < 64) {
        bsh[tid]  = blin_l[r*64 + tid];
        wa0s[tid] = Wa_l[r*128 + tid];
        wa1s[tid] = Wa_l[r*128 + 64 + tid];
    }
    int t = c_tsrc[r];
    int row0 = blockIdx.x*128;
    for (int i = tid; i < 1024; i += 256) {
        int rr = i >> 3, c4 = (i & 7)*4;
        int row = row0 + rr; if (row > NPER-1) row = NPER-1;
        size_t base = ((size_t)t*NPER + row)*8 + (i & 7);
        uint4 a = ((const uint4*)g_xb0)[base];
        uint4 b = ((const uint4*)g_xb1)[base];
        xp0[rr][c4]=a.x; xp0[rr][c4+1]=a.y; xp0[rr][c4+2]=a.z; xp0[rr][c4+3]=a.w;
        xp1[rr][c4]=b.x; xp1[rr][c4+1]=b.y; xp1[rr][c4+2]=b.z; xp1[rr][c4+3]=b.w;
    }
    __syncthreads();

    int warp = tid >> 5, lane = tid & 31;
    int gid = lane >> 2, tig = lane & 3;
    int rA = warp*16 + gid;
    float acc[8][4];
    #pragma unroll
    for (int nt = 0; nt < 8; nt++)
        #pragma unroll
        for (int j = 0; j < 4; j++) acc[nt][j] = 0.f;

    #pragma unroll
    for (int kk = 0; kk < 4; kk++) {
        int ku = kk*8;
        unsigned a0h = xp0[rA][ku+tig],   a1h = xp0[rA+8][ku+tig];
        unsigned a2h = xp0[rA][ku+tig+4], a3h = xp0[rA+8][ku+tig+4];
        unsigned a0l = xp1[rA][ku+tig],   a1l = xp1[rA+8][ku+tig];
        unsigned a2l = xp1[rA][ku+tig+4], a3l = xp1[rA+8][ku+tig+4];
        #pragma unroll
        for (int nt = 0; nt < 8; nt++) {
            int n0 = nt*8 + gid;
            unsigned b0h = wp0[n0][ku+tig], b1h = wp0[n0][ku+tig+4];
            unsigned b0l = wp1[n0][ku+tig], b1l = wp1[n0][ku+tig+4];
            mma_bf16(acc[nt], a0h, a1h, a2h, a3h, b0h, b1h);
            mma_bf16(acc[nt], a0l, a1l, a2l, a3l, b0h, b1h);
            mma_bf16(acc[nt], a0h, a1h, a2h, a3h, b0l, b1l);
        }
    }
    // bias + store + warp-local a_s/a_d
    int n = row0 + rA;
    float* base = g_hs + ((size_t)r*NPER + n)*CH;
    float sA = 0.f, sB = 0.f, dA = 0.f, dB = 0.f;
    #pragma unroll
    for (int nt = 0; nt < 8; nt++) {
        int col = nt*8 + 2*tig;
        float c0 = acc[nt][0] + bsh[col], c1 = acc[nt][1] + bsh[col+1];
        float c2 = acc[nt][2] + bsh[col], c3 = acc[nt][3] + bsh[col+1];
        if (n < NPER)     *(float2*)(base + col)        = make_float2(c0, c1);
        if (n + 8 < NPER) *(float2*)(base + 8*CH + col) = make_float2(c2, c3);
        sA += c0*wa1s[col] + c1*wa1s[col+1];
        sB += c2*wa1s[col] + c3*wa1s[col+1];
        dA += c0*wa0s[col] + c1*wa0s[col+1];
        dB += c2*wa0s[col] + c3*wa0s[col+1];
    }
    sA += __shfl_xor_sync(0xffffffffu, sA, 1); sA += __shfl_xor_sync(0xffffffffu, sA, 2);
    sB += __shfl_xor_sync(0xffffffffu, sB, 1); sB += __shfl_xor_sync(0xffffffffu, sB, 2);
    dA += __shfl_xor_sync(0xffffffffu, dA, 1); dA += __shfl_xor_sync(0xffffffffu, dA, 2);
    dB += __shfl_xor_sync(0xffffffffu, dB, 1); dB += __shfl_xor_sync(0xffffffffu, dB, 2);
    if (tig == 0) {
        float ba = ba_l[r];
        if (n < NPER) {
            g_as[r*NPER + n] = sA;
            if (r < 9) g_ad[r*NPER + n] = dA + ba;
        }
        if (n + 8 < NPER) {
            g_as[r*NPER + n + 8] = sB;
            if (r < 9) g_ad[r*NPER + n + 8] = dB + ba;
        }
    }
}

// ---------------- per-edge gated message scatter -----------------------------
__global__ void edge_scatter_kernel(const int* __restrict__ ei) {
    int idx = blockIdx.x*blockDim.x + threadIdx.x;
    int e = idx >> 4, lane = idx & 15;
    if (e >= NREL*NEDGE) return;
    int r = e / NEDGE, w = e - r*NEDGE;
    const int* base = ei + (size_t)r*2*NEDGE;
    int src = base[w], dst = base[NEDGE + w];
    float g = 0.f;
    if (lane == 0)
        g = fast_tanh(g_ad[r*NPER + dst] + g_as[r*NPER + src]) * g_icnt[r*NPER + dst];
    g = __shfl_sync(0xffffffffu, g, threadIdx.x & 16);
    float4 h = ((const float4*)(g_hs + ((size_t)r*NPER + src)*CH))[lane];
    int t = c_tdst[r];
    red_add_v4(g_acc + ((size_t)t*NPER + dst)*CH + lane*4,
               make_float4(g*h.x, g*h.y, g*h.z, g*h.w));
}

// ---------------- relu + store layer output (+ planes, re-zero, cross a_d) ---
__global__ void relu_kernel(int mode, float* __restrict__ dst,
                            const float* __restrict__ ba1) {
    int idx = blockIdx.x*blockDim.x + threadIdx.x;
    if (idx >= 3*NPER*16) return;
    int lane = idx & 15, tn = idx >> 4;
    int t = tn / NPER, n = tn - t*NPER;
    float4 a = ((const float4*)(g_acc + (size_t)tn*CH))[lane];
    if (mode == 0)   // reset accumulator for layer 2
        ((float4*)(g_acc + (size_t)tn*CH))[lane] = make_float4(0.f, 0.f, 0.f, 0.f);
    a.x = fmaxf(a.x, 0.f); a.y = fmaxf(a.y, 0.f);
    a.z = fmaxf(a.z, 0.f); a.w = fmaxf(a.w, 0.f);
    int row = mode ? (c_off[t] + n) : tn;
    ((float4*)(dst + (size_t)row*CH))[lane] = a;
    unsigned h0 = pack_hi2(a.x, a.y), h1 = pack_hi2(a.z, a.w);
    unsigned l0 = pack_lo2(a.x, a.y, h0), l1 = pack_lo2(a.z, a.w, h1);
    unsigned *p0 = mode ? g_hxb0 : g_xb0;
    unsigned *p1 = mode ? g_hxb1 : g_xb1;
    p0[(size_t)row*32 + lane*2]     = h0;
    p0[(size_t)row*32 + lane*2 + 1] = h1;
    p1[(size_t)row*32 + lane*2]     = l0;
    p1[(size_t)row*32 + lane*2 + 1] = l1;
    if (mode == 0)   // layer-1 cross a_d from post-relu xd (in registers)
        cross_ad_from_row(1, t, n, lane, a.x, a.y, a.z, a.w, ba1);
}

// ---------------- q/k/v/skip GEMM (128-row tile) + numden zero ---------------
__global__ void qkv_mma_kernel(const float* __restrict__ bq, const float* __restrict__ bk,
                               const float* __restrict__ bv, const float* __restrict__ bskip) {
    __shared__ unsigned xp0[128][LDP], xp1[128][LDP];
    __shared__ unsigned wp0[64][LDP],  wp1[64][LDP];
    __shared__ float bsh[64];
    // zero numden (grid-stride; overlaps staging below)
    {
        size_t nv4 = NUMDEN_SZ / 4;
        size_t gsz = (size_t)gridDim.x * gridDim.y * 256;
        size_t gi = ((size_t)(blockIdx.y*gridDim.x + blockIdx.x))*256 + threadIdx.x;
        for (size_t i = gi; i < nv4; i += gsz)
            ((float4*)g_numden)[i] = make_float4(0.f, 0.f, 0.f, 0.f);
        if (gi < (NUMDEN_SZ & 3))
            g_numden[nv4*4 + gi] = 0.f;
    }
    int chunk = blockIdx.y;
    const float* bsrc;
    float* dst;
    int coff, ldD;
    if (chunk < 2)      { bsrc = bq;    dst = g_q;    coff = chunk*64;     ldD = 128; }
    else if (chunk < 4) { bsrc = bk;    dst = g_k;    coff = (chunk-2)*64; ldD = 128; }
    else if (chunk < 6) { bsrc = bv;    dst = g_v;    coff = (chunk-4)*64; ldD = 128; }
    else                { bsrc = bskip; dst = g_outb; coff = 0;            ldD = 64;  }
    int tid = threadIdx.x;
    const uint4* wq0 = (const uint4*)(g_wq0 + chunk*2048);
    const uint4* wq1 = (const uint4*)(g_wq1 + chunk*2048);
    for (int i = tid; i < 512; i += 256) {
        int rr = i >> 3, c4 = (i & 7)*4;
        uint4 a = wq0[i], b = wq1[i];
        wp0[rr][c4]=a.x; wp0[rr][c4+1]=a.y; wp0[rr][c4+2]=a.z; wp0[rr][c4+3]=a.w;
        wp1[rr][c4]=b.x; wp1[rr][c4+1]=b.y; wp1[rr][c4+2]=b.z; wp1[rr][c4+3]=b.w;
    }
    if (tid < 64) bsh[tid] = bsrc[coff + tid];
    int m0 = blockIdx.x*128;
    for (int i = tid; i < 1024; i += 256) {
        int rr = i >> 3, c4 = (i & 7)*4;
        int row = m0 + rr; if (row > NH-1) row = NH-1;
        size_t base = (size_t)row*8 + (i & 7);
        uint4 a = ((const uint4*)g_hxb0)[base];
        uint4 b = ((const uint4*)g_hxb1)[base];
        xp0[rr][c4]=a.x; xp0[rr][c4+1]=a.y; xp0[rr][c4+2]=a.z; xp0[rr][c4+3]=a.w;
        xp1[rr][c4]=b.x; xp1[rr][c4+1]=b.y; xp1[rr][c4+2]=b.z; xp1[rr][c4+3]=b.w;
    }
    __syncthreads();

    int warp = tid >> 5, lane = tid & 31;
    int gid = lane >> 2, tig = lane & 3;
    int rA = warp*16 + gid;
    float acc[8][4];
    #pragma unroll
    for (int nt = 0; nt < 8; nt++)
        #pragma unroll
        for (int j = 0; j < 4; j++) acc[nt][j] = 0.f;

    #pragma unroll
    for (int kk = 0; kk < 4; kk++) {
        int ku = kk*8;
        unsigned a0h = xp0[rA][ku+tig],   a1h = xp0[rA+8][ku+tig];
        unsigned a2h = xp0[rA][ku+tig+4], a3h = xp0[rA+8][ku+tig+4];
        unsigned a0l = xp1[rA][ku+tig],   a1l = xp1[rA+8][ku+tig];
        unsigned a2l = xp1[rA][ku+tig+4], a3l = xp1[rA+8][ku+tig+4];
        #pragma unroll
        for (int nt = 0; nt < 8; nt++) {
            int n0 = nt*8 + gid;
            unsigned b0h = wp0[n0][ku+tig], b1h = wp0[n0][ku+tig+4];
            unsigned b0l = wp1[n0][ku+tig], b1l = wp1[n0][ku+tig+4];
            mma_bf16(acc[nt], a0h, a1h, a2h, a3h, b0h, b1h);
            mma_bf16(acc[nt], a0l, a1l, a2l, a3l, b0h, b1h);
            mma_bf16(acc[nt], a0h, a1h, a2h, a3h, b0l, b1l);
        }
    }
    int m = m0 + rA;
    #pragma unroll
    for (int nt = 0; nt < 8; nt++) {
        int col = nt*8 + 2*tig;
        if (m < NH)
            *(float2*)(dst + (size_t)m*ldD + coff + col)
                = make_float2(acc[nt][0]+bsh[col], acc[nt][1]+bsh[col+1]);
        if (m + 8 < NH)
            *(float2*)(dst + (size_t)(m+8)*ldD + coff + col)
                = make_float2(acc[nt][2]+bsh[col], acc[nt][3]+bsh[col+1]);
    }
}

// ---------------- fused attention: score + exp + weighted-v scatter ----------
__global__ void attn_fused_kernel(const int* __restrict__ ei) {
    int gw = (blockIdx.x*blockDim.x + threadIdx.x) >> 5;
    int lane = threadIdx.x & 31;
    if (gw >= NREL*NEDGE) return;
    int r = gw / NEDGE, w = gw - r*NEDGE;
    const int* base = ei + (size_t)r*2*NEDGE;
    int hsrc = base[w] + c_off[c_tsrc[r]];
    int hdst = base[NEDGE + w] + c_off[c_tdst[r]];
    int h = lane >> 4, l4 = lane & 15;
    float4 a = ((const float4*)(g_q + (size_t)hdst*128 + h*64))[l4];
    float4 b = ((const float4*)(g_k + (size_t)hsrc*128 + h*64))[l4];
    float p = a.x*b.x + a.y*b.y + a.z*b.z + a.w*b.w;
    p += __shfl_xor_sync(0xffffffffu, p, 8);
    p += __shfl_xor_sync(0xffffffffu, p, 4);
    p += __shfl_xor_sync(0xffffffffu, p, 2);
    p += __shfl_xor_sync(0xffffffffu, p, 1);
    float alpha = __expf(p * 0.125f);
    float4 v = ((const float4*)(g_v + (size_t)hsrc*128 + h*64))[l4];
    red_add_v4(g_numden + (size_t)hdst*128 + h*64 + l4*4,
               make_float4(alpha*v.x, alpha*v.y, alpha*v.z, alpha*v.w));
    if (l4 == 0) atomicAdd(&g_numden[(size_t)NH*128 + hdst*2 + h], alpha);
}

// ---------------- finalize rows + channel stats ------------------------------
__global__ void reduce_kernel() {
    const float* num = g_numden;
    const float* den = g_numden + (size_t)NH*128;
    int c = threadIdx.x & 63;
    int sub = threadIdx.x >> 6;
    int base = blockIdx.x * 256;
    double s = 0.0, s2 = 0.0;
    for (int i = 0; i < 64; i++) {
        int m = base + sub*64 + i;
        if (m < NH) {
            float d0 = den[m*2]     + 1e-16f;
            float d1 = den[m*2 + 1] + 1e-16f;
            float val = g_outb[(size_t)m*64 + c]
                      + 0.5f * (num[(size_t)m*128 + c] / d0
                              + num[(size_t)m*128 + 64 + c] / d1);
            g_outb[(size_t)m*64 + c] = val;
            s += val;
            s2 += (double)val * (double)val;
        }
    }
    __shared__ double ss[256], sq[256];
    ss[threadIdx.x] = s; sq[threadIdx.x] = s2;
    __syncthreads();
    if (threadIdx.x < 64) {
        double ts = ss[threadIdx.x] + ss[threadIdx.x+64] + ss[threadIdx.x+128] + ss[threadIdx.x+192];
        double tq = sq[threadIdx.x] + sq[threadIdx.x+64] + sq[threadIdx.x+128] + sq[threadIdx.x+192];
        atomicAdd(&g_stats[c], ts);
        atomicAdd(&g_stats[64 + c], tq);
    }
}

__global__ void stats_kernel() {
    int c = threadIdx.x;
    double mu = g_stats[c] / (double)NH;
    double var = g_stats[64 + c] / (double)NH - mu*mu;
    g_mu[c] = (float)mu;
    g_rstd[c] = rsqrtf((float)var + 1e-5f);
}

// ---------------- layernorm + leaky relu + permuted output -------------------
__global__ void final_kernel(const float* __restrict__ gamma,
                             const float* __restrict__ beta,
                             float* __restrict__ out) {
    int idx = blockIdx.x*blockDim.x + threadIdx.x;
    if (idx >= 3*NPER*CH) return;
    int c = idx & 63;
    int rown = idx >> 6;
    int b = rown / NPER, n = rown - b*NPER;
    int srow = (b == 0) ? n : ((b == 1) ? (2*NPER + n) : (NPER + n));
    float v = g_outb[(size_t)srow*CH + c];
    v = gamma[c] * (v - g_mu[c]) * g_rstd[c] + beta[c];
    out[idx] = (v >= 0.f) ? v : 0.01f * v;
}

// ---------------- host orchestration -----------------------------------------
extern "C" void kernel_launch(void* const* d_in, const int* in_sizes, int n_in,
                              void* d_out, int out_size) {
    const float* x     = (const float*)d_in[0];
    const int*   ei    = (const int*)  d_in[1];
    const float* Wlin  = (const float*)d_in[2];
    const float* blin  = (const float*)d_in[3];
    const float* Wa    = (const float*)d_in[4];
    const float* ba    = (const float*)d_in[5];
    const float* Wq    = (const float*)d_in[6];
    const float* bq    = (const float*)d_in[7];
    const float* Wk    = (const float*)d_in[8];
    const float* bk    = (const float*)d_in[9];
    const float* Wv    = (const float*)d_in[10];
    const float* bv    = (const float*)d_in[11];
    const float* Wskip = (const float*)d_in[12];
    const float* bskip = (const float*)d_in[13];
    const float* gamma = (const float*)d_in[14];
    const float* beta  = (const float*)d_in[15];
    float* out = (float*)d_out;

    void *p_cnt, *p_xd, *p_hx;
    cudaGetSymbolAddress(&p_cnt, g_cnt);
    cudaGetSymbolAddress(&p_xd, g_xd);
    cudaGetSymbolAddress(&p_hx, g_hx);

    cudaMemsetAsync(p_cnt, 0, sizeof(float)*NREL*NPER);
    cnt_kernel<<<(NREL*NEDGE + 255)/256, 256>>>(ei);
    weights_prep_kernel<<<49, 256>>>(Wlin, blin, Wa, Wq, Wk, Wv, Wskip);
    xsplit_kernel<<<(3*NPER*16 + 255)/256, 256>>>(x, ba);  // + icnt + zeros + ad_cross(l=0)

    for (int l = 0; l < 2; l++) {
        const float* blin_l = blin + (size_t)l*NREL*64;
        const float* Wa_l   = Wa   + (size_t)l*NREL*128;
        const float* ba_l   = ba   + (size_t)l*NREL;
        lin_mma_kernel<<<dim3(157, 15), 256>>>(l, blin_l, Wa_l, ba_l);
        edge_scatter_kernel<<<28125, 256>>>(ei);
        relu_kernel<<<(3*NPER*16 + 255)/256, 256>>>(l, l == 0 ? (float*)p_xd : (float*)p_hx,
                                                    ba + NREL);  // ad_cross(l=1) when mode==0
    }

    qkv_mma_kernel<<<dim3(469, 7), 256>>>(bq, bk, bv, bskip);  // + numden zero
    attn_fused_kernel<<<56250, 256>>>(ei);
    reduce_kernel<<<235, 256>>>();
    stats_kernel<<<1, 64>>>();
    final_kernel<<<15000, 256>>>(gamma, beta, out);
}